// round 1
// baseline (speedup 1.0000x reference)
#include <cuda_runtime.h>

#define B_ 2
#define T_ 2048
#define C_ 1024
#define H_ 16
#define D_ 64
#define F_ 4096
#define M_ (B_*T_)   // 4096 rows

// ---------------- scratch (device globals; no runtime allocation) ----------
__device__ __align__(16) float g_h  [M_*C_];
__device__ __align__(16) float g_q  [M_*C_];   // [B,H,T,D]
__device__ __align__(16) float g_k  [M_*C_];
__device__ __align__(16) float g_v  [M_*C_];
__device__ __align__(16) float g_att[M_*C_];   // [B,T,C] (heads concat)
__device__ __align__(16) float g_x1 [M_*C_];
__device__ __align__(16) float g_h2 [M_*C_];
__device__ __align__(16) float g_ff [M_*F_];

// ---------------- LayerNorm: one block per row, 256 threads ----------------
__global__ __launch_bounds__(256) void ln_kernel(
    const float* __restrict__ x, const float* __restrict__ g,
    const float* __restrict__ b, float* __restrict__ out)
{
    int row = blockIdx.x;
    int tid = threadIdx.x;
    const float4 xv = ((const float4*)(x + (size_t)row*C_))[tid];
    float s  = xv.x + xv.y + xv.z + xv.w;
    float s2 = xv.x*xv.x + xv.y*xv.y + xv.z*xv.z + xv.w*xv.w;
    __shared__ float rs[8], rs2[8];
    #pragma unroll
    for (int o = 16; o; o >>= 1) {
        s  += __shfl_down_sync(0xffffffffu, s,  o);
        s2 += __shfl_down_sync(0xffffffffu, s2, o);
    }
    if ((tid & 31) == 0) { rs[tid>>5] = s; rs2[tid>>5] = s2; }
    __syncthreads();
    if (tid == 0) {
        float a = 0.f, c = 0.f;
        #pragma unroll
        for (int i = 0; i < 8; i++) { a += rs[i]; c += rs2[i]; }
        rs[0] = a; rs2[0] = c;
    }
    __syncthreads();
    float mean = rs[0] * (1.0f/C_);
    float var  = rs2[0] * (1.0f/C_) - mean*mean;
    float rstd = rsqrtf(var + 1e-5f);
    const float4 gv = ((const float4*)g)[tid];
    const float4 bv = ((const float4*)b)[tid];
    float4 o;
    o.x = (xv.x-mean)*rstd*gv.x + bv.x;
    o.y = (xv.y-mean)*rstd*gv.y + bv.y;
    o.z = (xv.z-mean)*rstd*gv.z + bv.z;
    o.w = (xv.w-mean)*rstd*gv.w + bv.w;
    ((float4*)(out + (size_t)row*C_))[tid] = o;
}

// ---------------- generic 64x64 SGEMM with fused epilogue -------------------
// C[m,n] = sum_k A[m,k]*B[k,n] (+bias[n]) (relu?) (+res[m,n]?)
template<int RELU, int HASRES>
__global__ __launch_bounds__(256) void gemm_kernel(
    const float* __restrict__ A, const float* __restrict__ Bm,
    float* __restrict__ Cm, int M, int N, int K,
    const float* __restrict__ bias, const float* __restrict__ res)
{
    __shared__ float As[16][68];   // transposed: As[k][m]
    __shared__ float Bs[16][68];
    int tid = threadIdx.x;
    int tx = tid & 15, ty = tid >> 4;
    int m0 = blockIdx.y << 6, n0 = blockIdx.x << 6;
    int lr = tid >> 2, lc = (tid & 3) << 2;     // A tile load: row lr, cols lc..lc+3
    int br = tid >> 4, bc = (tid & 15) << 2;    // B tile load
    float acc[4][4] = {};
    const float* Aptr = A  + (size_t)(m0 + lr) * K + lc;
    const float* Bptr = Bm + (size_t)br * N + n0 + bc;
    for (int k0 = 0; k0 < K; k0 += 16) {
        float4 av = *(const float4*)(Aptr + k0);
        float4 bv = *(const float4*)(Bptr + (size_t)k0 * N);
        As[lc+0][lr] = av.x; As[lc+1][lr] = av.y;
        As[lc+2][lr] = av.z; As[lc+3][lr] = av.w;
        *(float4*)&Bs[br][bc] = bv;
        __syncthreads();
        #pragma unroll
        for (int kk = 0; kk < 16; kk++) {
            float4 a4 = *(const float4*)&As[kk][ty<<2];
            float4 b4 = *(const float4*)&Bs[kk][tx<<2];
            acc[0][0] += a4.x*b4.x; acc[0][1] += a4.x*b4.y; acc[0][2] += a4.x*b4.z; acc[0][3] += a4.x*b4.w;
            acc[1][0] += a4.y*b4.x; acc[1][1] += a4.y*b4.y; acc[1][2] += a4.y*b4.z; acc[1][3] += a4.y*b4.w;
            acc[2][0] += a4.z*b4.x; acc[2][1] += a4.z*b4.y; acc[2][2] += a4.z*b4.z; acc[2][3] += a4.z*b4.w;
            acc[3][0] += a4.w*b4.x; acc[3][1] += a4.w*b4.y; acc[3][2] += a4.w*b4.z; acc[3][3] += a4.w*b4.w;
        }
        __syncthreads();
    }
    int n = n0 + (tx << 2);
    float4 bsv = *(const float4*)(bias + n);
    #pragma unroll
    for (int i = 0; i < 4; i++) {
        int m = m0 + (ty << 2) + i;
        float4 o;
        o.x = acc[i][0] + bsv.x; o.y = acc[i][1] + bsv.y;
        o.z = acc[i][2] + bsv.z; o.w = acc[i][3] + bsv.w;
        if (RELU) {
            o.x = fmaxf(o.x, 0.f); o.y = fmaxf(o.y, 0.f);
            o.z = fmaxf(o.z, 0.f); o.w = fmaxf(o.w, 0.f);
        }
        if (HASRES) {
            float4 rv = *(const float4*)(res + (size_t)m * N + n);
            o.x += rv.x; o.y += rv.y; o.z += rv.z; o.w += rv.w;
        }
        *(float4*)(Cm + (size_t)m * N + n) = o;
    }
}

// ---------------- QKV: per-head GEMM [M,C]x[C,64] -> [B,H,T,D] -------------
__global__ __launch_bounds__(256) void qkv_kernel(
    const float* __restrict__ Ah,
    const float* __restrict__ Wq, const float* __restrict__ Wk,
    const float* __restrict__ Wv,
    float* __restrict__ qo, float* __restrict__ ko, float* __restrict__ vo)
{
    int h  = blockIdx.x;            // head == n-tile (D_==64 == tile width)
    int m0 = blockIdx.y << 6;
    int which = blockIdx.z;
    const float* W = (which == 0) ? Wq : (which == 1) ? Wk : Wv;
    float* O       = (which == 0) ? qo : (which == 1) ? ko : vo;
    const float* Bmat = W + (size_t)h * C_ * D_;   // [C_,64] row-major

    __shared__ float As[16][68];
    __shared__ float Bs[16][68];
    int tid = threadIdx.x;
    int tx = tid & 15, ty = tid >> 4;
    int lr = tid >> 2, lc = (tid & 3) << 2;
    int br = tid >> 4, bc = (tid & 15) << 2;
    float acc[4][4] = {};
    const float* Aptr = Ah   + (size_t)(m0 + lr) * C_ + lc;
    const float* Bptr = Bmat + (size_t)br * D_ + bc;
    for (int k0 = 0; k0 < C_; k0 += 16) {
        float4 av = *(const float4*)(Aptr + k0);
        float4 bv = *(const float4*)(Bptr + (size_t)k0 * D_);
        As[lc+0][lr] = av.x; As[lc+1][lr] = av.y;
        As[lc+2][lr] = av.z; As[lc+3][lr] = av.w;
        *(float4*)&Bs[br][bc] = bv;
        __syncthreads();
        #pragma unroll
        for (int kk = 0; kk < 16; kk++) {
            float4 a4 = *(const float4*)&As[kk][ty<<2];
            float4 b4 = *(const float4*)&Bs[kk][tx<<2];
            acc[0][0] += a4.x*b4.x; acc[0][1] += a4.x*b4.y; acc[0][2] += a4.x*b4.z; acc[0][3] += a4.x*b4.w;
            acc[1][0] += a4.y*b4.x; acc[1][1] += a4.y*b4.y; acc[1][2] += a4.y*b4.z; acc[1][3] += a4.y*b4.w;
            acc[2][0] += a4.z*b4.x; acc[2][1] += a4.z*b4.y; acc[2][2] += a4.z*b4.z; acc[2][3] += a4.z*b4.w;
            acc[3][0] += a4.w*b4.x; acc[3][1] += a4.w*b4.y; acc[3][2] += a4.w*b4.z; acc[3][3] += a4.w*b4.w;
        }
        __syncthreads();
    }
    #pragma unroll
    for (int i = 0; i < 4; i++) {
        int r = m0 + (ty << 2) + i;      // global row in [0, B*T)
        int b = r >> 11;                  // T_ = 2048
        int t = r & (T_ - 1);
        float* dst = O + ((size_t)(b * H_ + h) * T_ + t) * D_ + (tx << 2);
        *(float4*)dst = make_float4(acc[i][0], acc[i][1], acc[i][2], acc[i][3]);
    }
}

// ---------------- flash attention (Br=Bc=64, online softmax) ---------------
#define ATT_SMEM_BYTES ((4*64*68 + 3*64) * 4)

__global__ __launch_bounds__(256) void attn_kernel(
    const float* __restrict__ q, const float* __restrict__ k,
    const float* __restrict__ v, float* __restrict__ out)
{
    extern __shared__ float sm[];
    float* Qs   = sm;                 // [64][68]  (row-major, pre-scaled)
    float* Kt   = Qs + 64*68;         // [d][j] transposed
    float* Vs   = Kt + 64*68;         // [j][d]
    float* Ss   = Vs + 64*68;         // [i][j]
    float* mrow = Ss + 64*68;         // [64]
    float* lrow = mrow + 64;
    float* arow = lrow + 64;

    int bh = blockIdx.y;              // b*H+h, 0..31
    int qt = blockIdx.x;              // 0..31
    int q0 = qt << 6;
    const float* Qg = q + (size_t)bh * T_ * D_;
    const float* Kg = k + (size_t)bh * T_ * D_;
    const float* Vg = v + (size_t)bh * T_ * D_;
    int tid = threadIdx.x;
    int tx = tid & 15, ty = tid >> 4;
    const float scale = 0.03125f;     // C^-0.5 = 1/32 (faithful to reference)

    // load Q tile (scaled)
    {
        int r = tid >> 2, c0 = (tid & 3) << 4;
        #pragma unroll
        for (int u = 0; u < 4; u++) {
            float4 t4 = *(const float4*)(Qg + (size_t)(q0 + r) * D_ + c0 + (u<<2));
            t4.x *= scale; t4.y *= scale; t4.z *= scale; t4.w *= scale;
            *(float4*)&Qs[r*68 + c0 + (u<<2)] = t4;
        }
    }
    if (tid < 64) { mrow[tid] = -1e30f; lrow[tid] = 0.f; }
    float Oacc[4][4] = {};

    for (int kt = 0; kt <= qt; kt++) {
        int k0 = kt << 6;
        __syncthreads();   // prev-iter PV done (and Q-load done on iter 0)
        {
            int r = tid >> 2, c0 = (tid & 3) << 4;
            #pragma unroll
            for (int u = 0; u < 4; u++) {
                float4 kv4 = *(const float4*)(Kg + (size_t)(k0 + r) * D_ + c0 + (u<<2));
                Kt[(c0 + (u<<2) + 0)*68 + r] = kv4.x;
                Kt[(c0 + (u<<2) + 1)*68 + r] = kv4.y;
                Kt[(c0 + (u<<2) + 2)*68 + r] = kv4.z;
                Kt[(c0 + (u<<2) + 3)*68 + r] = kv4.w;
                *(float4*)&Vs[r*68 + c0 + (u<<2)] =
                    *(const float4*)(Vg + (size_t)(k0 + r) * D_ + c0 + (u<<2));
            }
        }
        __syncthreads();

        // S[i][j] = sum_d Qs[i][d] * K[j][d]
        float sacc[4][4] = {};
        #pragma unroll 8
        for (int d = 0; d < 64; d++) {
            float qa0 = Qs[((ty<<2)+0)*68 + d];
            float qa1 = Qs[((ty<<2)+1)*68 + d];
            float qa2 = Qs[((ty<<2)+2)*68 + d];
            float qa3 = Qs[((ty<<2)+3)*68 + d];
            float4 kb = *(const float4*)&Kt[d*68 + (tx<<2)];
            sacc[0][0] += qa0*kb.x; sacc[0][1] += qa0*kb.y; sacc[0][2] += qa0*kb.z; sacc[0][3] += qa0*kb.w;
            sacc[1][0] += qa1*kb.x; sacc[1][1] += qa1*kb.y; sacc[1][2] += qa1*kb.z; sacc[1][3] += qa1*kb.w;
            sacc[2][0] += qa2*kb.x; sacc[2][1] += qa2*kb.y; sacc[2][2] += qa2*kb.z; sacc[2][3] += qa2*kb.w;
            sacc[3][0] += qa3*kb.x; sacc[3][1] += qa3*kb.y; sacc[3][2] += qa3*kb.z; sacc[3][3] += qa3*kb.w;
        }
        #pragma unroll
        for (int a = 0; a < 4; a++)
            *(float4*)&Ss[((ty<<2)+a)*68 + (tx<<2)] =
                make_float4(sacc[a][0], sacc[a][1], sacc[a][2], sacc[a][3]);
        __syncthreads();

        // online softmax: 4 threads per row (16 cols each)
        {
            bool diag = (kt == qt);
            int r = tid >> 2;
            int cb = (tid & 3) << 4;
            float sv[16];
            float mloc = -1e30f;
            #pragma unroll
            for (int c = 0; c < 16; c++) {
                float s = Ss[r*68 + cb + c];
                if (diag && (cb + c) > r) s = -1e30f;
                sv[c] = s;
                mloc = fmaxf(mloc, s);
            }
            mloc = fmaxf(mloc, __shfl_xor_sync(0xffffffffu, mloc, 1));
            mloc = fmaxf(mloc, __shfl_xor_sync(0xffffffffu, mloc, 2));
            float mold = mrow[r];
            float mnew = fmaxf(mold, mloc);
            float ls = 0.f;
            #pragma unroll
            for (int c = 0; c < 16; c++) {
                float e = __expf(sv[c] - mnew);
                Ss[r*68 + cb + c] = e;
                ls += e;
            }
            ls += __shfl_xor_sync(0xffffffffu, ls, 1);
            ls += __shfl_xor_sync(0xffffffffu, ls, 2);
            if ((tid & 3) == 0) {
                float al = __expf(mold - mnew);
                arow[r] = al;
                lrow[r] = lrow[r] * al + ls;
                mrow[r] = mnew;
            }
        }
        __syncthreads();

        // rescale O, accumulate P@V
        #pragma unroll
        for (int a = 0; a < 4; a++) {
            float al = arow[(ty<<2) + a];
            Oacc[a][0] *= al; Oacc[a][1] *= al; Oacc[a][2] *= al; Oacc[a][3] *= al;
        }
        #pragma unroll 8
        for (int j = 0; j < 64; j++) {
            float p0 = Ss[((ty<<2)+0)*68 + j];
            float p1 = Ss[((ty<<2)+1)*68 + j];
            float p2 = Ss[((ty<<2)+2)*68 + j];
            float p3 = Ss[((ty<<2)+3)*68 + j];
            float4 vv = *(const float4*)&Vs[j*68 + (tx<<2)];
            Oacc[0][0] += p0*vv.x; Oacc[0][1] += p0*vv.y; Oacc[0][2] += p0*vv.z; Oacc[0][3] += p0*vv.w;
            Oacc[1][0] += p1*vv.x; Oacc[1][1] += p1*vv.y; Oacc[1][2] += p1*vv.z; Oacc[1][3] += p1*vv.w;
            Oacc[2][0] += p2*vv.x; Oacc[2][1] += p2*vv.y; Oacc[2][2] += p2*vv.z; Oacc[2][3] += p2*vv.w;
            Oacc[3][0] += p3*vv.x; Oacc[3][1] += p3*vv.y; Oacc[3][2] += p3*vv.z; Oacc[3][3] += p3*vv.w;
        }
    }

    // write O / l  -> att[b, t, h*64+d]
    int bb = bh >> 4, hh = bh & 15;
    #pragma unroll
    for (int a = 0; a < 4; a++) {
        int r = (ty << 2) + a;
        float inv = 1.0f / lrow[r];
        float4 o = make_float4(Oacc[a][0]*inv, Oacc[a][1]*inv,
                               Oacc[a][2]*inv, Oacc[a][3]*inv);
        *(float4*)(out + ((size_t)(bb * T_ + q0 + r)) * C_ + hh * D_ + (tx<<2)) = o;
    }
}

// ---------------- launch ----------------------------------------------------
extern "C" void kernel_launch(void* const* d_in, const int* in_sizes, int n_in,
                              void* d_out, int out_size)
{
    const float* x   = (const float*)d_in[0];
    const float* Wq  = (const float*)d_in[1];
    const float* Wk  = (const float*)d_in[2];
    const float* Wv  = (const float*)d_in[3];
    const float* Wo  = (const float*)d_in[4];
    const float* bo  = (const float*)d_in[5];
    const float* W1  = (const float*)d_in[6];
    const float* b1  = (const float*)d_in[7];
    const float* W2  = (const float*)d_in[8];
    const float* b2  = (const float*)d_in[9];
    const float* g1  = (const float*)d_in[10];
    const float* be1 = (const float*)d_in[11];
    const float* g2  = (const float*)d_in[12];
    const float* be2 = (const float*)d_in[13];
    float* out = (float*)d_out;

    float *h, *q, *k, *v, *att, *x1, *h2, *ff;
    cudaGetSymbolAddress((void**)&h,   g_h);
    cudaGetSymbolAddress((void**)&q,   g_q);
    cudaGetSymbolAddress((void**)&k,   g_k);
    cudaGetSymbolAddress((void**)&v,   g_v);
    cudaGetSymbolAddress((void**)&att, g_att);
    cudaGetSymbolAddress((void**)&x1,  g_x1);
    cudaGetSymbolAddress((void**)&h2,  g_h2);
    cudaGetSymbolAddress((void**)&ff,  g_ff);

    cudaFuncSetAttribute(attn_kernel,
        cudaFuncAttributeMaxDynamicSharedMemorySize, ATT_SMEM_BYTES);

    // 1) LN1
    ln_kernel<<<M_, 256>>>(x, g1, be1, h);
    // 2) QKV projections
    qkv_kernel<<<dim3(H_, M_/64, 3), 256>>>(h, Wq, Wk, Wv, q, k, v);
    // 3) causal flash attention
    attn_kernel<<<dim3(T_/64, B_*H_), 256, ATT_SMEM_BYTES>>>(q, k, v, att);
    // 4) Wo projection + bias + residual
    gemm_kernel<0,1><<<dim3(C_/64, M_/64), 256>>>(att, Wo, x1, M_, C_, C_, bo, x);
    // 5) LN2
    ln_kernel<<<M_, 256>>>(x1, g2, be2, h2);
    // 6) FFN up + ReLU
    gemm_kernel<1,0><<<dim3(F_/64, M_/64), 256>>>(h2, W1, ff, M_, F_, C_, b1, nullptr);
    // 7) FFN down + bias + residual -> final output
    gemm_kernel<0,1><<<dim3(C_/64, M_/64), 256>>>(ff, W2, out, M_, C_, F_, b2, x1);
}

// round 2
// speedup vs baseline: 1.6469x; 1.6469x over previous
#include <cuda_runtime.h>

#define B_ 2
#define T_ 2048
#define C_ 1024
#define H_ 16
#define D_ 64
#define F_ 4096
#define M_ (B_*T_)   // 4096 rows
#define QKVN 3072

// ---------------- scratch (device globals; no runtime allocation) ----------
__device__ __align__(16) float g_h  [M_*C_];    // ln1 out
__device__ __align__(16) float g_wp [C_*QKVN];  // packed Wqkv
__device__ __align__(16) float g_att[M_*C_];    // attn out (concat heads)
__device__ __align__(16) float g_x1 [M_*C_];    // attn residual out
__device__ __align__(16) float g_h2 [M_*C_];    // ln2 out
__device__ __align__(16) float g_ff [M_*F_];    // qkv activations, then ffn mid

__device__ __forceinline__ unsigned f2tf(float x) {
    unsigned r; asm("cvt.rna.tf32.f32 %0, %1;" : "=r"(r) : "f"(x)); return r;
}

// ---------------- LayerNorm: one block per row, 256 threads ----------------
__global__ __launch_bounds__(256) void ln_kernel(
    const float* __restrict__ x, const float* __restrict__ g,
    const float* __restrict__ b, float* __restrict__ out)
{
    int row = blockIdx.x;
    int tid = threadIdx.x;
    const float4 xv = ((const float4*)(x + (size_t)row*C_))[tid];
    float s  = xv.x + xv.y + xv.z + xv.w;
    float s2 = xv.x*xv.x + xv.y*xv.y + xv.z*xv.z + xv.w*xv.w;
    __shared__ float rs[8], rs2[8];
    #pragma unroll
    for (int o = 16; o; o >>= 1) {
        s  += __shfl_down_sync(0xffffffffu, s,  o);
        s2 += __shfl_down_sync(0xffffffffu, s2, o);
    }
    if ((tid & 31) == 0) { rs[tid>>5] = s; rs2[tid>>5] = s2; }
    __syncthreads();
    if (tid == 0) {
        float a = 0.f, c = 0.f;
        #pragma unroll
        for (int i = 0; i < 8; i++) { a += rs[i]; c += rs2[i]; }
        rs[0] = a; rs2[0] = c;
    }
    __syncthreads();
    float mean = rs[0] * (1.0f/C_);
    float var  = rs2[0] * (1.0f/C_) - mean*mean;
    float rstd = rsqrtf(var + 1e-5f);
    const float4 gv = ((const float4*)g)[tid];
    const float4 bv = ((const float4*)b)[tid];
    float4 o;
    o.x = (xv.x-mean)*rstd*gv.x + bv.x;
    o.y = (xv.y-mean)*rstd*gv.y + bv.y;
    o.z = (xv.z-mean)*rstd*gv.z + bv.z;
    o.w = (xv.w-mean)*rstd*gv.w + bv.w;
    ((float4*)(out + (size_t)row*C_))[tid] = o;
}

// ---------------- repack Wq/Wk/Wv [H][C][D] -> [C][3*C] --------------------
__global__ __launch_bounds__(256) void repack_kernel(
    const float* __restrict__ Wq, const float* __restrict__ Wk,
    const float* __restrict__ Wv, float* __restrict__ Wp)
{
    int idx = blockIdx.x*256 + threadIdx.x;        // over C*C
    int which = blockIdx.y;
    const float* W = (which==0) ? Wq : (which==1) ? Wk : Wv;
    int c = idx >> 10, n = idx & 1023;
    int h = n >> 6, d = n & 63;
    Wp[(size_t)c*QKVN + which*C_ + n] = W[((size_t)h*C_ + c)*D_ + d];
}

// ---------------- tf32 tensor-core GEMM, 128x128 block tile ----------------
// C[m,n] = A[m,:]*B[:,n] (+bias) (relu) (+res)
template<int RELU, int HASRES, int HASBIAS>
__global__ __launch_bounds__(256, 2) void tgemm(
    const float* __restrict__ A, const float* __restrict__ Bm,
    float* __restrict__ Cm, int M, int N, int K,
    const float* __restrict__ bias, const float* __restrict__ res)
{
    __shared__ unsigned As[32][132];   // [k][m], tf32 bits
    __shared__ unsigned Bs[32][132];   // [k][n]
    int tid = threadIdx.x;
    int m0 = blockIdx.y << 7, n0 = blockIdx.x << 7;
    int warp = tid >> 5, lane = tid & 31;
    int gid = lane >> 2, tig = lane & 3;
    int wm = (warp & 1) << 6;          // 0/64
    int wn = (warp >> 1) << 5;         // 0/32/64/96

    float acc[4][4][4] = {};           // [mt][nt][reg]

    int ra = tid & 127;                // A load: row within tile
    int ka = (tid >> 7) << 4;          // 0 or 16
    int kb = tid >> 3;                 // B load: k row 0..31
    int nb = (tid & 7) << 2;           // base col (float4)
    const float* Ap = A  + (size_t)(m0 + ra) * K + ka;
    const float* Bp = Bm + (size_t)kb * N + n0 + nb;

    for (int k0 = 0; k0 < K; k0 += 32) {
        #pragma unroll
        for (int i = 0; i < 4; i++) {
            float4 a4 = *(const float4*)(Ap + k0 + (i<<2));
            As[ka + (i<<2) + 0][ra] = f2tf(a4.x);
            As[ka + (i<<2) + 1][ra] = f2tf(a4.y);
            As[ka + (i<<2) + 2][ra] = f2tf(a4.z);
            As[ka + (i<<2) + 3][ra] = f2tf(a4.w);
        }
        #pragma unroll
        for (int i = 0; i < 4; i++) {
            float4 b4 = *(const float4*)(Bp + (size_t)k0 * N + (i<<5));
            uint4 tb;
            tb.x = f2tf(b4.x); tb.y = f2tf(b4.y);
            tb.z = f2tf(b4.z); tb.w = f2tf(b4.w);
            *(uint4*)&Bs[kb][nb + (i<<5)] = tb;
        }
        __syncthreads();
        #pragma unroll
        for (int kk = 0; kk < 4; kk++) {
            int ks = kk << 3;
            unsigned a[4][4], b[4][2];
            #pragma unroll
            for (int mt = 0; mt < 4; mt++) {
                int mr = wm + (mt<<4) + gid;
                a[mt][0] = As[ks + tig    ][mr    ];
                a[mt][1] = As[ks + tig    ][mr + 8];
                a[mt][2] = As[ks + tig + 4][mr    ];
                a[mt][3] = As[ks + tig + 4][mr + 8];
            }
            #pragma unroll
            for (int nt = 0; nt < 4; nt++) {
                int nc = wn + (nt<<3) + gid;
                b[nt][0] = Bs[ks + tig    ][nc];
                b[nt][1] = Bs[ks + tig + 4][nc];
            }
            #pragma unroll
            for (int mt = 0; mt < 4; mt++)
                #pragma unroll
                for (int nt = 0; nt < 4; nt++)
                    asm volatile(
                        "mma.sync.aligned.m16n8k8.row.col.f32.tf32.tf32.f32 "
                        "{%0,%1,%2,%3},{%4,%5,%6,%7},{%8,%9},{%0,%1,%2,%3};"
                        : "+f"(acc[mt][nt][0]), "+f"(acc[mt][nt][1]),
                          "+f"(acc[mt][nt][2]), "+f"(acc[mt][nt][3])
                        : "r"(a[mt][0]), "r"(a[mt][1]), "r"(a[mt][2]), "r"(a[mt][3]),
                          "r"(b[nt][0]), "r"(b[nt][1]));
        }
        __syncthreads();
    }

    // epilogue
    #pragma unroll
    for (int mt = 0; mt < 4; mt++) {
        int mr = m0 + wm + (mt<<4) + gid;
        #pragma unroll
        for (int nt = 0; nt < 4; nt++) {
            int nc = n0 + wn + (nt<<3) + (tig<<1);
            float2 bb = make_float2(0.f, 0.f);
            if (HASBIAS) bb = *(const float2*)(bias + nc);
            float2 o0 = make_float2(acc[mt][nt][0] + bb.x, acc[mt][nt][1] + bb.y);
            float2 o1 = make_float2(acc[mt][nt][2] + bb.x, acc[mt][nt][3] + bb.y);
            if (RELU) {
                o0.x = fmaxf(o0.x, 0.f); o0.y = fmaxf(o0.y, 0.f);
                o1.x = fmaxf(o1.x, 0.f); o1.y = fmaxf(o1.y, 0.f);
            }
            if (HASRES) {
                float2 r0 = *(const float2*)(res + (size_t)mr * N + nc);
                float2 r1 = *(const float2*)(res + (size_t)(mr+8) * N + nc);
                o0.x += r0.x; o0.y += r0.y;
                o1.x += r1.x; o1.y += r1.y;
            }
            *(float2*)(Cm + (size_t)mr     * N + nc) = o0;
            *(float2*)(Cm + (size_t)(mr+8) * N + nc) = o1;
        }
    }
}

// ---------------- flash attention (Br=Bc=64, online softmax) ---------------
// reads packed qkv activations [M][3072]: q at +0, k at +1024, v at +2048
#define ATT_SMEM_BYTES ((4*64*68 + 3*64) * 4)

__global__ __launch_bounds__(256) void attn_kernel(
    const float* __restrict__ qkv, float* __restrict__ out)
{
    extern __shared__ float sm[];
    float* Qs   = sm;                 // [64][68]  (pre-scaled)
    float* Kt   = Qs + 64*68;         // [d][j] transposed
    float* Vs   = Kt + 64*68;         // [j][d]
    float* Ss   = Vs + 64*68;         // [i][j]
    float* mrow = Ss + 64*68;         // [64]
    float* lrow = mrow + 64;
    float* arow = lrow + 64;

    int bh = blockIdx.y;              // b*H+h
    int qt = blockIdx.x;
    int q0 = qt << 6;
    int bb = bh >> 4, hh = bh & 15;
    const float* Qg = qkv + (size_t)(bb * T_) * QKVN + hh * D_;
    const float* Kg = Qg + C_;
    const float* Vg = Qg + 2*C_;
    int tid = threadIdx.x;
    int tx = tid & 15, ty = tid >> 4;
    const float scale = 0.03125f;     // C^-0.5

    {
        int r = tid >> 2, c0 = (tid & 3) << 4;
        #pragma unroll
        for (int u = 0; u < 4; u++) {
            float4 t4 = *(const float4*)(Qg + (size_t)(q0 + r) * QKVN + c0 + (u<<2));
            t4.x *= scale; t4.y *= scale; t4.z *= scale; t4.w *= scale;
            *(float4*)&Qs[r*68 + c0 + (u<<2)] = t4;
        }
    }
    if (tid < 64) { mrow[tid] = -1e30f; lrow[tid] = 0.f; }
    float Oacc[4][4] = {};

    for (int kt = 0; kt <= qt; kt++) {
        int k0 = kt << 6;
        __syncthreads();
        {
            int r = tid >> 2, c0 = (tid & 3) << 4;
            #pragma unroll
            for (int u = 0; u < 4; u++) {
                float4 kv4 = *(const float4*)(Kg + (size_t)(k0 + r) * QKVN + c0 + (u<<2));
                Kt[(c0 + (u<<2) + 0)*68 + r] = kv4.x;
                Kt[(c0 + (u<<2) + 1)*68 + r] = kv4.y;
                Kt[(c0 + (u<<2) + 2)*68 + r] = kv4.z;
                Kt[(c0 + (u<<2) + 3)*68 + r] = kv4.w;
                *(float4*)&Vs[r*68 + c0 + (u<<2)] =
                    *(const float4*)(Vg + (size_t)(k0 + r) * QKVN + c0 + (u<<2));
            }
        }
        __syncthreads();

        float sacc[4][4] = {};
        #pragma unroll 8
        for (int d = 0; d < 64; d++) {
            float qa0 = Qs[((ty<<2)+0)*68 + d];
            float qa1 = Qs[((ty<<2)+1)*68 + d];
            float qa2 = Qs[((ty<<2)+2)*68 + d];
            float qa3 = Qs[((ty<<2)+3)*68 + d];
            float4 kb = *(const float4*)&Kt[d*68 + (tx<<2)];
            sacc[0][0] += qa0*kb.x; sacc[0][1] += qa0*kb.y; sacc[0][2] += qa0*kb.z; sacc[0][3] += qa0*kb.w;
            sacc[1][0] += qa1*kb.x; sacc[1][1] += qa1*kb.y; sacc[1][2] += qa1*kb.z; sacc[1][3] += qa1*kb.w;
            sacc[2][0] += qa2*kb.x; sacc[2][1] += qa2*kb.y; sacc[2][2] += qa2*kb.z; sacc[2][3] += qa2*kb.w;
            sacc[3][0] += qa3*kb.x; sacc[3][1] += qa3*kb.y; sacc[3][2] += qa3*kb.z; sacc[3][3] += qa3*kb.w;
        }
        #pragma unroll
        for (int a = 0; a < 4; a++)
            *(float4*)&Ss[((ty<<2)+a)*68 + (tx<<2)] =
                make_float4(sacc[a][0], sacc[a][1], sacc[a][2], sacc[a][3]);
        __syncthreads();

        {
            bool diag = (kt == qt);
            int r = tid >> 2;
            int cb = (tid & 3) << 4;
            float sv[16];
            float mloc = -1e30f;
            #pragma unroll
            for (int c = 0; c < 16; c++) {
                float s = Ss[r*68 + cb + c];
                if (diag && (cb + c) > r) s = -1e30f;
                sv[c] = s;
                mloc = fmaxf(mloc, s);
            }
            mloc = fmaxf(mloc, __shfl_xor_sync(0xffffffffu, mloc, 1));
            mloc = fmaxf(mloc, __shfl_xor_sync(0xffffffffu, mloc, 2));
            float mold = mrow[r];
            float mnew = fmaxf(mold, mloc);
            float ls = 0.f;
            #pragma unroll
            for (int c = 0; c < 16; c++) {
                float e = __expf(sv[c] - mnew);
                Ss[r*68 + cb + c] = e;
                ls += e;
            }
            ls += __shfl_xor_sync(0xffffffffu, ls, 1);
            ls += __shfl_xor_sync(0xffffffffu, ls, 2);
            if ((tid & 3) == 0) {
                float al = __expf(mold - mnew);
                arow[r] = al;
                lrow[r] = lrow[r] * al + ls;
                mrow[r] = mnew;
            }
        }
        __syncthreads();

        #pragma unroll
        for (int a = 0; a < 4; a++) {
            float al = arow[(ty<<2) + a];
            Oacc[a][0] *= al; Oacc[a][1] *= al; Oacc[a][2] *= al; Oacc[a][3] *= al;
        }
        #pragma unroll 8
        for (int j = 0; j < 64; j++) {
            float p0 = Ss[((ty<<2)+0)*68 + j];
            float p1 = Ss[((ty<<2)+1)*68 + j];
            float p2 = Ss[((ty<<2)+2)*68 + j];
            float p3 = Ss[((ty<<2)+3)*68 + j];
            float4 vv = *(const float4*)&Vs[j*68 + (tx<<2)];
            Oacc[0][0] += p0*vv.x; Oacc[0][1] += p0*vv.y; Oacc[0][2] += p0*vv.z; Oacc[0][3] += p0*vv.w;
            Oacc[1][0] += p1*vv.x; Oacc[1][1] += p1*vv.y; Oacc[1][2] += p1*vv.z; Oacc[1][3] += p1*vv.w;
            Oacc[2][0] += p2*vv.x; Oacc[2][1] += p2*vv.y; Oacc[2][2] += p2*vv.z; Oacc[2][3] += p2*vv.w;
            Oacc[3][0] += p3*vv.x; Oacc[3][1] += p3*vv.y; Oacc[3][2] += p3*vv.z; Oacc[3][3] += p3*vv.w;
        }
    }

    #pragma unroll
    for (int a = 0; a < 4; a++) {
        int r = (ty << 2) + a;
        float inv = 1.0f / lrow[r];
        float4 o = make_float4(Oacc[a][0]*inv, Oacc[a][1]*inv,
                               Oacc[a][2]*inv, Oacc[a][3]*inv);
        *(float4*)(out + ((size_t)(bb * T_ + q0 + r)) * C_ + hh * D_ + (tx<<2)) = o;
    }
}

// ---------------- launch ----------------------------------------------------
extern "C" void kernel_launch(void* const* d_in, const int* in_sizes, int n_in,
                              void* d_out, int out_size)
{
    const float* x   = (const float*)d_in[0];
    const float* Wq  = (const float*)d_in[1];
    const float* Wk  = (const float*)d_in[2];
    const float* Wv  = (const float*)d_in[3];
    const float* Wo  = (const float*)d_in[4];
    const float* bo  = (const float*)d_in[5];
    const float* W1  = (const float*)d_in[6];
    const float* b1  = (const float*)d_in[7];
    const float* W2  = (const float*)d_in[8];
    const float* b2  = (const float*)d_in[9];
    const float* g1  = (const float*)d_in[10];
    const float* be1 = (const float*)d_in[11];
    const float* g2  = (const float*)d_in[12];
    const float* be2 = (const float*)d_in[13];
    float* out = (float*)d_out;

    float *h, *wp, *att, *x1, *h2, *ff;
    cudaGetSymbolAddress((void**)&h,   g_h);
    cudaGetSymbolAddress((void**)&wp,  g_wp);
    cudaGetSymbolAddress((void**)&att, g_att);
    cudaGetSymbolAddress((void**)&x1,  g_x1);
    cudaGetSymbolAddress((void**)&h2,  g_h2);
    cudaGetSymbolAddress((void**)&ff,  g_ff);

    cudaFuncSetAttribute(attn_kernel,
        cudaFuncAttributeMaxDynamicSharedMemorySize, ATT_SMEM_BYTES);

    // 1) LN1
    ln_kernel<<<M_, 256>>>(x, g1, be1, h);
    // 2) pack Wq/Wk/Wv -> [C][3C]
    repack_kernel<<<dim3((C_*C_)/256, 3), 256>>>(Wq, Wk, Wv, wp);
    // 3) fused QKV projection: [M,3072] = h @ Wqkv
    tgemm<0,0,0><<<dim3(QKVN/128, M_/128), 256>>>(h, wp, ff, M_, QKVN, C_, nullptr, nullptr);
    // 4) causal flash attention on packed qkv
    attn_kernel<<<dim3(T_/64, B_*H_), 256, ATT_SMEM_BYTES>>>(ff, att);
    // 5) Wo projection + bias + residual
    tgemm<0,1,1><<<dim3(C_/128, M_/128), 256>>>(att, Wo, x1, M_, C_, C_, bo, x);
    // 6) LN2
    ln_kernel<<<M_, 256>>>(x1, g2, be2, h2);
    // 7) FFN up + ReLU  (qkv in g_ff is dead now; reuse it)
    tgemm<1,0,1><<<dim3(F_/128, M_/128), 256>>>(h2, W1, ff, M_, F_, C_, b1, nullptr);
    // 8) FFN down + bias + residual -> final output
    tgemm<0,1,1><<<dim3(C_/128, M_/128), 256>>>(ff, W2, out, M_, C_, F_, b2, x1);
}

// round 3
// speedup vs baseline: 1.9352x; 1.1751x over previous
#include <cuda_runtime.h>

#define B_ 2
#define T_ 2048
#define C_ 1024
#define H_ 16
#define D_ 64
#define F_ 4096
#define M_ (B_*T_)   // 4096 rows
#define QKVN 3072

// ---------------- scratch (device globals; no runtime allocation) ----------
__device__ __align__(16) float g_h  [M_*C_];    // ln1 out
__device__ __align__(16) float g_wp [C_*QKVN];  // packed Wqkv
__device__ __align__(16) float g_att[M_*C_];    // attn out (concat heads)
__device__ __align__(16) float g_x1 [M_*C_];    // attn residual out
__device__ __align__(16) float g_h2 [M_*C_];    // ln2 out
__device__ __align__(16) float g_ff [M_*F_];    // qkv activations, then ffn mid

__device__ __forceinline__ unsigned f2tf(float x) {
    unsigned r; asm("cvt.rna.tf32.f32 %0, %1;" : "=r"(r) : "f"(x)); return r;
}

#define MMA_TF32(acc, a, b) \
    asm volatile( \
        "mma.sync.aligned.m16n8k8.row.col.f32.tf32.tf32.f32 " \
        "{%0,%1,%2,%3},{%4,%5,%6,%7},{%8,%9},{%0,%1,%2,%3};" \
        : "+f"((acc)[0]), "+f"((acc)[1]), "+f"((acc)[2]), "+f"((acc)[3]) \
        : "r"((a)[0]), "r"((a)[1]), "r"((a)[2]), "r"((a)[3]), \
          "r"((b)[0]), "r"((b)[1]))

// ---------------- LayerNorm: one block per row, 256 threads ----------------
__global__ __launch_bounds__(256) void ln_kernel(
    const float* __restrict__ x, const float* __restrict__ g,
    const float* __restrict__ b, float* __restrict__ out)
{
    int row = blockIdx.x;
    int tid = threadIdx.x;
    const float4 xv = ((const float4*)(x + (size_t)row*C_))[tid];
    float s  = xv.x + xv.y + xv.z + xv.w;
    float s2 = xv.x*xv.x + xv.y*xv.y + xv.z*xv.z + xv.w*xv.w;
    __shared__ float rs[8], rs2[8];
    #pragma unroll
    for (int o = 16; o; o >>= 1) {
        s  += __shfl_down_sync(0xffffffffu, s,  o);
        s2 += __shfl_down_sync(0xffffffffu, s2, o);
    }
    if ((tid & 31) == 0) { rs[tid>>5] = s; rs2[tid>>5] = s2; }
    __syncthreads();
    if (tid == 0) {
        float a = 0.f, c = 0.f;
        #pragma unroll
        for (int i = 0; i < 8; i++) { a += rs[i]; c += rs2[i]; }
        rs[0] = a; rs2[0] = c;
    }
    __syncthreads();
    float mean = rs[0] * (1.0f/C_);
    float var  = rs2[0] * (1.0f/C_) - mean*mean;
    float rstd = rsqrtf(var + 1e-5f);
    const float4 gv = ((const float4*)g)[tid];
    const float4 bv = ((const float4*)b)[tid];
    float4 o;
    o.x = (xv.x-mean)*rstd*gv.x + bv.x;
    o.y = (xv.y-mean)*rstd*gv.y + bv.y;
    o.z = (xv.z-mean)*rstd*gv.z + bv.z;
    o.w = (xv.w-mean)*rstd*gv.w + bv.w;
    ((float4*)(out + (size_t)row*C_))[tid] = o;
}

// ---------------- repack Wq/Wk/Wv [H][C][D] -> [C][3*C] --------------------
__global__ __launch_bounds__(256) void repack_kernel(
    const float* __restrict__ Wq, const float* __restrict__ Wk,
    const float* __restrict__ Wv, float* __restrict__ Wp)
{
    int idx = blockIdx.x*256 + threadIdx.x;        // over C*C
    int which = blockIdx.y;
    const float* W = (which==0) ? Wq : (which==1) ? Wk : Wv;
    int c = idx >> 10, n = idx & 1023;
    int h = n >> 6, d = n & 63;
    Wp[(size_t)c*QKVN + which*C_ + n] = W[((size_t)h*C_ + c)*D_ + d];
}

// ---------------- tf32 tensor-core GEMM, 128x128 block tile ----------------
template<int RELU, int HASRES, int HASBIAS>
__global__ __launch_bounds__(256, 2) void tgemm(
    const float* __restrict__ A, const float* __restrict__ Bm,
    float* __restrict__ Cm, int M, int N, int K,
    const float* __restrict__ bias, const float* __restrict__ res)
{
    __shared__ unsigned As[32][132];   // [k][m], tf32 bits
    __shared__ unsigned Bs[32][132];   // [k][n]
    int tid = threadIdx.x;
    int m0 = blockIdx.y << 7, n0 = blockIdx.x << 7;
    int warp = tid >> 5, lane = tid & 31;
    int gid = lane >> 2, tig = lane & 3;
    int wm = (warp & 1) << 6;
    int wn = (warp >> 1) << 5;

    float acc[4][4][4] = {};

    int ra = tid & 127;
    int ka = (tid >> 7) << 4;
    int kb = tid >> 3;
    int nb = (tid & 7) << 2;
    const float* Ap = A  + (size_t)(m0 + ra) * K + ka;
    const float* Bp = Bm + (size_t)kb * N + n0 + nb;

    for (int k0 = 0; k0 < K; k0 += 32) {
        #pragma unroll
        for (int i = 0; i < 4; i++) {
            float4 a4 = *(const float4*)(Ap + k0 + (i<<2));
            As[ka + (i<<2) + 0][ra] = f2tf(a4.x);
            As[ka + (i<<2) + 1][ra] = f2tf(a4.y);
            As[ka + (i<<2) + 2][ra] = f2tf(a4.z);
            As[ka + (i<<2) + 3][ra] = f2tf(a4.w);
        }
        #pragma unroll
        for (int i = 0; i < 4; i++) {
            float4 b4 = *(const float4*)(Bp + (size_t)k0 * N + (i<<5));
            uint4 tb;
            tb.x = f2tf(b4.x); tb.y = f2tf(b4.y);
            tb.z = f2tf(b4.z); tb.w = f2tf(b4.w);
            *(uint4*)&Bs[kb][nb + (i<<5)] = tb;
        }
        __syncthreads();
        #pragma unroll
        for (int kk = 0; kk < 4; kk++) {
            int ks = kk << 3;
            unsigned a[4][4], b[4][2];
            #pragma unroll
            for (int mt = 0; mt < 4; mt++) {
                int mr = wm + (mt<<4) + gid;
                a[mt][0] = As[ks + tig    ][mr    ];
                a[mt][1] = As[ks + tig    ][mr + 8];
                a[mt][2] = As[ks + tig + 4][mr    ];
                a[mt][3] = As[ks + tig + 4][mr + 8];
            }
            #pragma unroll
            for (int nt = 0; nt < 4; nt++) {
                int nc = wn + (nt<<3) + gid;
                b[nt][0] = Bs[ks + tig    ][nc];
                b[nt][1] = Bs[ks + tig + 4][nc];
            }
            #pragma unroll
            for (int mt = 0; mt < 4; mt++)
                #pragma unroll
                for (int nt = 0; nt < 4; nt++)
                    MMA_TF32(acc[mt][nt], a[mt], b[nt]);
        }
        __syncthreads();
    }

    #pragma unroll
    for (int mt = 0; mt < 4; mt++) {
        int mr = m0 + wm + (mt<<4) + gid;
        #pragma unroll
        for (int nt = 0; nt < 4; nt++) {
            int nc = n0 + wn + (nt<<3) + (tig<<1);
            float2 bb = make_float2(0.f, 0.f);
            if (HASBIAS) bb = *(const float2*)(bias + nc);
            float2 o0 = make_float2(acc[mt][nt][0] + bb.x, acc[mt][nt][1] + bb.y);
            float2 o1 = make_float2(acc[mt][nt][2] + bb.x, acc[mt][nt][3] + bb.y);
            if (RELU) {
                o0.x = fmaxf(o0.x, 0.f); o0.y = fmaxf(o0.y, 0.f);
                o1.x = fmaxf(o1.x, 0.f); o1.y = fmaxf(o1.y, 0.f);
            }
            if (HASRES) {
                float2 r0 = *(const float2*)(res + (size_t)mr * N + nc);
                float2 r1 = *(const float2*)(res + (size_t)(mr+8) * N + nc);
                o0.x += r0.x; o0.y += r0.y;
                o1.x += r1.x; o1.y += r1.y;
            }
            *(float2*)(Cm + (size_t)mr     * N + nc) = o0;
            *(float2*)(Cm + (size_t)(mr+8) * N + nc) = o1;
        }
    }
}

// ---------------- tensor-core flash attention (Br=128, Bc=64) ---------------
// reads packed qkv activations [M][3072]: q at +0, k at +1024, v at +2048
// smem: Kt[64][68] (tf32, [d][j]) | Vs[64][68] (tf32, [j][d]) |
//       Ss[128][68] (S floats, then P tf32 bits) | mrow/lrow/arow[128]
#define ATT_SMEM_FLOATS (64*68 + 64*68 + 128*68 + 3*128)
#define ATT_SMEM_BYTES  (ATT_SMEM_FLOATS*4)

__global__ __launch_bounds__(256, 2) void attn_kernel(
    const float* __restrict__ qkv, float* __restrict__ out)
{
    extern __shared__ float sm[];
    float* Kt   = sm;                // [d][j], tf32 bits
    float* Vs   = Kt + 64*68;        // [j][d], tf32 bits
    float* Ss   = Vs + 64*68;        // [i][j]
    float* mrow = Ss + 128*68;
    float* lrow = mrow + 128;
    float* arow = lrow + 128;

    int qt = (int)gridDim.x - 1 - (int)blockIdx.x;   // heavy tiles first
    int bh = blockIdx.y;
    int q0 = qt << 7;
    int bb = bh >> 4, hh = bh & 15;
    const float* Qg = qkv + (size_t)(bb * T_) * QKVN + hh * D_;
    const float* Kg = Qg + C_;
    const float* Vg = Qg + 2*C_;
    int tid = threadIdx.x;
    int warp = tid >> 5, lane = tid & 31;
    int gid = lane >> 2, tig = lane & 3;
    int i0 = warp << 4;              // warp's 16 Q rows
    const float scale = 0.03125f;    // C^-0.5

    // Q fragments, pre-scaled tf32, kept in registers for all KV tiles
    unsigned qa[8][4];
    {
        const float* q0p = Qg + (size_t)(q0 + i0 + gid) * QKVN;
        const float* q1p = q0p + 8 * QKVN;
        #pragma unroll
        for (int kk = 0; kk < 8; kk++) {
            int c = (kk<<3) + tig;
            qa[kk][0] = f2tf(scale * q0p[c]);
            qa[kk][1] = f2tf(scale * q1p[c]);
            qa[kk][2] = f2tf(scale * q0p[c+4]);
            qa[kk][3] = f2tf(scale * q1p[c+4]);
        }
    }
    if (tid < 128) { mrow[tid] = -1e30f; lrow[tid] = 0.f; }

    float oacc[8][4] = {};           // O = 16 x 64 per warp

    int ktmax = 2*qt + 1;
    for (int kt = 0; kt <= ktmax; kt++) {
        int k0 = kt << 6;
        __syncthreads();             // prev PV done; mrow/lrow init visible
        {   // load K (transposed) + V, tf32
            int r = tid >> 2, c0 = (tid & 3) << 4;
            const float* kp = Kg + (size_t)(k0 + r) * QKVN + c0;
            const float* vp = Vg + (size_t)(k0 + r) * QKVN + c0;
            #pragma unroll
            for (int u = 0; u < 4; u++) {
                float4 k4 = *(const float4*)(kp + (u<<2));
                int c = c0 + (u<<2);
                Kt[(c+0)*68 + r] = __uint_as_float(f2tf(k4.x));
                Kt[(c+1)*68 + r] = __uint_as_float(f2tf(k4.y));
                Kt[(c+2)*68 + r] = __uint_as_float(f2tf(k4.z));
                Kt[(c+3)*68 + r] = __uint_as_float(f2tf(k4.w));
                float4 v4 = *(const float4*)(vp + (u<<2));
                uint4 tv;
                tv.x = f2tf(v4.x); tv.y = f2tf(v4.y);
                tv.z = f2tf(v4.z); tv.w = f2tf(v4.w);
                *(uint4*)&Vs[r*68 + c] = tv;
            }
        }
        __syncthreads();

        // S = Q K^T  (tensor cores)
        {
            float sacc[8][4] = {};
            #pragma unroll
            for (int kk = 0; kk < 8; kk++) {
                int ks = kk << 3;
                #pragma unroll
                for (int nt = 0; nt < 8; nt++) {
                    unsigned b[2];
                    b[0] = __float_as_uint(Kt[(ks+tig  )*68 + (nt<<3) + gid]);
                    b[1] = __float_as_uint(Kt[(ks+tig+4)*68 + (nt<<3) + gid]);
                    MMA_TF32(sacc[nt], qa[kk], b);
                }
            }
            float* s0 = &Ss[(i0+gid)*68 + (tig<<1)];
            float* s1 = s0 + 8*68;
            #pragma unroll
            for (int nt = 0; nt < 8; nt++) {
                *(float2*)(s0 + (nt<<3)) = make_float2(sacc[nt][0], sacc[nt][1]);
                *(float2*)(s1 + (nt<<3)) = make_float2(sacc[nt][2], sacc[nt][3]);
            }
        }
        __syncwarp();                // warp's own 16 rows only

        // online softmax on warp's rows; writes P back as tf32 bits
        {
            int r  = i0 + ((lane) >> 1);        // 2 threads per row
            int co = (lane & 1) << 5;           // cols 0..31 / 32..63
            bool diag = (kt >= 2*qt);
            float sv[32];
            float mloc = -1e30f;
            #pragma unroll
            for (int u = 0; u < 8; u++) {
                float4 s4 = *(const float4*)&Ss[r*68 + co + (u<<2)];
                if (diag) {
                    int jb = k0 + co + (u<<2), ii = q0 + r;
                    if (jb+0 > ii) s4.x = -1e30f;
                    if (jb+1 > ii) s4.y = -1e30f;
                    if (jb+2 > ii) s4.z = -1e30f;
                    if (jb+3 > ii) s4.w = -1e30f;
                }
                sv[(u<<2)+0] = s4.x; sv[(u<<2)+1] = s4.y;
                sv[(u<<2)+2] = s4.z; sv[(u<<2)+3] = s4.w;
                mloc = fmaxf(mloc, fmaxf(fmaxf(s4.x, s4.y), fmaxf(s4.z, s4.w)));
            }
            mloc = fmaxf(mloc, __shfl_xor_sync(0xffffffffu, mloc, 1));
            float mold = mrow[r];
            float mnew = fmaxf(mold, mloc);
            float ls = 0.f;
            #pragma unroll
            for (int u = 0; u < 32; u++) {
                float e = __expf(sv[u] - mnew);
                ls += e;
                Ss[r*68 + co + u] = __uint_as_float(f2tf(e));
            }
            ls += __shfl_xor_sync(0xffffffffu, ls, 1);
            if ((lane & 1) == 0) {
                float al = __expf(mold - mnew);
                arow[r] = al;
                lrow[r] = lrow[r] * al + ls;
                mrow[r] = mnew;
            }
        }
        __syncwarp();

        // rescale O, accumulate P @ V  (tensor cores)
        {
            float al0 = arow[i0 + gid];
            float al1 = arow[i0 + gid + 8];
            #pragma unroll
            for (int nt = 0; nt < 8; nt++) {
                oacc[nt][0] *= al0; oacc[nt][1] *= al0;
                oacc[nt][2] *= al1; oacc[nt][3] *= al1;
            }
            const float* p0 = &Ss[(i0+gid)*68];
            const float* p1 = p0 + 8*68;
            #pragma unroll
            for (int kk = 0; kk < 8; kk++) {
                int ks = kk << 3;
                unsigned a[4];
                a[0] = __float_as_uint(p0[ks + tig]);
                a[1] = __float_as_uint(p1[ks + tig]);
                a[2] = __float_as_uint(p0[ks + tig + 4]);
                a[3] = __float_as_uint(p1[ks + tig + 4]);
                #pragma unroll
                for (int nt = 0; nt < 8; nt++) {
                    unsigned b[2];
                    b[0] = __float_as_uint(Vs[(ks+tig  )*68 + (nt<<3) + gid]);
                    b[1] = __float_as_uint(Vs[(ks+tig+4)*68 + (nt<<3) + gid]);
                    MMA_TF32(oacc[nt], a, b);
                }
            }
        }
    }
    __syncthreads();   // lrow final

    // normalize + write out[b, t, hh*64 + d]
    {
        float inv0 = 1.0f / lrow[i0 + gid];
        float inv1 = 1.0f / lrow[i0 + gid + 8];
        float* o0 = out + ((size_t)(bb * T_ + q0 + i0 + gid)) * C_ + hh * D_ + (tig<<1);
        float* o1 = o0 + 8 * C_;
        #pragma unroll
        for (int nt = 0; nt < 8; nt++) {
            *(float2*)(o0 + (nt<<3)) = make_float2(oacc[nt][0]*inv0, oacc[nt][1]*inv0);
            *(float2*)(o1 + (nt<<3)) = make_float2(oacc[nt][2]*inv1, oacc[nt][3]*inv1);
        }
    }
}

// ---------------- launch ----------------------------------------------------
extern "C" void kernel_launch(void* const* d_in, const int* in_sizes, int n_in,
                              void* d_out, int out_size)
{
    const float* x   = (const float*)d_in[0];
    const float* Wq  = (const float*)d_in[1];
    const float* Wk  = (const float*)d_in[2];
    const float* Wv  = (const float*)d_in[3];
    const float* Wo  = (const float*)d_in[4];
    const float* bo  = (const float*)d_in[5];
    const float* W1  = (const float*)d_in[6];
    const float* b1  = (const float*)d_in[7];
    const float* W2  = (const float*)d_in[8];
    const float* b2  = (const float*)d_in[9];
    const float* g1  = (const float*)d_in[10];
    const float* be1 = (const float*)d_in[11];
    const float* g2  = (const float*)d_in[12];
    const float* be2 = (const float*)d_in[13];
    float* out = (float*)d_out;

    float *h, *wp, *att, *x1, *h2, *ff;
    cudaGetSymbolAddress((void**)&h,   g_h);
    cudaGetSymbolAddress((void**)&wp,  g_wp);
    cudaGetSymbolAddress((void**)&att, g_att);
    cudaGetSymbolAddress((void**)&x1,  g_x1);
    cudaGetSymbolAddress((void**)&h2,  g_h2);
    cudaGetSymbolAddress((void**)&ff,  g_ff);

    cudaFuncSetAttribute(attn_kernel,
        cudaFuncAttributeMaxDynamicSharedMemorySize, ATT_SMEM_BYTES);

    // 1) LN1
    ln_kernel<<<M_, 256>>>(x, g1, be1, h);
    // 2) pack Wq/Wk/Wv -> [C][3C]
    repack_kernel<<<dim3((C_*C_)/256, 3), 256>>>(Wq, Wk, Wv, wp);
    // 3) fused QKV projection: [M,3072] = h @ Wqkv
    tgemm<0,0,0><<<dim3(QKVN/128, M_/128), 256>>>(h, wp, ff, M_, QKVN, C_, nullptr, nullptr);
    // 4) causal flash attention (tensor cores) on packed qkv
    attn_kernel<<<dim3(T_/128, B_*H_), 256, ATT_SMEM_BYTES>>>(ff, att);
    // 5) Wo projection + bias + residual
    tgemm<0,1,1><<<dim3(C_/128, M_/128), 256>>>(att, Wo, x1, M_, C_, C_, bo, x);
    // 6) LN2
    ln_kernel<<<M_, 256>>>(x1, g2, be2, h2);
    // 7) FFN up + ReLU
    tgemm<1,0,1><<<dim3(F_/128, M_/128), 256>>>(h2, W1, ff, M_, F_, C_, b1, nullptr);
    // 8) FFN down + bias + residual -> final output
    tgemm<0,1,1><<<dim3(C_/128, M_/128), 256>>>(ff, W2, out, M_, C_, F_, b2, x1);
}

// round 5
// speedup vs baseline: 2.7410x; 1.4164x over previous
#include <cuda_runtime.h>
#include <cuda_fp16.h>
#include <cstdint>

#define B_ 2
#define T_ 2048
#define C_ 1024
#define H_ 16
#define D_ 64
#define F_ 4096
#define M_ (B_*T_)   // 4096 rows
#define QKVN 3072

// ---------------- scratch (device globals; no runtime allocation) ----------
__device__ __align__(16) float g_h  [M_*C_];    // ln1 out
__device__ __align__(16) float g_wp [C_*QKVN];  // packed Wqkv
__device__ __align__(16) float g_att[M_*C_];    // attn out (concat heads)
__device__ __align__(16) float g_x1 [M_*C_];    // attn residual out
__device__ __align__(16) float g_h2 [M_*C_];    // ln2 out
__device__ __align__(16) float g_ff [M_*F_];    // qkv activations, then ffn mid

__device__ __forceinline__ uint32_t f2h2(float x, float y) {
    __half2 h = __floats2half2_rn(x, y);
    return *(uint32_t*)&h;
}

#define MMA_F16(acc, a, b) \
    asm volatile( \
        "mma.sync.aligned.m16n8k16.row.col.f32.f16.f16.f32 " \
        "{%0,%1,%2,%3},{%4,%5,%6,%7},{%8,%9},{%0,%1,%2,%3};" \
        : "+f"((acc)[0]), "+f"((acc)[1]), "+f"((acc)[2]), "+f"((acc)[3]) \
        : "r"((a)[0]), "r"((a)[1]), "r"((a)[2]), "r"((a)[3]), \
          "r"((b)[0]), "r"((b)[1]))

// ---------------- LayerNorm: one block per row, 256 threads ----------------
__global__ __launch_bounds__(256) void ln_kernel(
    const float* __restrict__ x, const float* __restrict__ g,
    const float* __restrict__ b, float* __restrict__ out)
{
    int row = blockIdx.x;
    int tid = threadIdx.x;
    const float4 xv = ((const float4*)(x + (size_t)row*C_))[tid];
    float s  = xv.x + xv.y + xv.z + xv.w;
    float s2 = xv.x*xv.x + xv.y*xv.y + xv.z*xv.z + xv.w*xv.w;
    __shared__ float rs[8], rs2[8];
    #pragma unroll
    for (int o = 16; o; o >>= 1) {
        s  += __shfl_down_sync(0xffffffffu, s,  o);
        s2 += __shfl_down_sync(0xffffffffu, s2, o);
    }
    if ((tid & 31) == 0) { rs[tid>>5] = s; rs2[tid>>5] = s2; }
    __syncthreads();
    if (tid == 0) {
        float a = 0.f, c = 0.f;
        #pragma unroll
        for (int i = 0; i < 8; i++) { a += rs[i]; c += rs2[i]; }
        rs[0] = a; rs2[0] = c;
    }
    __syncthreads();
    float mean = rs[0] * (1.0f/C_);
    float var  = rs2[0] * (1.0f/C_) - mean*mean;
    float rstd = rsqrtf(var + 1e-5f);
    const float4 gv = ((const float4*)g)[tid];
    const float4 bv = ((const float4*)b)[tid];
    float4 o;
    o.x = (xv.x-mean)*rstd*gv.x + bv.x;
    o.y = (xv.y-mean)*rstd*gv.y + bv.y;
    o.z = (xv.z-mean)*rstd*gv.z + bv.z;
    o.w = (xv.w-mean)*rstd*gv.w + bv.w;
    ((float4*)(out + (size_t)row*C_))[tid] = o;
}

// ---------------- repack Wq/Wk/Wv [H][C][D] -> [C][3*C] --------------------
__global__ __launch_bounds__(256) void repack_kernel(
    const float* __restrict__ Wq, const float* __restrict__ Wk,
    const float* __restrict__ Wv, float* __restrict__ Wp)
{
    int idx = blockIdx.x*256 + threadIdx.x;        // over C*C
    int which = blockIdx.y;
    const float* W = (which==0) ? Wq : (which==1) ? Wk : Wv;
    int c = idx >> 10, n = idx & 1023;
    int h = n >> 6, d = n & 63;
    Wp[(size_t)c*QKVN + which*C_ + n] = W[((size_t)h*C_ + c)*D_ + d];
}

// ---------------- fp16 tensor-core GEMM, 128x128 tile, double buffer -------
// As[buf][m][40 halves] (k-major rows, pad 8), Bs[buf][n][40 halves]
template<int RELU, int HASRES, int HASBIAS>
__global__ __launch_bounds__(256, 2) void tgemm(
    const float* __restrict__ A, const float* __restrict__ Bm,
    float* __restrict__ Cm, int M, int N, int K,
    const float* __restrict__ bias, const float* __restrict__ res)
{
    __shared__ __half As[2][128][40];
    __shared__ __half Bs[2][128][40];
    int tid = threadIdx.x;
    int m0 = blockIdx.y << 7, n0 = blockIdx.x << 7;
    int warp = tid >> 5, lane = tid & 31;
    int gid = lane >> 2, tig = lane & 3;
    int wm = (warp & 1) << 6;
    int wn = (warp >> 1) << 5;

    float acc[4][4][4] = {};

    int ra = tid >> 1, ca = (tid & 1) << 4;   // A: row, 16-float col base
    int rb = tid & 31, cb = (tid >> 5) << 4;  // B: k-row, 16-float n base
    const float* Ap = A  + (size_t)(m0 + ra) * K + ca;
    const float* Bp = Bm + (size_t)rb * N + n0 + cb;

    int KT = K >> 5;
    float4 av[4], bv[4];

    // prologue: tile 0
    #pragma unroll
    for (int u = 0; u < 4; u++) av[u] = *(const float4*)(Ap + (u<<2));
    #pragma unroll
    for (int u = 0; u < 4; u++) bv[u] = *(const float4*)(Bp + (u<<2));
    {
        uint32_t* aw = (uint32_t*)&As[0][ra][ca];
        uint4 w0, w1;
        w0.x = f2h2(av[0].x, av[0].y); w0.y = f2h2(av[0].z, av[0].w);
        w0.z = f2h2(av[1].x, av[1].y); w0.w = f2h2(av[1].z, av[1].w);
        w1.x = f2h2(av[2].x, av[2].y); w1.y = f2h2(av[2].z, av[2].w);
        w1.z = f2h2(av[3].x, av[3].y); w1.w = f2h2(av[3].z, av[3].w);
        *(uint4*)aw = w0; *(uint4*)(aw + 4) = w1;
        #pragma unroll
        for (int u = 0; u < 4; u++) {
            float e[4] = {bv[u].x, bv[u].y, bv[u].z, bv[u].w};
            #pragma unroll
            for (int i = 0; i < 4; i++)
                Bs[0][cb + (u<<2) + i][rb] = __float2half_rn(e[i]);
        }
    }
    __syncthreads();

    for (int kt = 0; kt < KT; kt++) {
        int buf = kt & 1;
        if (kt + 1 < KT) {
            int k0 = (kt + 1) << 5;
            #pragma unroll
            for (int u = 0; u < 4; u++) av[u] = *(const float4*)(Ap + k0 + (u<<2));
            #pragma unroll
            for (int u = 0; u < 4; u++) bv[u] = *(const float4*)(Bp + (size_t)k0 * N + (u<<2));
        }
        // compute on buf
        const uint32_t* aw = (const uint32_t*)&As[buf][0][0];
        const uint32_t* bw = (const uint32_t*)&Bs[buf][0][0];
        #pragma unroll
        for (int ks = 0; ks < 2; ks++) {
            unsigned a[4][4], b[4][2];
            #pragma unroll
            for (int mt = 0; mt < 4; mt++) {
                int base = (wm + (mt<<4) + gid)*20 + (ks<<3) + tig;
                a[mt][0] = aw[base];       a[mt][2] = aw[base + 4];
                a[mt][1] = aw[base + 160]; a[mt][3] = aw[base + 164];
            }
            #pragma unroll
            for (int nt = 0; nt < 4; nt++) {
                int base = (wn + (nt<<3) + gid)*20 + (ks<<3) + tig;
                b[nt][0] = bw[base]; b[nt][1] = bw[base + 4];
            }
            #pragma unroll
            for (int mt = 0; mt < 4; mt++)
                #pragma unroll
                for (int nt = 0; nt < 4; nt++)
                    MMA_F16(acc[mt][nt], a[mt], b[nt]);
        }
        if (kt + 1 < KT) {
            int nb = buf ^ 1;
            uint32_t* awd = (uint32_t*)&As[nb][ra][ca];
            uint4 w0, w1;
            w0.x = f2h2(av[0].x, av[0].y); w0.y = f2h2(av[0].z, av[0].w);
            w0.z = f2h2(av[1].x, av[1].y); w0.w = f2h2(av[1].z, av[1].w);
            w1.x = f2h2(av[2].x, av[2].y); w1.y = f2h2(av[2].z, av[2].w);
            w1.z = f2h2(av[3].x, av[3].y); w1.w = f2h2(av[3].z, av[3].w);
            *(uint4*)awd = w0; *(uint4*)(awd + 4) = w1;
            #pragma unroll
            for (int u = 0; u < 4; u++) {
                float e[4] = {bv[u].x, bv[u].y, bv[u].z, bv[u].w};
                #pragma unroll
                for (int i = 0; i < 4; i++)
                    Bs[nb][cb + (u<<2) + i][rb] = __float2half_rn(e[i]);
            }
            __syncthreads();
        }
    }

    // epilogue
    #pragma unroll
    for (int mt = 0; mt < 4; mt++) {
        int mr = m0 + wm + (mt<<4) + gid;
        #pragma unroll
        for (int nt = 0; nt < 4; nt++) {
            int nc = n0 + wn + (nt<<3) + (tig<<1);
            float2 bb = make_float2(0.f, 0.f);
            if (HASBIAS) bb = *(const float2*)(bias + nc);
            float2 o0 = make_float2(acc[mt][nt][0] + bb.x, acc[mt][nt][1] + bb.y);
            float2 o1 = make_float2(acc[mt][nt][2] + bb.x, acc[mt][nt][3] + bb.y);
            if (RELU) {
                o0.x = fmaxf(o0.x, 0.f); o0.y = fmaxf(o0.y, 0.f);
                o1.x = fmaxf(o1.x, 0.f); o1.y = fmaxf(o1.y, 0.f);
            }
            if (HASRES) {
                float2 r0 = *(const float2*)(res + (size_t)mr * N + nc);
                float2 r1 = *(const float2*)(res + (size_t)(mr+8) * N + nc);
                o0.x += r0.x; o0.y += r0.y;
                o1.x += r1.x; o1.y += r1.y;
            }
            *(float2*)(Cm + (size_t)mr     * N + nc) = o0;
            *(float2*)(Cm + (size_t)(mr+8) * N + nc) = o1;
        }
    }
}

// ---------------- fp16 tensor-core flash attention (Br=128, Bc=64) ---------
// smem floats: Ss[128][68] | Ps 128x72 half | Ks 64x72 half | Vt 64x72 half |
//              mrow/lrow/arow[128]
#define ATT_SS    0
#define ATT_PS    (128*68)                 // float offset
#define ATT_KS    (ATT_PS + 128*72/2)
#define ATT_VT    (ATT_KS + 64*72/2)
#define ATT_ROWS  (ATT_VT + 64*72/2)
#define ATT_SMEM_FLOATS (ATT_ROWS + 3*128)
#define ATT_SMEM_BYTES  (ATT_SMEM_FLOATS*4)

__global__ __launch_bounds__(256, 2) void attn_kernel(
    const float* __restrict__ qkv, float* __restrict__ out)
{
    extern __shared__ float sm[];
    float*    Ss   = sm;
    uint32_t* Pw   = (uint32_t*)(sm + ATT_PS);   // halves, row stride 36 words
    uint32_t* Kw   = (uint32_t*)(sm + ATT_KS);   // [j][d] halves, stride 36 words
    uint32_t* Vw   = (uint32_t*)(sm + ATT_VT);   // [d][j] halves, stride 36 words
    __half*   Vth  = (__half*)Vw;
    float* mrow = sm + ATT_ROWS;
    float* lrow = mrow + 128;
    float* arow = lrow + 128;

    int qt = (int)gridDim.x - 1 - (int)blockIdx.x;   // heavy tiles first
    int bh = blockIdx.y;
    int q0 = qt << 7;
    int bb = bh >> 4, hh = bh & 15;
    const float* Qg = qkv + (size_t)(bb * T_) * QKVN + hh * D_;
    const float* Kg = Qg + C_;
    const float* Vg = Qg + 2*C_;
    int tid = threadIdx.x;
    int warp = tid >> 5, lane = tid & 31;
    int gid = lane >> 2, tig = lane & 3;
    int i0 = warp << 4;
    const float scale = 0.03125f;    // C^-0.5

    // Q fragments (fp16, pre-scaled), registers for all KV tiles
    unsigned qa[4][4];
    {
        const float* q0p = Qg + (size_t)(q0 + i0 + gid) * QKVN;
        const float* q1p = q0p + 8 * QKVN;
        #pragma unroll
        for (int ks = 0; ks < 4; ks++) {
            int c = (ks<<4) + (tig<<1);
            qa[ks][0] = f2h2(scale*q0p[c],   scale*q0p[c+1]);
            qa[ks][1] = f2h2(scale*q1p[c],   scale*q1p[c+1]);
            qa[ks][2] = f2h2(scale*q0p[c+8], scale*q0p[c+9]);
            qa[ks][3] = f2h2(scale*q1p[c+8], scale*q1p[c+9]);
        }
    }
    if (tid < 128) { mrow[tid] = -1e30f; lrow[tid] = 0.f; }

    float oacc[8][4] = {};

    int ktmax = 2*qt + 1;
    for (int kt = 0; kt <= ktmax; kt++) {
        int k0 = kt << 6;
        __syncthreads();
        {   // load K natural [j][d] (half2 words) + V transposed [d][j]
            int r = tid >> 2, c0 = (tid & 3) << 4;
            const float* kp = Kg + (size_t)(k0 + r) * QKVN + c0;
            const float* vp = Vg + (size_t)(k0 + r) * QKVN + c0;
            #pragma unroll
            for (int u = 0; u < 4; u++) {
                float4 k4 = *(const float4*)(kp + (u<<2));
                int w = r*36 + (c0>>1) + (u<<1);
                Kw[w]   = f2h2(k4.x, k4.y);
                Kw[w+1] = f2h2(k4.z, k4.w);
                float4 v4 = *(const float4*)(vp + (u<<2));
                int c = c0 + (u<<2);
                Vth[(c+0)*72 + r] = __float2half_rn(v4.x);
                Vth[(c+1)*72 + r] = __float2half_rn(v4.y);
                Vth[(c+2)*72 + r] = __float2half_rn(v4.z);
                Vth[(c+3)*72 + r] = __float2half_rn(v4.w);
            }
        }
        __syncthreads();

        // S = Q K^T  (fp16 mma)
        {
            float sacc[8][4] = {};
            #pragma unroll
            for (int ks = 0; ks < 4; ks++) {
                #pragma unroll
                for (int nt = 0; nt < 8; nt++) {
                    unsigned b[2];
                    int base = ((nt<<3) + gid)*36 + (ks<<3) + tig;
                    b[0] = Kw[base]; b[1] = Kw[base + 4];
                    MMA_F16(sacc[nt], qa[ks], b);
                }
            }
            float* s0 = &Ss[(i0+gid)*68 + (tig<<1)];
            float* s1 = s0 + 8*68;
            #pragma unroll
            for (int nt = 0; nt < 8; nt++) {
                *(float2*)(s0 + (nt<<3)) = make_float2(sacc[nt][0], sacc[nt][1]);
                *(float2*)(s1 + (nt<<3)) = make_float2(sacc[nt][2], sacc[nt][3]);
            }
        }
        __syncwarp();

        // online softmax on warp's 16 rows; writes P (half)
        {
            int r  = i0 + (lane >> 1);
            int co = (lane & 1) << 5;
            bool diag = (kt >= 2*qt);
            float sv[32];
            float mloc = -1e30f;
            #pragma unroll
            for (int u = 0; u < 8; u++) {
                float4 s4 = *(const float4*)&Ss[r*68 + co + (u<<2)];
                if (diag) {
                    int jb = k0 + co + (u<<2), ii = q0 + r;
                    if (jb+0 > ii) s4.x = -1e30f;
                    if (jb+1 > ii) s4.y = -1e30f;
                    if (jb+2 > ii) s4.z = -1e30f;
                    if (jb+3 > ii) s4.w = -1e30f;
                }
                sv[(u<<2)+0] = s4.x; sv[(u<<2)+1] = s4.y;
                sv[(u<<2)+2] = s4.z; sv[(u<<2)+3] = s4.w;
                mloc = fmaxf(mloc, fmaxf(fmaxf(s4.x, s4.y), fmaxf(s4.z, s4.w)));
            }
            mloc = fmaxf(mloc, __shfl_xor_sync(0xffffffffu, mloc, 1));
            float mold = mrow[r];
            float mnew = fmaxf(mold, mloc);
            float ls = 0.f;
            int wbase = r*36 + (co>>1);
            #pragma unroll
            for (int u = 0; u < 16; u++) {
                float e0 = __expf(sv[(u<<1)]   - mnew);
                float e1 = __expf(sv[(u<<1)+1] - mnew);
                ls += e0 + e1;
                Pw[wbase + u] = f2h2(e0, e1);
            }
            ls += __shfl_xor_sync(0xffffffffu, ls, 1);
            if ((lane & 1) == 0) {
                float al = __expf(mold - mnew);
                arow[r] = al;
                lrow[r] = lrow[r] * al + ls;
                mrow[r] = mnew;
            }
        }
        __syncwarp();

        // rescale O, accumulate P @ V  (fp16 mma)
        {
            float al0 = arow[i0 + gid];
            float al1 = arow[i0 + gid + 8];
            #pragma unroll
            for (int nt = 0; nt < 8; nt++) {
                oacc[nt][0] *= al0; oacc[nt][1] *= al0;
                oacc[nt][2] *= al1; oacc[nt][3] *= al1;
            }
            #pragma unroll
            for (int ks = 0; ks < 4; ks++) {
                unsigned a[4];
                int abase = (i0 + gid)*36 + (ks<<3) + tig;
                a[0] = Pw[abase];       a[2] = Pw[abase + 4];
                a[1] = Pw[abase + 288]; a[3] = Pw[abase + 292];
                #pragma unroll
                for (int nt = 0; nt < 8; nt++) {
                    unsigned b[2];
                    int base = ((nt<<3) + gid)*36 + (ks<<3) + tig;
                    b[0] = Vw[base]; b[1] = Vw[base + 4];
                    MMA_F16(oacc[nt], a, b);
                }
            }
        }
    }
    __syncthreads();

    // normalize + write out[b, t, hh*64 + d]
    {
        float inv0 = 1.0f / lrow[i0 + gid];
        float inv1 = 1.0f / lrow[i0 + gid + 8];
        float* o0 = out + ((size_t)(bb * T_ + q0 + i0 + gid)) * C_ + hh * D_ + (tig<<1);
        float* o1 = o0 + 8 * C_;
        #pragma unroll
        for (int nt = 0; nt < 8; nt++) {
            *(float2*)(o0 + (nt<<3)) = make_float2(oacc[nt][0]*inv0, oacc[nt][1]*inv0);
            *(float2*)(o1 + (nt<<3)) = make_float2(oacc[nt][2]*inv1, oacc[nt][3]*inv1);
        }
    }
}

// ---------------- launch ----------------------------------------------------
extern "C" void kernel_launch(void* const* d_in, const int* in_sizes, int n_in,
                              void* d_out, int out_size)
{
    const float* x   = (const float*)d_in[0];
    const float* Wq  = (const float*)d_in[1];
    const float* Wk  = (const float*)d_in[2];
    const float* Wv  = (const float*)d_in[3];
    const float* Wo  = (const float*)d_in[4];
    const float* bo  = (const float*)d_in[5];
    const float* W1  = (const float*)d_in[6];
    const float* b1  = (const float*)d_in[7];
    const float* W2  = (const float*)d_in[8];
    const float* b2  = (const float*)d_in[9];
    const float* g1  = (const float*)d_in[10];
    const float* be1 = (const float*)d_in[11];
    const float* g2  = (const float*)d_in[12];
    const float* be2 = (const float*)d_in[13];
    float* out = (float*)d_out;

    float *h, *wp, *att, *x1, *h2, *ff;
    cudaGetSymbolAddress((void**)&h,   g_h);
    cudaGetSymbolAddress((void**)&wp,  g_wp);
    cudaGetSymbolAddress((void**)&att, g_att);
    cudaGetSymbolAddress((void**)&x1,  g_x1);
    cudaGetSymbolAddress((void**)&h2,  g_h2);
    cudaGetSymbolAddress((void**)&ff,  g_ff);

    cudaFuncSetAttribute(attn_kernel,
        cudaFuncAttributeMaxDynamicSharedMemorySize, ATT_SMEM_BYTES);

    // 1) LN1
    ln_kernel<<<M_, 256>>>(x, g1, be1, h);
    // 2) pack Wq/Wk/Wv -> [C][3C]
    repack_kernel<<<dim3((C_*C_)/256, 3), 256>>>(Wq, Wk, Wv, wp);
    // 3) fused QKV projection: [M,3072] = h @ Wqkv
    tgemm<0,0,0><<<dim3(QKVN/128, M_/128), 256>>>(h, wp, ff, M_, QKVN, C_, nullptr, nullptr);
    // 4) causal flash attention (fp16 mma) on packed qkv
    attn_kernel<<<dim3(T_/128, B_*H_), 256, ATT_SMEM_BYTES>>>(ff, att);
    // 5) Wo projection + bias + residual
    tgemm<0,1,1><<<dim3(C_/128, M_/128), 256>>>(att, Wo, x1, M_, C_, C_, bo, x);
    // 6) LN2
    ln_kernel<<<M_, 256>>>(x1, g2, be2, h2);
    // 7) FFN up + ReLU
    tgemm<1,0,1><<<dim3(F_/128, M_/128), 256>>>(h2, W1, ff, M_, F_, C_, b1, nullptr);
    // 8) FFN down + bias + residual -> final output
    tgemm<0,1,1><<<dim3(C_/128, M_/128), 256>>>(ff, W2, out, M_, C_, F_, b2, x1);
}

// round 6
// speedup vs baseline: 3.6929x; 1.3473x over previous
#include <cuda_runtime.h>
#include <cuda_fp16.h>
#include <cstdint>

#define B_ 2
#define T_ 2048
#define C_ 1024
#define H_ 16
#define D_ 64
#define F_ 4096
#define M_ (B_*T_)   // 4096 rows
#define QKVN 3072

// ---------------- scratch (device globals; no runtime allocation) ----------
__device__ __align__(16) float g_h  [M_*C_];    // ln1 out
__device__ __align__(16) float g_wp [C_*QKVN];  // packed Wqkv
__device__ __align__(16) float g_att[M_*C_];    // attn out (concat heads)
__device__ __align__(16) float g_x1 [M_*C_];    // attn residual out
__device__ __align__(16) float g_h2 [M_*C_];    // ln2 out
__device__ __align__(16) float g_ff [M_*F_];    // qkv activations, then ffn mid

__device__ __forceinline__ uint32_t f2h2(float x, float y) {
    __half2 h = __floats2half2_rn(x, y);
    return *(uint32_t*)&h;
}
__device__ __forceinline__ uint32_t su32(const void* p) {
    return (uint32_t)__cvta_generic_to_shared(p);
}

#define MMA_F16(acc, a, b) \
    asm volatile( \
        "mma.sync.aligned.m16n8k16.row.col.f32.f16.f16.f32 " \
        "{%0,%1,%2,%3},{%4,%5,%6,%7},{%8,%9},{%0,%1,%2,%3};" \
        : "+f"((acc)[0]), "+f"((acc)[1]), "+f"((acc)[2]), "+f"((acc)[3]) \
        : "r"((a)[0]), "r"((a)[1]), "r"((a)[2]), "r"((a)[3]), \
          "r"((b)[0]), "r"((b)[1]))

#define LDSM4(r0, r1, r2, r3, addr) \
    asm volatile("ldmatrix.sync.aligned.m8n8.x4.shared.b16 {%0,%1,%2,%3}, [%4];" \
        : "=r"(r0), "=r"(r1), "=r"(r2), "=r"(r3) : "r"(addr))
#define LDSM4T(r0, r1, r2, r3, addr) \
    asm volatile("ldmatrix.sync.aligned.m8n8.x4.trans.shared.b16 {%0,%1,%2,%3}, [%4];" \
        : "=r"(r0), "=r"(r1), "=r"(r2), "=r"(r3) : "r"(addr))

// ---------------- LayerNorm: one block per row, 256 threads ----------------
__global__ __launch_bounds__(256) void ln_kernel(
    const float* __restrict__ x, const float* __restrict__ g,
    const float* __restrict__ b, float* __restrict__ out)
{
    int row = blockIdx.x;
    int tid = threadIdx.x;
    const float4 xv = ((const float4*)(x + (size_t)row*C_))[tid];
    float s  = xv.x + xv.y + xv.z + xv.w;
    float s2 = xv.x*xv.x + xv.y*xv.y + xv.z*xv.z + xv.w*xv.w;
    __shared__ float rs[8], rs2[8];
    #pragma unroll
    for (int o = 16; o; o >>= 1) {
        s  += __shfl_down_sync(0xffffffffu, s,  o);
        s2 += __shfl_down_sync(0xffffffffu, s2, o);
    }
    if ((tid & 31) == 0) { rs[tid>>5] = s; rs2[tid>>5] = s2; }
    __syncthreads();
    if (tid == 0) {
        float a = 0.f, c = 0.f;
        #pragma unroll
        for (int i = 0; i < 8; i++) { a += rs[i]; c += rs2[i]; }
        rs[0] = a; rs2[0] = c;
    }
    __syncthreads();
    float mean = rs[0] * (1.0f/C_);
    float var  = rs2[0] * (1.0f/C_) - mean*mean;
    float rstd = rsqrtf(var + 1e-5f);
    const float4 gv = ((const float4*)g)[tid];
    const float4 bv = ((const float4*)b)[tid];
    float4 o;
    o.x = (xv.x-mean)*rstd*gv.x + bv.x;
    o.y = (xv.y-mean)*rstd*gv.y + bv.y;
    o.z = (xv.z-mean)*rstd*gv.z + bv.z;
    o.w = (xv.w-mean)*rstd*gv.w + bv.w;
    ((float4*)(out + (size_t)row*C_))[tid] = o;
}

// ---------------- repack Wq/Wk/Wv [H][C][D] -> [C][3*C] --------------------
__global__ __launch_bounds__(256) void repack_kernel(
    const float* __restrict__ Wq, const float* __restrict__ Wk,
    const float* __restrict__ Wv, float* __restrict__ Wp)
{
    int idx = blockIdx.x*256 + threadIdx.x;        // over C*C
    int which = blockIdx.y;
    const float* W = (which==0) ? Wq : (which==1) ? Wk : Wv;
    int c = idx >> 10, n = idx & 1023;
    int h = n >> 6, d = n & 63;
    Wp[(size_t)c*QKVN + which*C_ + n] = W[((size_t)h*C_ + c)*D_ + d];
}

// ---------------- fp16 tensor-core GEMM, 128x128 tile, double buffer -------
// As[buf][m][40 halves] (k-major rows, pad 8), Bs[buf][k][136 halves] natural
template<int RELU, int HASRES, int HASBIAS>
__global__ __launch_bounds__(256, 2) void tgemm(
    const float* __restrict__ A, const float* __restrict__ Bm,
    float* __restrict__ Cm, int M, int N, int K,
    const float* __restrict__ bias, const float* __restrict__ res)
{
    __shared__ __half As[2][128][40];
    __shared__ __half Bs[2][32][136];
    int tid = threadIdx.x;
    int m0 = blockIdx.y << 7, n0 = blockIdx.x << 7;
    int warp = tid >> 5, lane = tid & 31;
    int l16 = lane & 15, l2 = lane >> 4;
    int gid = lane >> 2, tig = lane & 3;
    int wm = (warp & 1) << 6;
    int wn = (warp >> 1) << 5;

    float acc[4][4][4] = {};

    int ra = tid >> 1, ca = (tid & 1) << 4;   // A: row, 16-float col base
    int rb = tid >> 3, cb = (tid & 7) << 4;   // B: k-row, 16-float n base
    const float* Ap = A  + (size_t)(m0 + ra) * K + ca;
    const float* Bp = Bm + (size_t)rb * N + n0 + cb;

    int KT = K >> 5;
    float4 av[4], bv[4];

    // prologue: tile 0
    #pragma unroll
    for (int u = 0; u < 4; u++) av[u] = *(const float4*)(Ap + (u<<2));
    #pragma unroll
    for (int u = 0; u < 4; u++) bv[u] = *(const float4*)(Bp + (u<<2));
    {
        uint32_t* aw = (uint32_t*)&As[0][ra][ca];
        uint4 w0, w1;
        w0.x = f2h2(av[0].x, av[0].y); w0.y = f2h2(av[0].z, av[0].w);
        w0.z = f2h2(av[1].x, av[1].y); w0.w = f2h2(av[1].z, av[1].w);
        w1.x = f2h2(av[2].x, av[2].y); w1.y = f2h2(av[2].z, av[2].w);
        w1.z = f2h2(av[3].x, av[3].y); w1.w = f2h2(av[3].z, av[3].w);
        *(uint4*)aw = w0; *(uint4*)(aw + 4) = w1;
        uint32_t* bw = (uint32_t*)&Bs[0][rb][cb];
        uint4 x0, x1;
        x0.x = f2h2(bv[0].x, bv[0].y); x0.y = f2h2(bv[0].z, bv[0].w);
        x0.z = f2h2(bv[1].x, bv[1].y); x0.w = f2h2(bv[1].z, bv[1].w);
        x1.x = f2h2(bv[2].x, bv[2].y); x1.y = f2h2(bv[2].z, bv[2].w);
        x1.z = f2h2(bv[3].x, bv[3].y); x1.w = f2h2(bv[3].z, bv[3].w);
        *(uint4*)bw = x0; *(uint4*)(bw + 4) = x1;
    }
    __syncthreads();

    for (int kt = 0; kt < KT; kt++) {
        int buf = kt & 1;
        if (kt + 1 < KT) {
            int k0 = (kt + 1) << 5;
            #pragma unroll
            for (int u = 0; u < 4; u++) av[u] = *(const float4*)(Ap + k0 + (u<<2));
            #pragma unroll
            for (int u = 0; u < 4; u++) bv[u] = *(const float4*)(Bp + (size_t)k0 * N + (u<<2));
        }
        // compute on buf (ldmatrix fragments)
        #pragma unroll
        for (int ks = 0; ks < 2; ks++) {
            unsigned a[4][4], b[4][2];
            #pragma unroll
            for (int mt = 0; mt < 4; mt++) {
                uint32_t ad = su32(&As[buf][wm + (mt<<4) + l16][(ks<<4) + (l2<<3)]);
                LDSM4(a[mt][0], a[mt][1], a[mt][2], a[mt][3], ad);
            }
            #pragma unroll
            for (int np = 0; np < 2; np++) {
                uint32_t bd = su32(&Bs[buf][(ks<<4) + l16][wn + (np<<4) + (l2<<3)]);
                uint32_t r0, r1, r2, r3;
                LDSM4T(r0, r1, r2, r3, bd);
                b[2*np][0] = r0; b[2*np][1] = r1;
                b[2*np+1][0] = r2; b[2*np+1][1] = r3;
            }
            #pragma unroll
            for (int mt = 0; mt < 4; mt++)
                #pragma unroll
                for (int nt = 0; nt < 4; nt++)
                    MMA_F16(acc[mt][nt], a[mt], b[nt]);
        }
        if (kt + 1 < KT) {
            int nb = buf ^ 1;
            uint32_t* awd = (uint32_t*)&As[nb][ra][ca];
            uint4 w0, w1;
            w0.x = f2h2(av[0].x, av[0].y); w0.y = f2h2(av[0].z, av[0].w);
            w0.z = f2h2(av[1].x, av[1].y); w0.w = f2h2(av[1].z, av[1].w);
            w1.x = f2h2(av[2].x, av[2].y); w1.y = f2h2(av[2].z, av[2].w);
            w1.z = f2h2(av[3].x, av[3].y); w1.w = f2h2(av[3].z, av[3].w);
            *(uint4*)awd = w0; *(uint4*)(awd + 4) = w1;
            uint32_t* bwd = (uint32_t*)&Bs[nb][rb][cb];
            uint4 x0, x1;
            x0.x = f2h2(bv[0].x, bv[0].y); x0.y = f2h2(bv[0].z, bv[0].w);
            x0.z = f2h2(bv[1].x, bv[1].y); x0.w = f2h2(bv[1].z, bv[1].w);
            x1.x = f2h2(bv[2].x, bv[2].y); x1.y = f2h2(bv[2].z, bv[2].w);
            x1.z = f2h2(bv[3].x, bv[3].y); x1.w = f2h2(bv[3].z, bv[3].w);
            *(uint4*)bwd = x0; *(uint4*)(bwd + 4) = x1;
            __syncthreads();
        }
    }

    // epilogue
    #pragma unroll
    for (int mt = 0; mt < 4; mt++) {
        int mr = m0 + wm + (mt<<4) + gid;
        #pragma unroll
        for (int nt = 0; nt < 4; nt++) {
            int nc = n0 + wn + (nt<<3) + (tig<<1);
            float2 bb = make_float2(0.f, 0.f);
            if (HASBIAS) bb = *(const float2*)(bias + nc);
            float2 o0 = make_float2(acc[mt][nt][0] + bb.x, acc[mt][nt][1] + bb.y);
            float2 o1 = make_float2(acc[mt][nt][2] + bb.x, acc[mt][nt][3] + bb.y);
            if (RELU) {
                o0.x = fmaxf(o0.x, 0.f); o0.y = fmaxf(o0.y, 0.f);
                o1.x = fmaxf(o1.x, 0.f); o1.y = fmaxf(o1.y, 0.f);
            }
            if (HASRES) {
                float2 r0 = *(const float2*)(res + (size_t)mr * N + nc);
                float2 r1 = *(const float2*)(res + (size_t)(mr+8) * N + nc);
                o0.x += r0.x; o0.y += r0.y;
                o1.x += r1.x; o1.y += r1.y;
            }
            *(float2*)(Cm + (size_t)mr     * N + nc) = o0;
            *(float2*)(Cm + (size_t)(mr+8) * N + nc) = o1;
        }
    }
}

// ---------------- fp16 tensor-core flash attention (Br=128, Bc=64) ---------
// smem floats: Ss[128][68] | Ps 128x72 half | Ks 64x72 half | Vs 64x72 half |
//              mrow/lrow/arow[128]
#define ATT_SS    0
#define ATT_PS    (128*68)                 // float offset
#define ATT_KS    (ATT_PS + 128*72/2)
#define ATT_VS    (ATT_KS + 64*72/2)
#define ATT_ROWS  (ATT_VS + 64*72/2)
#define ATT_SMEM_FLOATS (ATT_ROWS + 3*128)
#define ATT_SMEM_BYTES  (ATT_SMEM_FLOATS*4)

__global__ __launch_bounds__(256, 2) void attn_kernel(
    const float* __restrict__ qkv, float* __restrict__ out)
{
    extern __shared__ float sm[];
    float*    Ss = sm;
    uint32_t* Pw = (uint32_t*)(sm + ATT_PS);   // halves, row stride 36 words
    __half*   Ph = (__half*)Pw;                // row stride 72 halves
    uint32_t* Kw = (uint32_t*)(sm + ATT_KS);   // [j][d] halves, stride 36 words
    __half*   Kh = (__half*)Kw;
    uint32_t* Vw = (uint32_t*)(sm + ATT_VS);   // [j][d] natural, stride 36 words
    __half*   Vh = (__half*)Vw;
    float* mrow = sm + ATT_ROWS;
    float* lrow = mrow + 128;
    float* arow = lrow + 128;

    int qt = (int)gridDim.x - 1 - (int)blockIdx.x;   // heavy tiles first
    int bh = blockIdx.y;
    int q0 = qt << 7;
    int bb = bh >> 4, hh = bh & 15;
    const float* Qg = qkv + (size_t)(bb * T_) * QKVN + hh * D_;
    const float* Kg = Qg + C_;
    const float* Vg = Qg + 2*C_;
    int tid = threadIdx.x;
    int warp = tid >> 5, lane = tid & 31;
    int l16 = lane & 15, l2 = lane >> 4;
    int gid = lane >> 2, tig = lane & 3;
    int i0 = warp << 4;
    const float scale = 0.03125f;    // C^-0.5

    // Q fragments (fp16, pre-scaled), registers for all KV tiles
    unsigned qa[4][4];
    {
        const float* q0p = Qg + (size_t)(q0 + i0 + gid) * QKVN;
        const float* q1p = q0p + 8 * QKVN;
        #pragma unroll
        for (int ks = 0; ks < 4; ks++) {
            int c = (ks<<4) + (tig<<1);
            qa[ks][0] = f2h2(scale*q0p[c],   scale*q0p[c+1]);
            qa[ks][1] = f2h2(scale*q1p[c],   scale*q1p[c+1]);
            qa[ks][2] = f2h2(scale*q0p[c+8], scale*q0p[c+9]);
            qa[ks][3] = f2h2(scale*q1p[c+8], scale*q1p[c+9]);
        }
    }
    if (tid < 128) { mrow[tid] = -1e30f; lrow[tid] = 0.f; }

    float oacc[8][4] = {};

    int ktmax = 2*qt + 1;
    for (int kt = 0; kt <= ktmax; kt++) {
        int k0 = kt << 6;
        __syncthreads();
        {   // load K + V natural [j][d] (vectorized half2 stores)
            int r = tid >> 2, c0 = (tid & 3) << 4;
            const float* kp = Kg + (size_t)(k0 + r) * QKVN + c0;
            const float* vp = Vg + (size_t)(k0 + r) * QKVN + c0;
            float4 k4[4], v4[4];
            #pragma unroll
            for (int u = 0; u < 4; u++) { k4[u] = *(const float4*)(kp + (u<<2));
                                          v4[u] = *(const float4*)(vp + (u<<2)); }
            uint32_t* kd = Kw + r*36 + (c0>>1);
            uint4 kw0, kw1;
            kw0.x = f2h2(k4[0].x, k4[0].y); kw0.y = f2h2(k4[0].z, k4[0].w);
            kw0.z = f2h2(k4[1].x, k4[1].y); kw0.w = f2h2(k4[1].z, k4[1].w);
            kw1.x = f2h2(k4[2].x, k4[2].y); kw1.y = f2h2(k4[2].z, k4[2].w);
            kw1.z = f2h2(k4[3].x, k4[3].y); kw1.w = f2h2(k4[3].z, k4[3].w);
            *(uint4*)kd = kw0; *(uint4*)(kd + 4) = kw1;
            uint32_t* vd = Vw + r*36 + (c0>>1);
            uint4 vw0, vw1;
            vw0.x = f2h2(v4[0].x, v4[0].y); vw0.y = f2h2(v4[0].z, v4[0].w);
            vw0.z = f2h2(v4[1].x, v4[1].y); vw0.w = f2h2(v4[1].z, v4[1].w);
            vw1.x = f2h2(v4[2].x, v4[2].y); vw1.y = f2h2(v4[2].z, v4[2].w);
            vw1.z = f2h2(v4[3].x, v4[3].y); vw1.w = f2h2(v4[3].z, v4[3].w);
            *(uint4*)vd = vw0; *(uint4*)(vd + 4) = vw1;
        }
        __syncthreads();

        // S = Q K^T  (fp16 mma; K fragments via ldmatrix)
        {
            float sacc[8][4] = {};
            #pragma unroll
            for (int ks = 0; ks < 4; ks++) {
                #pragma unroll
                for (int np = 0; np < 4; np++) {
                    uint32_t kd = su32(Kh + ((np<<4) + l16)*72 + (ks<<4) + (l2<<3));
                    uint32_t r0, r1, r2, r3;
                    LDSM4(r0, r1, r2, r3, kd);
                    unsigned b0[2] = {r0, r2}, b1[2] = {r1, r3};
                    MMA_F16(sacc[2*np],   qa[ks], b0);
                    MMA_F16(sacc[2*np+1], qa[ks], b1);
                }
            }
            float* s0 = &Ss[(i0+gid)*68 + (tig<<1)];
            float* s1 = s0 + 8*68;
            #pragma unroll
            for (int nt = 0; nt < 8; nt++) {
                *(float2*)(s0 + (nt<<3)) = make_float2(sacc[nt][0], sacc[nt][1]);
                *(float2*)(s1 + (nt<<3)) = make_float2(sacc[nt][2], sacc[nt][3]);
            }
        }
        __syncwarp();

        // online softmax on warp's 16 rows; writes P (half)
        {
            int r  = i0 + (lane >> 1);
            int co = (lane & 1) << 5;
            bool diag = (kt >= 2*qt);
            float sv[32];
            float mloc = -1e30f;
            #pragma unroll
            for (int u = 0; u < 8; u++) {
                float4 s4 = *(const float4*)&Ss[r*68 + co + (u<<2)];
                if (diag) {
                    int jb = k0 + co + (u<<2), ii = q0 + r;
                    if (jb+0 > ii) s4.x = -1e30f;
                    if (jb+1 > ii) s4.y = -1e30f;
                    if (jb+2 > ii) s4.z = -1e30f;
                    if (jb+3 > ii) s4.w = -1e30f;
                }
                sv[(u<<2)+0] = s4.x; sv[(u<<2)+1] = s4.y;
                sv[(u<<2)+2] = s4.z; sv[(u<<2)+3] = s4.w;
                mloc = fmaxf(mloc, fmaxf(fmaxf(s4.x, s4.y), fmaxf(s4.z, s4.w)));
            }
            mloc = fmaxf(mloc, __shfl_xor_sync(0xffffffffu, mloc, 1));
            float mold = mrow[r];
            float mnew = fmaxf(mold, mloc);
            float ls = 0.f;
            int wbase = r*36 + (co>>1);
            #pragma unroll
            for (int u = 0; u < 16; u++) {
                float e0 = __expf(sv[(u<<1)]   - mnew);
                float e1 = __expf(sv[(u<<1)+1] - mnew);
                ls += e0 + e1;
                Pw[wbase + u] = f2h2(e0, e1);
            }
            ls += __shfl_xor_sync(0xffffffffu, ls, 1);
            if ((lane & 1) == 0) {
                float al = __expf(mold - mnew);
                arow[r] = al;
                lrow[r] = lrow[r] * al + ls;
                mrow[r] = mnew;
            }
        }
        __syncwarp();

        // rescale O, accumulate P @ V  (fp16 mma; P/V fragments via ldmatrix)
        {
            float al0 = arow[i0 + gid];
            float al1 = arow[i0 + gid + 8];
            #pragma unroll
            for (int nt = 0; nt < 8; nt++) {
                oacc[nt][0] *= al0; oacc[nt][1] *= al0;
                oacc[nt][2] *= al1; oacc[nt][3] *= al1;
            }
            #pragma unroll
            for (int ks = 0; ks < 4; ks++) {
                unsigned a[4];
                uint32_t pd = su32(Ph + (i0 + l16)*72 + (ks<<4) + (l2<<3));
                LDSM4(a[0], a[1], a[2], a[3], pd);
                #pragma unroll
                for (int np = 0; np < 4; np++) {
                    uint32_t vdx = su32(Vh + ((ks<<4) + l16)*72 + (np<<4) + (l2<<3));
                    uint32_t r0, r1, r2, r3;
                    LDSM4T(r0, r1, r2, r3, vdx);
                    unsigned b0[2] = {r0, r1}, b1[2] = {r2, r3};
                    MMA_F16(oacc[2*np],   a, b0);
                    MMA_F16(oacc[2*np+1], a, b1);
                }
            }
        }
    }
    __syncthreads();

    // normalize + write out[b, t, hh*64 + d]
    {
        float inv0 = 1.0f / lrow[i0 + gid];
        float inv1 = 1.0f / lrow[i0 + gid + 8];
        float* o0 = out + ((size_t)(bb * T_ + q0 + i0 + gid)) * C_ + hh * D_ + (tig<<1);
        float* o1 = o0 + 8 * C_;
        #pragma unroll
        for (int nt = 0; nt < 8; nt++) {
            *(float2*)(o0 + (nt<<3)) = make_float2(oacc[nt][0]*inv0, oacc[nt][1]*inv0);
            *(float2*)(o1 + (nt<<3)) = make_float2(oacc[nt][2]*inv1, oacc[nt][3]*inv1);
        }
    }
}

// ---------------- launch ----------------------------------------------------
extern "C" void kernel_launch(void* const* d_in, const int* in_sizes, int n_in,
                              void* d_out, int out_size)
{
    const float* x   = (const float*)d_in[0];
    const float* Wq  = (const float*)d_in[1];
    const float* Wk  = (const float*)d_in[2];
    const float* Wv  = (const float*)d_in[3];
    const float* Wo  = (const float*)d_in[4];
    const float* bo  = (const float*)d_in[5];
    const float* W1  = (const float*)d_in[6];
    const float* b1  = (const float*)d_in[7];
    const float* W2  = (const float*)d_in[8];
    const float* b2  = (const float*)d_in[9];
    const float* g1  = (const float*)d_in[10];
    const float* be1 = (const float*)d_in[11];
    const float* g2  = (const float*)d_in[12];
    const float* be2 = (const float*)d_in[13];
    float* out = (float*)d_out;

    float *h, *wp, *att, *x1, *h2, *ff;
    cudaGetSymbolAddress((void**)&h,   g_h);
    cudaGetSymbolAddress((void**)&wp,  g_wp);
    cudaGetSymbolAddress((void**)&att, g_att);
    cudaGetSymbolAddress((void**)&x1,  g_x1);
    cudaGetSymbolAddress((void**)&h2,  g_h2);
    cudaGetSymbolAddress((void**)&ff,  g_ff);

    cudaFuncSetAttribute(attn_kernel,
        cudaFuncAttributeMaxDynamicSharedMemorySize, ATT_SMEM_BYTES);

    // 1) LN1
    ln_kernel<<<M_, 256>>>(x, g1, be1, h);
    // 2) pack Wq/Wk/Wv -> [C][3C]
    repack_kernel<<<dim3((C_*C_)/256, 3), 256>>>(Wq, Wk, Wv, wp);
    // 3) fused QKV projection: [M,3072] = h @ Wqkv
    tgemm<0,0,0><<<dim3(QKVN/128, M_/128), 256>>>(h, wp, ff, M_, QKVN, C_, nullptr, nullptr);
    // 4) causal flash attention (fp16 mma) on packed qkv
    attn_kernel<<<dim3(T_/128, B_*H_), 256, ATT_SMEM_BYTES>>>(ff, att);
    // 5) Wo projection + bias + residual
    tgemm<0,1,1><<<dim3(C_/128, M_/128), 256>>>(att, Wo, x1, M_, C_, C_, bo, x);
    // 6) LN2
    ln_kernel<<<M_, 256>>>(x1, g2, be2, h2);
    // 7) FFN up + ReLU
    tgemm<1,0,1><<<dim3(F_/128, M_/128), 256>>>(h2, W1, ff, M_, F_, C_, b1, nullptr);
    // 8) FFN down + bias + residual -> final output
    tgemm<0,1,1><<<dim3(C_/128, M_/128), 256>>>(ff, W2, out, M_, C_, F_, b2, x1);
}

// round 7
// speedup vs baseline: 5.3676x; 1.4535x over previous
#include <cuda_runtime.h>
#include <cuda_fp16.h>
#include <cstdint>

#define B_ 2
#define T_ 2048
#define C_ 1024
#define H_ 16
#define D_ 64
#define F_ 4096
#define M_ (B_*T_)   // 4096 rows
#define QKVN 3072

// ---------------- scratch (device globals; no runtime allocation) ----------
__device__ __align__(16) __half hb_h  [M_*C_];    // ln1 out (half)
__device__ __align__(16) __half hb_wp [C_*QKVN];  // packed Wqkv (half)
__device__ __align__(16) __half hb_qkv[M_*QKVN];  // qkv activations (half)
__device__ __align__(16) __half hb_att[M_*C_];    // attn out (half)
__device__ __align__(16) __half hb_h2 [M_*C_];    // ln2 out (half)
__device__ __align__(16) __half hb_ff [M_*F_];    // ffn mid (half)
__device__ __align__(16) __half hb_wo [C_*C_];
__device__ __align__(16) __half hb_w1 [C_*F_];
__device__ __align__(16) __half hb_w2 [F_*C_];
__device__ __align__(16) float  g_x1  [M_*C_];    // attn residual out (fp32)

__device__ __forceinline__ uint32_t f2h2(float x, float y) {
    __half2 h = __floats2half2_rn(x, y);
    return *(uint32_t*)&h;
}
__device__ __forceinline__ uint32_t su32(const void* p) {
    return (uint32_t)__cvta_generic_to_shared(p);
}

#define MMA_F16(acc, a, b) \
    asm volatile( \
        "mma.sync.aligned.m16n8k16.row.col.f32.f16.f16.f32 " \
        "{%0,%1,%2,%3},{%4,%5,%6,%7},{%8,%9},{%0,%1,%2,%3};" \
        : "+f"((acc)[0]), "+f"((acc)[1]), "+f"((acc)[2]), "+f"((acc)[3]) \
        : "r"((a)[0]), "r"((a)[1]), "r"((a)[2]), "r"((a)[3]), \
          "r"((b)[0]), "r"((b)[1]))

#define LDSM4(r0, r1, r2, r3, addr) \
    asm volatile("ldmatrix.sync.aligned.m8n8.x4.shared.b16 {%0,%1,%2,%3}, [%4];" \
        : "=r"(r0), "=r"(r1), "=r"(r2), "=r"(r3) : "r"(addr))
#define LDSM4T(r0, r1, r2, r3, addr) \
    asm volatile("ldmatrix.sync.aligned.m8n8.x4.trans.shared.b16 {%0,%1,%2,%3}, [%4];" \
        : "=r"(r0), "=r"(r1), "=r"(r2), "=r"(r3) : "r"(addr))

#define CPA16(dst, src) \
    asm volatile("cp.async.cg.shared.global [%0], [%1], 16;" :: "r"(dst), "l"(src))
#define CPA_COMMIT() asm volatile("cp.async.commit_group;" ::: "memory")
#define CPA_WAIT(n)  asm volatile("cp.async.wait_group %0;" :: "n"(n) : "memory")

// ---------------- LayerNorm: fp32 in, half out ------------------------------
__global__ __launch_bounds__(256) void ln_kernel(
    const float* __restrict__ x, const float* __restrict__ g,
    const float* __restrict__ b, __half* __restrict__ out)
{
    int row = blockIdx.x;
    int tid = threadIdx.x;
    const float4 xv = ((const float4*)(x + (size_t)row*C_))[tid];
    float s  = xv.x + xv.y + xv.z + xv.w;
    float s2 = xv.x*xv.x + xv.y*xv.y + xv.z*xv.z + xv.w*xv.w;
    __shared__ float rs[8], rs2[8];
    #pragma unroll
    for (int o = 16; o; o >>= 1) {
        s  += __shfl_down_sync(0xffffffffu, s,  o);
        s2 += __shfl_down_sync(0xffffffffu, s2, o);
    }
    if ((tid & 31) == 0) { rs[tid>>5] = s; rs2[tid>>5] = s2; }
    __syncthreads();
    if (tid == 0) {
        float a = 0.f, c = 0.f;
        #pragma unroll
        for (int i = 0; i < 8; i++) { a += rs[i]; c += rs2[i]; }
        rs[0] = a; rs2[0] = c;
    }
    __syncthreads();
    float mean = rs[0] * (1.0f/C_);
    float var  = rs2[0] * (1.0f/C_) - mean*mean;
    float rstd = rsqrtf(var + 1e-5f);
    const float4 gv = ((const float4*)g)[tid];
    const float4 bv = ((const float4*)b)[tid];
    uint2 w;
    w.x = f2h2((xv.x-mean)*rstd*gv.x + bv.x, (xv.y-mean)*rstd*gv.y + bv.y);
    w.y = f2h2((xv.z-mean)*rstd*gv.z + bv.z, (xv.w-mean)*rstd*gv.w + bv.w);
    *(uint2*)(out + (size_t)row*C_ + (tid<<2)) = w;
}

// ---------------- fp32 -> fp16 copy ----------------------------------------
__global__ __launch_bounds__(256) void f2h_kernel(
    const float* __restrict__ src, __half* __restrict__ dst)
{
    int i = (blockIdx.x*256 + threadIdx.x) << 2;
    float4 v = *(const float4*)(src + i);
    uint2 w;
    w.x = f2h2(v.x, v.y); w.y = f2h2(v.z, v.w);
    *(uint2*)(dst + i) = w;
}

// ---------------- repack Wq/Wk/Wv [H][C][D] -> half [C][3*C] ----------------
__global__ __launch_bounds__(256) void repack_kernel(
    const float* __restrict__ Wq, const float* __restrict__ Wk,
    const float* __restrict__ Wv, __half* __restrict__ Wp)
{
    int idx = blockIdx.x*256 + threadIdx.x;        // over C*C
    int which = blockIdx.y;
    const float* W = (which==0) ? Wq : (which==1) ? Wk : Wv;
    int c = idx >> 10, n = idx & 1023;
    int h = n >> 6, d = n & 63;
    Wp[(size_t)c*QKVN + which*C_ + n] = __float2half_rn(W[((size_t)h*C_ + c)*D_ + d]);
}

// ---------------- fp16 tensor-core GEMM, 128x128, cp.async double buffer ---
// As[buf][m][40 halves], Bs[buf][k][136 halves]
template<int RELU, int HASRES, int HASBIAS, int OUTHALF>
__global__ __launch_bounds__(256, 2) void tgemm(
    const __half* __restrict__ A, const __half* __restrict__ Bm,
    void* __restrict__ Cm, int M, int N, int K,
    const float* __restrict__ bias, const float* __restrict__ res)
{
    __shared__ __half As[2][128][40];
    __shared__ __half Bs[2][32][136];
    int tid = threadIdx.x;
    int m0 = blockIdx.y << 7, n0 = blockIdx.x << 7;
    int warp = tid >> 5, lane = tid & 31;
    int l16 = lane & 15, l2 = lane >> 4;
    int gid = lane >> 2, tig = lane & 3;
    int wm = (warp & 1) << 6;
    int wn = (warp >> 1) << 5;

    float acc[4][4][4] = {};

    int ra = tid >> 1, ca = (tid & 1) << 4;   // A: row, 16-half col base (2x16B)
    int rb = tid >> 3, cb = (tid & 7) << 4;   // B: k-row, 16-half n base
    const __half* Ap = A  + (size_t)(m0 + ra) * K + ca;
    const __half* Bp = Bm + (size_t)rb * N + n0 + cb;
    uint32_t adst[2], bdst[2];
    #pragma unroll
    for (int b = 0; b < 2; b++) {
        adst[b] = su32(&As[b][ra][ca]);
        bdst[b] = su32(&Bs[b][rb][cb]);
    }

    int KT = K >> 5;
    // preload tile 0
    CPA16(adst[0],      Ap);
    CPA16(adst[0] + 16, Ap + 8);
    CPA16(bdst[0],      Bp);
    CPA16(bdst[0] + 16, Bp + 8);
    CPA_COMMIT();

    for (int kt = 0; kt < KT; kt++) {
        int buf = kt & 1;
        if (kt + 1 < KT) {
            int k0 = (kt + 1) << 5;
            const __half* ap = Ap + k0;
            const __half* bp = Bp + (size_t)k0 * N;
            CPA16(adst[buf^1],      ap);
            CPA16(adst[buf^1] + 16, ap + 8);
            CPA16(bdst[buf^1],      bp);
            CPA16(bdst[buf^1] + 16, bp + 8);
            CPA_COMMIT();
            CPA_WAIT(1);
        } else {
            CPA_WAIT(0);
        }
        __syncthreads();
        // compute on buf (ldmatrix fragments)
        #pragma unroll
        for (int ks = 0; ks < 2; ks++) {
            unsigned a[4][4], b[4][2];
            #pragma unroll
            for (int mt = 0; mt < 4; mt++) {
                uint32_t ad = su32(&As[buf][wm + (mt<<4) + l16][(ks<<4) + (l2<<3)]);
                LDSM4(a[mt][0], a[mt][1], a[mt][2], a[mt][3], ad);
            }
            #pragma unroll
            for (int np = 0; np < 2; np++) {
                uint32_t bd = su32(&Bs[buf][(ks<<4) + l16][wn + (np<<4) + (l2<<3)]);
                uint32_t r0, r1, r2, r3;
                LDSM4T(r0, r1, r2, r3, bd);
                b[2*np][0] = r0; b[2*np][1] = r1;
                b[2*np+1][0] = r2; b[2*np+1][1] = r3;
            }
            #pragma unroll
            for (int mt = 0; mt < 4; mt++)
                #pragma unroll
                for (int nt = 0; nt < 4; nt++)
                    MMA_F16(acc[mt][nt], a[mt], b[nt]);
        }
        __syncthreads();   // all reads of buf done before next cp.async overwrites
    }

    // epilogue
    #pragma unroll
    for (int mt = 0; mt < 4; mt++) {
        int mr = m0 + wm + (mt<<4) + gid;
        #pragma unroll
        for (int nt = 0; nt < 4; nt++) {
            int nc = n0 + wn + (nt<<3) + (tig<<1);
            float2 bb = make_float2(0.f, 0.f);
            if (HASBIAS) bb = *(const float2*)(bias + nc);
            float2 o0 = make_float2(acc[mt][nt][0] + bb.x, acc[mt][nt][1] + bb.y);
            float2 o1 = make_float2(acc[mt][nt][2] + bb.x, acc[mt][nt][3] + bb.y);
            if (RELU) {
                o0.x = fmaxf(o0.x, 0.f); o0.y = fmaxf(o0.y, 0.f);
                o1.x = fmaxf(o1.x, 0.f); o1.y = fmaxf(o1.y, 0.f);
            }
            if (HASRES) {
                float2 r0 = *(const float2*)(res + (size_t)mr * N + nc);
                float2 r1 = *(const float2*)(res + (size_t)(mr+8) * N + nc);
                o0.x += r0.x; o0.y += r0.y;
                o1.x += r1.x; o1.y += r1.y;
            }
            if (OUTHALF) {
                __half* Ch = (__half*)Cm;
                *(uint32_t*)(Ch + (size_t)mr     * N + nc) = f2h2(o0.x, o0.y);
                *(uint32_t*)(Ch + (size_t)(mr+8) * N + nc) = f2h2(o1.x, o1.y);
            } else {
                float* Cf = (float*)Cm;
                *(float2*)(Cf + (size_t)mr     * N + nc) = o0;
                *(float2*)(Cf + (size_t)(mr+8) * N + nc) = o1;
            }
        }
    }
}

// ---------------- fp16 tensor-core flash attention (Br=128, Bc=64) ---------
// smem floats: Ss[128][68] | Ps 128x72h | Ks 64x72h | Vs 64x72h | rows[384]
#define ATT_PS    (128*68)                 // float offset
#define ATT_KS    (ATT_PS + 128*72/2)
#define ATT_VS    (ATT_KS + 64*72/2)
#define ATT_ROWS  (ATT_VS + 64*72/2)
#define ATT_SMEM_FLOATS (ATT_ROWS + 3*128)
#define ATT_SMEM_BYTES  (ATT_SMEM_FLOATS*4)

__global__ __launch_bounds__(256, 2) void attn_kernel(
    const __half* __restrict__ qkv, __half* __restrict__ out)
{
    extern __shared__ float sm[];
    float*    Ss = sm;
    uint32_t* Pw = (uint32_t*)(sm + ATT_PS);   // halves, row stride 36 words
    __half*   Ph = (__half*)Pw;                // row stride 72 halves
    uint32_t* Kw = (uint32_t*)(sm + ATT_KS);   // [j][d], stride 36 words
    __half*   Kh = (__half*)Kw;
    uint32_t* Vw = (uint32_t*)(sm + ATT_VS);   // [j][d], stride 36 words
    __half*   Vh = (__half*)Vw;
    float* mrow = sm + ATT_ROWS;
    float* lrow = mrow + 128;
    float* arow = lrow + 128;

    int qt = (int)gridDim.x - 1 - (int)blockIdx.x;   // heavy tiles first
    int bh = blockIdx.y;
    int q0 = qt << 7;
    int bb = bh >> 4, hh = bh & 15;
    const __half* Qg = qkv + (size_t)(bb * T_) * QKVN + hh * D_;
    const __half* Kg = Qg + C_;
    const __half* Vg = Qg + 2*C_;
    int tid = threadIdx.x;
    int warp = tid >> 5, lane = tid & 31;
    int l16 = lane & 15, l2 = lane >> 4;
    int gid = lane >> 2, tig = lane & 3;
    int i0 = warp << 4;
    const float scale = 0.03125f;    // C^-0.5, applied to fp32 S in softmax

    // Q fragments (packed half2 words straight from gmem)
    unsigned qa[4][4];
    {
        const __half* q0p = Qg + (size_t)(q0 + i0 + gid) * QKVN;
        const __half* q1p = q0p + 8 * QKVN;
        #pragma unroll
        for (int ks = 0; ks < 4; ks++) {
            int c = (ks<<4) + (tig<<1);
            qa[ks][0] = *(const uint32_t*)(q0p + c);
            qa[ks][1] = *(const uint32_t*)(q1p + c);
            qa[ks][2] = *(const uint32_t*)(q0p + c + 8);
            qa[ks][3] = *(const uint32_t*)(q1p + c + 8);
        }
    }
    if (tid < 128) { mrow[tid] = -1e30f; lrow[tid] = 0.f; }

    float oacc[8][4] = {};

    int ktmax = 2*qt + 1;
    for (int kt = 0; kt <= ktmax; kt++) {
        int k0 = kt << 6;
        __syncthreads();
        {   // copy K + V tiles (raw half, no conversion)
            int r = tid >> 2, c0 = (tid & 3) << 4;       // 16 halves per thread
            const __half* kp = Kg + (size_t)(k0 + r) * QKVN + c0;
            const __half* vp = Vg + (size_t)(k0 + r) * QKVN + c0;
            uint4 ka = *(const uint4*)kp;
            uint4 kb2 = *(const uint4*)(kp + 8);
            uint4 va = *(const uint4*)vp;
            uint4 vb = *(const uint4*)(vp + 8);
            uint32_t* kd = Kw + r*36 + (c0>>1);
            *(uint4*)kd = ka; *(uint4*)(kd + 4) = kb2;
            uint32_t* vd = Vw + r*36 + (c0>>1);
            *(uint4*)vd = va; *(uint4*)(vd + 4) = vb;
        }
        __syncthreads();

        // S = Q K^T  (fp16 mma; K fragments via ldmatrix)
        {
            float sacc[8][4] = {};
            #pragma unroll
            for (int ks = 0; ks < 4; ks++) {
                #pragma unroll
                for (int np = 0; np < 4; np++) {
                    uint32_t kd = su32(Kh + ((np<<4) + l16)*72 + (ks<<4) + (l2<<3));
                    uint32_t r0, r1, r2, r3;
                    LDSM4(r0, r1, r2, r3, kd);
                    unsigned b0[2] = {r0, r2}, b1[2] = {r1, r3};
                    MMA_F16(sacc[2*np],   qa[ks], b0);
                    MMA_F16(sacc[2*np+1], qa[ks], b1);
                }
            }
            float* s0 = &Ss[(i0+gid)*68 + (tig<<1)];
            float* s1 = s0 + 8*68;
            #pragma unroll
            for (int nt = 0; nt < 8; nt++) {
                *(float2*)(s0 + (nt<<3)) = make_float2(sacc[nt][0], sacc[nt][1]);
                *(float2*)(s1 + (nt<<3)) = make_float2(sacc[nt][2], sacc[nt][3]);
            }
        }
        __syncwarp();

        // online softmax on warp's 16 rows (scale applied here, fp32)
        {
            int r  = i0 + (lane >> 1);
            int co = (lane & 1) << 5;
            bool diag = (kt >= 2*qt);
            float sv[32];
            float mloc = -1e30f;
            #pragma unroll
            for (int u = 0; u < 8; u++) {
                float4 s4 = *(const float4*)&Ss[r*68 + co + (u<<2)];
                s4.x *= scale; s4.y *= scale; s4.z *= scale; s4.w *= scale;
                if (diag) {
                    int jb = k0 + co + (u<<2), ii = q0 + r;
                    if (jb+0 > ii) s4.x = -1e30f;
                    if (jb+1 > ii) s4.y = -1e30f;
                    if (jb+2 > ii) s4.z = -1e30f;
                    if (jb+3 > ii) s4.w = -1e30f;
                }
                sv[(u<<2)+0] = s4.x; sv[(u<<2)+1] = s4.y;
                sv[(u<<2)+2] = s4.z; sv[(u<<2)+3] = s4.w;
                mloc = fmaxf(mloc, fmaxf(fmaxf(s4.x, s4.y), fmaxf(s4.z, s4.w)));
            }
            mloc = fmaxf(mloc, __shfl_xor_sync(0xffffffffu, mloc, 1));
            float mold = mrow[r];
            float mnew = fmaxf(mold, mloc);
            float ls = 0.f;
            int wbase = r*36 + (co>>1);
            #pragma unroll
            for (int u = 0; u < 16; u++) {
                float e0 = __expf(sv[(u<<1)]   - mnew);
                float e1 = __expf(sv[(u<<1)+1] - mnew);
                ls += e0 + e1;
                Pw[wbase + u] = f2h2(e0, e1);
            }
            ls += __shfl_xor_sync(0xffffffffu, ls, 1);
            if ((lane & 1) == 0) {
                float al = __expf(mold - mnew);
                arow[r] = al;
                lrow[r] = lrow[r] * al + ls;
                mrow[r] = mnew;
            }
        }
        __syncwarp();

        // rescale O, accumulate P @ V  (fp16 mma; P/V via ldmatrix)
        {
            float al0 = arow[i0 + gid];
            float al1 = arow[i0 + gid + 8];
            #pragma unroll
            for (int nt = 0; nt < 8; nt++) {
                oacc[nt][0] *= al0; oacc[nt][1] *= al0;
                oacc[nt][2] *= al1; oacc[nt][3] *= al1;
            }
            #pragma unroll
            for (int ks = 0; ks < 4; ks++) {
                unsigned a[4];
                uint32_t pd = su32(Ph + (i0 + l16)*72 + (ks<<4) + (l2<<3));
                LDSM4(a[0], a[1], a[2], a[3], pd);
                #pragma unroll
                for (int np = 0; np < 4; np++) {
                    uint32_t vdx = su32(Vh + ((ks<<4) + l16)*72 + (np<<4) + (l2<<3));
                    uint32_t r0, r1, r2, r3;
                    LDSM4T(r0, r1, r2, r3, vdx);
                    unsigned b0[2] = {r0, r1}, b1[2] = {r2, r3};
                    MMA_F16(oacc[2*np],   a, b0);
                    MMA_F16(oacc[2*np+1], a, b1);
                }
            }
        }
    }
    __syncthreads();

    // normalize + write half out[b, t, hh*64 + d]
    {
        float inv0 = 1.0f / lrow[i0 + gid];
        float inv1 = 1.0f / lrow[i0 + gid + 8];
        __half* o0 = out + ((size_t)(bb * T_ + q0 + i0 + gid)) * C_ + hh * D_ + (tig<<1);
        __half* o1 = o0 + 8 * C_;
        #pragma unroll
        for (int nt = 0; nt < 8; nt++) {
            *(uint32_t*)(o0 + (nt<<3)) = f2h2(oacc[nt][0]*inv0, oacc[nt][1]*inv0);
            *(uint32_t*)(o1 + (nt<<3)) = f2h2(oacc[nt][2]*inv1, oacc[nt][3]*inv1);
        }
    }
}

// ---------------- launch ----------------------------------------------------
extern "C" void kernel_launch(void* const* d_in, const int* in_sizes, int n_in,
                              void* d_out, int out_size)
{
    const float* x   = (const float*)d_in[0];
    const float* Wq  = (const float*)d_in[1];
    const float* Wk  = (const float*)d_in[2];
    const float* Wv  = (const float*)d_in[3];
    const float* Wo  = (const float*)d_in[4];
    const float* bo  = (const float*)d_in[5];
    const float* W1  = (const float*)d_in[6];
    const float* b1  = (const float*)d_in[7];
    const float* W2  = (const float*)d_in[8];
    const float* b2  = (const float*)d_in[9];
    const float* g1  = (const float*)d_in[10];
    const float* be1 = (const float*)d_in[11];
    const float* g2  = (const float*)d_in[12];
    const float* be2 = (const float*)d_in[13];
    float* out = (float*)d_out;

    __half *h, *wp, *qkv, *att, *h2, *ff, *woh, *w1h, *w2h;
    float *x1;
    cudaGetSymbolAddress((void**)&h,   hb_h);
    cudaGetSymbolAddress((void**)&wp,  hb_wp);
    cudaGetSymbolAddress((void**)&qkv, hb_qkv);
    cudaGetSymbolAddress((void**)&att, hb_att);
    cudaGetSymbolAddress((void**)&h2,  hb_h2);
    cudaGetSymbolAddress((void**)&ff,  hb_ff);
    cudaGetSymbolAddress((void**)&woh, hb_wo);
    cudaGetSymbolAddress((void**)&w1h, hb_w1);
    cudaGetSymbolAddress((void**)&w2h, hb_w2);
    cudaGetSymbolAddress((void**)&x1,  g_x1);

    cudaFuncSetAttribute(attn_kernel,
        cudaFuncAttributeMaxDynamicSharedMemorySize, ATT_SMEM_BYTES);

    // 1) LN1 (half out)
    ln_kernel<<<M_, 256>>>(x, g1, be1, h);
    // 2) weight conversions (once per launch; tiny)
    repack_kernel<<<dim3((C_*C_)/256, 3), 256>>>(Wq, Wk, Wv, wp);
    f2h_kernel<<<(C_*C_)/1024, 256>>>(Wo, woh);
    f2h_kernel<<<(C_*F_)/1024, 256>>>(W1, w1h);
    f2h_kernel<<<(F_*C_)/1024, 256>>>(W2, w2h);
    // 3) fused QKV projection (half in/out)
    tgemm<0,0,0,1><<<dim3(QKVN/128, M_/128), 256>>>(h, wp, qkv, M_, QKVN, C_, nullptr, nullptr);
    // 4) causal flash attention (half in/out)
    attn_kernel<<<dim3(T_/128, B_*H_), 256, ATT_SMEM_BYTES>>>(qkv, att);
    // 5) Wo projection + bias + residual (fp32 out)
    tgemm<0,1,1,0><<<dim3(C_/128, M_/128), 256>>>(att, woh, x1, M_, C_, C_, bo, x);
    // 6) LN2 (half out)
    ln_kernel<<<M_, 256>>>(x1, g2, be2, h2);
    // 7) FFN up + ReLU (half out)
    tgemm<1,0,1,1><<<dim3(F_/128, M_/128), 256>>>(h2, w1h, ff, M_, F_, C_, b1, nullptr);
    // 8) FFN down + bias + residual -> final fp32 output
    tgemm<0,1,1,0><<<dim3(C_/128, M_/128), 256>>>(ff, w2h, out, M_, C_, F_, b2, x1);
}

// round 8
// speedup vs baseline: 5.9781x; 1.1137x over previous
#include <cuda_runtime.h>
#include <cuda_fp16.h>
#include <cstdint>

#define B_ 2
#define T_ 2048
#define C_ 1024
#define H_ 16
#define D_ 64
#define F_ 4096
#define M_ (B_*T_)   // 4096 rows
#define QKVN 3072

// ---------------- scratch (device globals; no runtime allocation) ----------
__device__ __align__(16) __half hb_h  [M_*C_];    // ln1 out (half)
__device__ __align__(16) __half hb_wp [C_*QKVN];  // packed Wqkv (half)
__device__ __align__(16) __half hb_qkv[M_*QKVN];  // qkv activations (half)
__device__ __align__(16) __half hb_att[M_*C_];    // attn out (half)
__device__ __align__(16) __half hb_h2 [M_*C_];    // ln2 out (half)
__device__ __align__(16) __half hb_ff [M_*F_];    // ffn mid (half)
__device__ __align__(16) __half hb_wo [C_*C_];
__device__ __align__(16) __half hb_w1 [C_*F_];
__device__ __align__(16) __half hb_w2 [F_*C_];
__device__ __align__(16) float  g_x1  [M_*C_];    // attn residual out (fp32)

__device__ __forceinline__ uint32_t f2h2(float x, float y) {
    __half2 h = __floats2half2_rn(x, y);
    return *(uint32_t*)&h;
}
__device__ __forceinline__ uint32_t su32(const void* p) {
    return (uint32_t)__cvta_generic_to_shared(p);
}

#define MMA_F16(acc, a, b) \
    asm volatile( \
        "mma.sync.aligned.m16n8k16.row.col.f32.f16.f16.f32 " \
        "{%0,%1,%2,%3},{%4,%5,%6,%7},{%8,%9},{%0,%1,%2,%3};" \
        : "+f"((acc)[0]), "+f"((acc)[1]), "+f"((acc)[2]), "+f"((acc)[3]) \
        : "r"((a)[0]), "r"((a)[1]), "r"((a)[2]), "r"((a)[3]), \
          "r"((b)[0]), "r"((b)[1]))

#define LDSM4(r0, r1, r2, r3, addr) \
    asm volatile("ldmatrix.sync.aligned.m8n8.x4.shared.b16 {%0,%1,%2,%3}, [%4];" \
        : "=r"(r0), "=r"(r1), "=r"(r2), "=r"(r3) : "r"(addr))
#define LDSM4T(r0, r1, r2, r3, addr) \
    asm volatile("ldmatrix.sync.aligned.m8n8.x4.trans.shared.b16 {%0,%1,%2,%3}, [%4];" \
        : "=r"(r0), "=r"(r1), "=r"(r2), "=r"(r3) : "r"(addr))

#define CPA16(dst, src) \
    asm volatile("cp.async.cg.shared.global [%0], [%1], 16;" :: "r"(dst), "l"(src))
#define CPA_COMMIT() asm volatile("cp.async.commit_group;" ::: "memory")
#define CPA_WAIT(n)  asm volatile("cp.async.wait_group %0;" :: "n"(n) : "memory")

// ---------------- LayerNorm: fp32 in, half out ------------------------------
__global__ __launch_bounds__(256) void ln_kernel(
    const float* __restrict__ x, const float* __restrict__ g,
    const float* __restrict__ b, __half* __restrict__ out)
{
    int row = blockIdx.x;
    int tid = threadIdx.x;
    const float4 xv = ((const float4*)(x + (size_t)row*C_))[tid];
    float s  = xv.x + xv.y + xv.z + xv.w;
    float s2 = xv.x*xv.x + xv.y*xv.y + xv.z*xv.z + xv.w*xv.w;
    __shared__ float rs[8], rs2[8];
    #pragma unroll
    for (int o = 16; o; o >>= 1) {
        s  += __shfl_down_sync(0xffffffffu, s,  o);
        s2 += __shfl_down_sync(0xffffffffu, s2, o);
    }
    if ((tid & 31) == 0) { rs[tid>>5] = s; rs2[tid>>5] = s2; }
    __syncthreads();
    if (tid == 0) {
        float a = 0.f, c = 0.f;
        #pragma unroll
        for (int i = 0; i < 8; i++) { a += rs[i]; c += rs2[i]; }
        rs[0] = a; rs2[0] = c;
    }
    __syncthreads();
    float mean = rs[0] * (1.0f/C_);
    float var  = rs2[0] * (1.0f/C_) - mean*mean;
    float rstd = rsqrtf(var + 1e-5f);
    const float4 gv = ((const float4*)g)[tid];
    const float4 bv = ((const float4*)b)[tid];
    uint2 w;
    w.x = f2h2((xv.x-mean)*rstd*gv.x + bv.x, (xv.y-mean)*rstd*gv.y + bv.y);
    w.y = f2h2((xv.z-mean)*rstd*gv.z + bv.z, (xv.w-mean)*rstd*gv.w + bv.w);
    *(uint2*)(out + (size_t)row*C_ + (tid<<2)) = w;
}

// ---------------- fp32 -> fp16 copy ----------------------------------------
__global__ __launch_bounds__(256) void f2h_kernel(
    const float* __restrict__ src, __half* __restrict__ dst)
{
    int i = (blockIdx.x*256 + threadIdx.x) << 2;
    float4 v = *(const float4*)(src + i);
    uint2 w;
    w.x = f2h2(v.x, v.y); w.y = f2h2(v.z, v.w);
    *(uint2*)(dst + i) = w;
}

// ---------------- repack Wq/Wk/Wv [H][C][D] -> half [C][3*C] ----------------
__global__ __launch_bounds__(256) void repack_kernel(
    const float* __restrict__ Wq, const float* __restrict__ Wk,
    const float* __restrict__ Wv, __half* __restrict__ Wp)
{
    int idx = blockIdx.x*256 + threadIdx.x;        // over C*C
    int which = blockIdx.y;
    const float* W = (which==0) ? Wq : (which==1) ? Wk : Wv;
    int c = idx >> 10, n = idx & 1023;
    int h = n >> 6, d = n & 63;
    Wp[(size_t)c*QKVN + which*C_ + n] = __float2half_rn(W[((size_t)h*C_ + c)*D_ + d]);
}

// ---------------- fp16 GEMM: 128x256 tile, 64x64 warp tile, 4-stage async --
// stage: A 128x40h (10240B) | B 32x264h (16896B)  -> 27136B; 4 stages
#define GSTAGE 27136
#define GBOF   10240
#define GT_SMEM (4*GSTAGE)

template<int RELU, int HASRES, int HASBIAS, int OUTHALF>
__global__ __launch_bounds__(256, 1) void tgemm(
    const __half* __restrict__ A, const __half* __restrict__ Bm,
    void* __restrict__ Cm, int M, int N, int K,
    const float* __restrict__ bias, const float* __restrict__ res)
{
    extern __shared__ char dsm[];
    int tid = threadIdx.x;
    int m0 = blockIdx.y << 7, n0 = blockIdx.x << 8;
    int warp = tid >> 5, lane = tid & 31;
    int l16 = lane & 15, l2 = lane >> 4;
    int gid = lane >> 2, tig = lane & 3;
    int wm = (warp & 1) << 6;
    int wn = (warp >> 1) << 6;

    float acc[4][8][4] = {};

    int ra = tid >> 1, ca = (tid & 1) << 4;   // A: row 0..127, col 0/16 halves
    int rb = tid >> 3, tb = (tid & 7) << 3;   // B: k-row 0..31, col base halves
    const __half* Ap = A  + (size_t)(m0 + ra) * K + ca;
    const __half* Bp = Bm + (size_t)rb * N + n0 + tb;
    uint32_t abase[4], bbase[4];
    #pragma unroll
    for (int s = 0; s < 4; s++) {
        abase[s] = su32(dsm + s*GSTAGE + (ra*40 + ca)*2);
        bbase[s] = su32(dsm + s*GSTAGE + GBOF + (rb*264 + tb)*2);
    }

    int KT = K >> 5;
    // prologue: stages 0,1
    #pragma unroll
    for (int p = 0; p < 2; p++) {
        const __half* ap = Ap + (p<<5);
        const __half* bp = Bp + (size_t)(p<<5) * N;
        CPA16(abase[p],      ap);
        CPA16(abase[p] + 16, ap + 8);
        #pragma unroll
        for (int u = 0; u < 4; u++)
            CPA16(bbase[p] + (u<<7), bp + (u<<6));
        CPA_COMMIT();
    }

    for (int kt = 0; kt < KT; kt++) {
        if (kt + 2 < KT) {
            int s = (kt + 2) & 3;
            const __half* ap = Ap + ((kt+2)<<5);
            const __half* bp = Bp + (size_t)((kt+2)<<5) * N;
            CPA16(abase[s],      ap);
            CPA16(abase[s] + 16, ap + 8);
            #pragma unroll
            for (int u = 0; u < 4; u++)
                CPA16(bbase[s] + (u<<7), bp + (u<<6));
            CPA_COMMIT();
            CPA_WAIT(2);
        } else if (kt + 1 < KT) {
            CPA_WAIT(1);
        } else {
            CPA_WAIT(0);
        }
        __syncthreads();

        const __half* Ah = (const __half*)(dsm + (kt&3)*GSTAGE);
        const __half* Bh = (const __half*)(dsm + (kt&3)*GSTAGE + GBOF);
        #pragma unroll
        for (int ks = 0; ks < 2; ks++) {
            unsigned a[4][4], b[8][2];
            #pragma unroll
            for (int mt = 0; mt < 4; mt++) {
                uint32_t ad = su32(Ah + (wm + (mt<<4) + l16)*40 + (ks<<4) + (l2<<3));
                LDSM4(a[mt][0], a[mt][1], a[mt][2], a[mt][3], ad);
            }
            #pragma unroll
            for (int np = 0; np < 4; np++) {
                uint32_t bd = su32(Bh + ((ks<<4) + l16)*264 + wn + (np<<4) + (l2<<3));
                uint32_t r0, r1, r2, r3;
                LDSM4T(r0, r1, r2, r3, bd);
                b[2*np][0] = r0; b[2*np][1] = r1;
                b[2*np+1][0] = r2; b[2*np+1][1] = r3;
            }
            #pragma unroll
            for (int mt = 0; mt < 4; mt++)
                #pragma unroll
                for (int nt = 0; nt < 8; nt++)
                    MMA_F16(acc[mt][nt], a[mt], b[nt]);
        }
    }

    // epilogue
    #pragma unroll
    for (int mt = 0; mt < 4; mt++) {
        int mr = m0 + wm + (mt<<4) + gid;
        #pragma unroll
        for (int nt = 0; nt < 8; nt++) {
            int nc = n0 + wn + (nt<<3) + (tig<<1);
            float2 bb = make_float2(0.f, 0.f);
            if (HASBIAS) bb = *(const float2*)(bias + nc);
            float2 o0 = make_float2(acc[mt][nt][0] + bb.x, acc[mt][nt][1] + bb.y);
            float2 o1 = make_float2(acc[mt][nt][2] + bb.x, acc[mt][nt][3] + bb.y);
            if (RELU) {
                o0.x = fmaxf(o0.x, 0.f); o0.y = fmaxf(o0.y, 0.f);
                o1.x = fmaxf(o1.x, 0.f); o1.y = fmaxf(o1.y, 0.f);
            }
            if (HASRES) {
                float2 r0 = *(const float2*)(res + (size_t)mr * N + nc);
                float2 r1 = *(const float2*)(res + (size_t)(mr+8) * N + nc);
                o0.x += r0.x; o0.y += r0.y;
                o1.x += r1.x; o1.y += r1.y;
            }
            if (OUTHALF) {
                __half* Ch = (__half*)Cm;
                *(uint32_t*)(Ch + (size_t)mr     * N + nc) = f2h2(o0.x, o0.y);
                *(uint32_t*)(Ch + (size_t)(mr+8) * N + nc) = f2h2(o1.x, o1.y);
            } else {
                float* Cf = (float*)Cm;
                *(float2*)(Cf + (size_t)mr     * N + nc) = o0;
                *(float2*)(Cf + (size_t)(mr+8) * N + nc) = o1;
            }
        }
    }
}

// ---------------- fp16 tensor-core flash attention (Br=128, Bc=64) ---------
// smem floats: Ss[128][68] | Ps 128x72h | Ks 64x72h | Vs 64x72h | rows[384]
#define ATT_PS    (128*68)                 // float offset
#define ATT_KS    (ATT_PS + 128*72/2)
#define ATT_VS    (ATT_KS + 64*72/2)
#define ATT_ROWS  (ATT_VS + 64*72/2)
#define ATT_SMEM_FLOATS (ATT_ROWS + 3*128)
#define ATT_SMEM_BYTES  (ATT_SMEM_FLOATS*4)

__global__ __launch_bounds__(256, 2) void attn_kernel(
    const __half* __restrict__ qkv, __half* __restrict__ out)
{
    extern __shared__ float sm[];
    float*    Ss = sm;
    uint32_t* Pw = (uint32_t*)(sm + ATT_PS);   // halves, row stride 36 words
    __half*   Ph = (__half*)Pw;                // row stride 72 halves
    uint32_t* Kw = (uint32_t*)(sm + ATT_KS);   // [j][d], stride 36 words
    __half*   Kh = (__half*)Kw;
    uint32_t* Vw = (uint32_t*)(sm + ATT_VS);   // [j][d], stride 36 words
    __half*   Vh = (__half*)Vw;
    float* mrow = sm + ATT_ROWS;
    float* lrow = mrow + 128;
    float* arow = lrow + 128;

    int qt = (int)gridDim.x - 1 - (int)blockIdx.x;   // heavy tiles first
    int bh = blockIdx.y;
    int q0 = qt << 7;
    int bb = bh >> 4, hh = bh & 15;
    const __half* Qg = qkv + (size_t)(bb * T_) * QKVN + hh * D_;
    const __half* Kg = Qg + C_;
    const __half* Vg = Qg + 2*C_;
    int tid = threadIdx.x;
    int warp = tid >> 5, lane = tid & 31;
    int l16 = lane & 15, l2 = lane >> 4;
    int gid = lane >> 2, tig = lane & 3;
    int i0 = warp << 4;
    const float scale = 0.03125f;    // C^-0.5, applied to fp32 S in softmax

    // Q fragments (packed half2 words straight from gmem)
    unsigned qa[4][4];
    {
        const __half* q0p = Qg + (size_t)(q0 + i0 + gid) * QKVN;
        const __half* q1p = q0p + 8 * QKVN;
        #pragma unroll
        for (int ks = 0; ks < 4; ks++) {
            int c = (ks<<4) + (tig<<1);
            qa[ks][0] = *(const uint32_t*)(q0p + c);
            qa[ks][1] = *(const uint32_t*)(q1p + c);
            qa[ks][2] = *(const uint32_t*)(q0p + c + 8);
            qa[ks][3] = *(const uint32_t*)(q1p + c + 8);
        }
    }
    if (tid < 128) { mrow[tid] = -1e30f; lrow[tid] = 0.f; }

    float oacc[8][4] = {};

    int ktmax = 2*qt + 1;
    for (int kt = 0; kt <= ktmax; kt++) {
        int k0 = kt << 6;
        __syncthreads();
        {   // copy K + V tiles (raw half)
            int r = tid >> 2, c0 = (tid & 3) << 4;
            const __half* kp = Kg + (size_t)(k0 + r) * QKVN + c0;
            const __half* vp = Vg + (size_t)(k0 + r) * QKVN + c0;
            uint4 ka = *(const uint4*)kp;
            uint4 kb2 = *(const uint4*)(kp + 8);
            uint4 va = *(const uint4*)vp;
            uint4 vb = *(const uint4*)(vp + 8);
            uint32_t* kd = Kw + r*36 + (c0>>1);
            *(uint4*)kd = ka; *(uint4*)(kd + 4) = kb2;
            uint32_t* vd = Vw + r*36 + (c0>>1);
            *(uint4*)vd = va; *(uint4*)(vd + 4) = vb;
        }
        __syncthreads();

        // S = Q K^T
        {
            float sacc[8][4] = {};
            #pragma unroll
            for (int ks = 0; ks < 4; ks++) {
                #pragma unroll
                for (int np = 0; np < 4; np++) {
                    uint32_t kd = su32(Kh + ((np<<4) + l16)*72 + (ks<<4) + (l2<<3));
                    uint32_t r0, r1, r2, r3;
                    LDSM4(r0, r1, r2, r3, kd);
                    unsigned b0[2] = {r0, r2}, b1[2] = {r1, r3};
                    MMA_F16(sacc[2*np],   qa[ks], b0);
                    MMA_F16(sacc[2*np+1], qa[ks], b1);
                }
            }
            float* s0 = &Ss[(i0+gid)*68 + (tig<<1)];
            float* s1 = s0 + 8*68;
            #pragma unroll
            for (int nt = 0; nt < 8; nt++) {
                *(float2*)(s0 + (nt<<3)) = make_float2(sacc[nt][0], sacc[nt][1]);
                *(float2*)(s1 + (nt<<3)) = make_float2(sacc[nt][2], sacc[nt][3]);
            }
        }
        __syncwarp();

        // online softmax (fp32, scale applied here)
        {
            int r  = i0 + (lane >> 1);
            int co = (lane & 1) << 5;
            bool diag = (kt >= 2*qt);
            float sv[32];
            float mloc = -1e30f;
            #pragma unroll
            for (int u = 0; u < 8; u++) {
                float4 s4 = *(const float4*)&Ss[r*68 + co + (u<<2)];
                s4.x *= scale; s4.y *= scale; s4.z *= scale; s4.w *= scale;
                if (diag) {
                    int jb = k0 + co + (u<<2), ii = q0 + r;
                    if (jb+0 > ii) s4.x = -1e30f;
                    if (jb+1 > ii) s4.y = -1e30f;
                    if (jb+2 > ii) s4.z = -1e30f;
                    if (jb+3 > ii) s4.w = -1e30f;
                }
                sv[(u<<2)+0] = s4.x; sv[(u<<2)+1] = s4.y;
                sv[(u<<2)+2] = s4.z; sv[(u<<2)+3] = s4.w;
                mloc = fmaxf(mloc, fmaxf(fmaxf(s4.x, s4.y), fmaxf(s4.z, s4.w)));
            }
            mloc = fmaxf(mloc, __shfl_xor_sync(0xffffffffu, mloc, 1));
            float mold = mrow[r];
            float mnew = fmaxf(mold, mloc);
            float ls = 0.f;
            int wbase = r*36 + (co>>1);
            #pragma unroll
            for (int u = 0; u < 16; u++) {
                float e0 = __expf(sv[(u<<1)]   - mnew);
                float e1 = __expf(sv[(u<<1)+1] - mnew);
                ls += e0 + e1;
                Pw[wbase + u] = f2h2(e0, e1);
            }
            ls += __shfl_xor_sync(0xffffffffu, ls, 1);
            if ((lane & 1) == 0) {
                float al = __expf(mold - mnew);
                arow[r] = al;
                lrow[r] = lrow[r] * al + ls;
                mrow[r] = mnew;
            }
        }
        __syncwarp();

        // rescale O, accumulate P @ V
        {
            float al0 = arow[i0 + gid];
            float al1 = arow[i0 + gid + 8];
            #pragma unroll
            for (int nt = 0; nt < 8; nt++) {
                oacc[nt][0] *= al0; oacc[nt][1] *= al0;
                oacc[nt][2] *= al1; oacc[nt][3] *= al1;
            }
            #pragma unroll
            for (int ks = 0; ks < 4; ks++) {
                unsigned a[4];
                uint32_t pd = su32(Ph + (i0 + l16)*72 + (ks<<4) + (l2<<3));
                LDSM4(a[0], a[1], a[2], a[3], pd);
                #pragma unroll
                for (int np = 0; np < 4; np++) {
                    uint32_t vdx = su32(Vh + ((ks<<4) + l16)*72 + (np<<4) + (l2<<3));
                    uint32_t r0, r1, r2, r3;
                    LDSM4T(r0, r1, r2, r3, vdx);
                    unsigned b0[2] = {r0, r1}, b1[2] = {r2, r3};
                    MMA_F16(oacc[2*np],   a, b0);
                    MMA_F16(oacc[2*np+1], a, b1);
                }
            }
        }
    }
    __syncthreads();

    // normalize + write half out[b, t, hh*64 + d]
    {
        float inv0 = 1.0f / lrow[i0 + gid];
        float inv1 = 1.0f / lrow[i0 + gid + 8];
        __half* o0 = out + ((size_t)(bb * T_ + q0 + i0 + gid)) * C_ + hh * D_ + (tig<<1);
        __half* o1 = o0 + 8 * C_;
        #pragma unroll
        for (int nt = 0; nt < 8; nt++) {
            *(uint32_t*)(o0 + (nt<<3)) = f2h2(oacc[nt][0]*inv0, oacc[nt][1]*inv0);
            *(uint32_t*)(o1 + (nt<<3)) = f2h2(oacc[nt][2]*inv1, oacc[nt][3]*inv1);
        }
    }
}

// ---------------- launch ----------------------------------------------------
extern "C" void kernel_launch(void* const* d_in, const int* in_sizes, int n_in,
                              void* d_out, int out_size)
{
    const float* x   = (const float*)d_in[0];
    const float* Wq  = (const float*)d_in[1];
    const float* Wk  = (const float*)d_in[2];
    const float* Wv  = (const float*)d_in[3];
    const float* Wo  = (const float*)d_in[4];
    const float* bo  = (const float*)d_in[5];
    const float* W1  = (const float*)d_in[6];
    const float* b1  = (const float*)d_in[7];
    const float* W2  = (const float*)d_in[8];
    const float* b2  = (const float*)d_in[9];
    const float* g1  = (const float*)d_in[10];
    const float* be1 = (const float*)d_in[11];
    const float* g2  = (const float*)d_in[12];
    const float* be2 = (const float*)d_in[13];
    float* out = (float*)d_out;

    __half *h, *wp, *qkv, *att, *h2, *ff, *woh, *w1h, *w2h;
    float *x1;
    cudaGetSymbolAddress((void**)&h,   hb_h);
    cudaGetSymbolAddress((void**)&wp,  hb_wp);
    cudaGetSymbolAddress((void**)&qkv, hb_qkv);
    cudaGetSymbolAddress((void**)&att, hb_att);
    cudaGetSymbolAddress((void**)&h2,  hb_h2);
    cudaGetSymbolAddress((void**)&ff,  hb_ff);
    cudaGetSymbolAddress((void**)&woh, hb_wo);
    cudaGetSymbolAddress((void**)&w1h, hb_w1);
    cudaGetSymbolAddress((void**)&w2h, hb_w2);
    cudaGetSymbolAddress((void**)&x1,  g_x1);

    cudaFuncSetAttribute(attn_kernel,
        cudaFuncAttributeMaxDynamicSharedMemorySize, ATT_SMEM_BYTES);
    cudaFuncSetAttribute(tgemm<0,0,0,1>,
        cudaFuncAttributeMaxDynamicSharedMemorySize, GT_SMEM);
    cudaFuncSetAttribute(tgemm<0,1,1,0>,
        cudaFuncAttributeMaxDynamicSharedMemorySize, GT_SMEM);
    cudaFuncSetAttribute(tgemm<1,0,1,1>,
        cudaFuncAttributeMaxDynamicSharedMemorySize, GT_SMEM);

    // 1) LN1 (half out)
    ln_kernel<<<M_, 256>>>(x, g1, be1, h);
    // 2) weight conversions (once per launch; tiny)
    repack_kernel<<<dim3((C_*C_)/256, 3), 256>>>(Wq, Wk, Wv, wp);
    f2h_kernel<<<(C_*C_)/1024, 256>>>(Wo, woh);
    f2h_kernel<<<(C_*F_)/1024, 256>>>(W1, w1h);
    f2h_kernel<<<(F_*C_)/1024, 256>>>(W2, w2h);
    // 3) fused QKV projection (half in/out)
    tgemm<0,0,0,1><<<dim3(QKVN/256, M_/128), 256, GT_SMEM>>>(h, wp, qkv, M_, QKVN, C_, nullptr, nullptr);
    // 4) causal flash attention (half in/out)
    attn_kernel<<<dim3(T_/128, B_*H_), 256, ATT_SMEM_BYTES>>>(qkv, att);
    // 5) Wo projection + bias + residual (fp32 out)
    tgemm<0,1,1,0><<<dim3(C_/256, M_/128), 256, GT_SMEM>>>(att, woh, x1, M_, C_, C_, bo, x);
    // 6) LN2 (half out)
    ln_kernel<<<M_, 256>>>(x1, g2, be2, h2);
    // 7) FFN up + ReLU (half out)
    tgemm<1,0,1,1><<<dim3(F_/256, M_/128), 256, GT_SMEM>>>(h2, w1h, ff, M_, F_, C_, b1, nullptr);
    // 8) FFN down + bias + residual -> final fp32 output
    tgemm<0,1,1,0><<<dim3(C_/256, M_/128), 256, GT_SMEM>>>(ff, w2h, out, M_, C_, F_, b2, x1);
}

// round 9
// speedup vs baseline: 6.1126x; 1.0225x over previous
#include <cuda_runtime.h>
#include <cuda_fp16.h>
#include <cstdint>

#define B_ 2
#define T_ 2048
#define C_ 1024
#define H_ 16
#define D_ 64
#define F_ 4096
#define M_ (B_*T_)   // 4096 rows
#define QKVN 3072

// ---------------- scratch (device globals; no runtime allocation) ----------
__device__ __align__(16) __half hb_h  [M_*C_];    // ln1 out (half)
__device__ __align__(16) __half hb_wp [C_*QKVN];  // packed Wqkv (half)
__device__ __align__(16) __half hb_qkv[M_*QKVN];  // qkv activations (half)
__device__ __align__(16) __half hb_att[M_*C_];    // attn out (half)
__device__ __align__(16) __half hb_h2 [M_*C_];    // ln2 out (half)
__device__ __align__(16) __half hb_ff [M_*F_];    // ffn mid (half)
__device__ __align__(16) __half hb_wo [C_*C_];
__device__ __align__(16) __half hb_w1 [C_*F_];
__device__ __align__(16) __half hb_w2 [F_*C_];
__device__ __align__(16) float  g_x1  [M_*C_];    // attn residual out (fp32)

__device__ __forceinline__ uint32_t f2h2(float x, float y) {
    __half2 h = __floats2half2_rn(x, y);
    return *(uint32_t*)&h;
}
__device__ __forceinline__ uint32_t su32(const void* p) {
    return (uint32_t)__cvta_generic_to_shared(p);
}

#define MMA_F16(acc, a, b) \
    asm volatile( \
        "mma.sync.aligned.m16n8k16.row.col.f32.f16.f16.f32 " \
        "{%0,%1,%2,%3},{%4,%5,%6,%7},{%8,%9},{%0,%1,%2,%3};" \
        : "+f"((acc)[0]), "+f"((acc)[1]), "+f"((acc)[2]), "+f"((acc)[3]) \
        : "r"((a)[0]), "r"((a)[1]), "r"((a)[2]), "r"((a)[3]), \
          "r"((b)[0]), "r"((b)[1]))

#define LDSM4(r0, r1, r2, r3, addr) \
    asm volatile("ldmatrix.sync.aligned.m8n8.x4.shared.b16 {%0,%1,%2,%3}, [%4];" \
        : "=r"(r0), "=r"(r1), "=r"(r2), "=r"(r3) : "r"(addr))
#define LDSM4T(r0, r1, r2, r3, addr) \
    asm volatile("ldmatrix.sync.aligned.m8n8.x4.trans.shared.b16 {%0,%1,%2,%3}, [%4];" \
        : "=r"(r0), "=r"(r1), "=r"(r2), "=r"(r3) : "r"(addr))

#define CPA16(dst, src) \
    asm volatile("cp.async.cg.shared.global [%0], [%1], 16;" :: "r"(dst), "l"(src))
#define CPA_COMMIT() asm volatile("cp.async.commit_group;" ::: "memory")
#define CPA_WAIT(n)  asm volatile("cp.async.wait_group %0;" :: "n"(n) : "memory")

// ---------------- LayerNorm: fp32 in, half out ------------------------------
__global__ __launch_bounds__(256) void ln_kernel(
    const float* __restrict__ x, const float* __restrict__ g,
    const float* __restrict__ b, __half* __restrict__ out)
{
    int row = blockIdx.x;
    int tid = threadIdx.x;
    const float4 xv = ((const float4*)(x + (size_t)row*C_))[tid];
    float s  = xv.x + xv.y + xv.z + xv.w;
    float s2 = xv.x*xv.x + xv.y*xv.y + xv.z*xv.z + xv.w*xv.w;
    __shared__ float rs[8], rs2[8];
    #pragma unroll
    for (int o = 16; o; o >>= 1) {
        s  += __shfl_down_sync(0xffffffffu, s,  o);
        s2 += __shfl_down_sync(0xffffffffu, s2, o);
    }
    if ((tid & 31) == 0) { rs[tid>>5] = s; rs2[tid>>5] = s2; }
    __syncthreads();
    if (tid == 0) {
        float a = 0.f, c = 0.f;
        #pragma unroll
        for (int i = 0; i < 8; i++) { a += rs[i]; c += rs2[i]; }
        rs[0] = a; rs2[0] = c;
    }
    __syncthreads();
    float mean = rs[0] * (1.0f/C_);
    float var  = rs2[0] * (1.0f/C_) - mean*mean;
    float rstd = rsqrtf(var + 1e-5f);
    const float4 gv = ((const float4*)g)[tid];
    const float4 bv = ((const float4*)b)[tid];
    uint2 w;
    w.x = f2h2((xv.x-mean)*rstd*gv.x + bv.x, (xv.y-mean)*rstd*gv.y + bv.y);
    w.y = f2h2((xv.z-mean)*rstd*gv.z + bv.z, (xv.w-mean)*rstd*gv.w + bv.w);
    *(uint2*)(out + (size_t)row*C_ + (tid<<2)) = w;
}

// ---------------- merged weight prep: Wo/W1/W2 fp32 -> fp16 ------------------
__global__ __launch_bounds__(256) void wprep_kernel(
    const float* __restrict__ Wo, const float* __restrict__ W1,
    const float* __restrict__ W2, __half* __restrict__ woh,
    __half* __restrict__ w1h, __half* __restrict__ w2h)
{
    size_t i = ((size_t)blockIdx.x*256 + threadIdx.x) << 2;
    const float* src; __half* dst; size_t off;
    const size_t S0 = (size_t)C_*C_, S1 = S0 + (size_t)C_*F_;
    if (i < S0)      { src = Wo; dst = woh; off = i; }
    else if (i < S1) { src = W1; dst = w1h; off = i - S0; }
    else             { src = W2; dst = w2h; off = i - S1; }
    float4 v = *(const float4*)(src + off);
    uint2 w;
    w.x = f2h2(v.x, v.y); w.y = f2h2(v.z, v.w);
    *(uint2*)(dst + off) = w;
}

// ---------------- repack Wq/Wk/Wv [H][C][D] -> half [C][3*C] ----------------
__global__ __launch_bounds__(256) void repack_kernel(
    const float* __restrict__ Wq, const float* __restrict__ Wk,
    const float* __restrict__ Wv, __half* __restrict__ Wp)
{
    int idx = blockIdx.x*256 + threadIdx.x;        // over C*C
    int which = blockIdx.y;
    const float* W = (which==0) ? Wq : (which==1) ? Wk : Wv;
    int c = idx >> 10, n = idx & 1023;
    int h = n >> 6, d = n & 63;
    Wp[(size_t)c*QKVN + which*C_ + n] = __float2half_rn(W[((size_t)h*C_ + c)*D_ + d]);
}

// ---------------- fp16 GEMM: 128x256 tile, 64x64 warp tile, 4-stage async --
#define GSTAGE 27136
#define GBOF   10240
#define GT_SMEM (4*GSTAGE)

template<int RELU, int HASRES, int HASBIAS, int OUTHALF>
__global__ __launch_bounds__(256, 1) void tgemm(
    const __half* __restrict__ A, const __half* __restrict__ Bm,
    void* __restrict__ Cm, int M, int N, int K,
    const float* __restrict__ bias, const float* __restrict__ res)
{
    extern __shared__ char dsm[];
    int tid = threadIdx.x;
    int m0 = blockIdx.y << 7, n0 = blockIdx.x << 8;
    int warp = tid >> 5, lane = tid & 31;
    int l16 = lane & 15, l2 = lane >> 4;
    int gid = lane >> 2, tig = lane & 3;
    int wm = (warp & 1) << 6;
    int wn = (warp >> 1) << 6;

    float acc[4][8][4] = {};

    int ra = tid >> 1, ca = (tid & 1) << 4;
    int rb = tid >> 3, tb = (tid & 7) << 3;
    const __half* Ap = A  + (size_t)(m0 + ra) * K + ca;
    const __half* Bp = Bm + (size_t)rb * N + n0 + tb;
    uint32_t abase[4], bbase[4];
    #pragma unroll
    for (int s = 0; s < 4; s++) {
        abase[s] = su32(dsm + s*GSTAGE + (ra*40 + ca)*2);
        bbase[s] = su32(dsm + s*GSTAGE + GBOF + (rb*264 + tb)*2);
    }

    int KT = K >> 5;
    #pragma unroll
    for (int p = 0; p < 2; p++) {
        const __half* ap = Ap + (p<<5);
        const __half* bp = Bp + (size_t)(p<<5) * N;
        CPA16(abase[p],      ap);
        CPA16(abase[p] + 16, ap + 8);
        #pragma unroll
        for (int u = 0; u < 4; u++)
            CPA16(bbase[p] + (u<<7), bp + (u<<6));
        CPA_COMMIT();
    }

    for (int kt = 0; kt < KT; kt++) {
        if (kt + 2 < KT) {
            int s = (kt + 2) & 3;
            const __half* ap = Ap + ((kt+2)<<5);
            const __half* bp = Bp + (size_t)((kt+2)<<5) * N;
            CPA16(abase[s],      ap);
            CPA16(abase[s] + 16, ap + 8);
            #pragma unroll
            for (int u = 0; u < 4; u++)
                CPA16(bbase[s] + (u<<7), bp + (u<<6));
            CPA_COMMIT();
            CPA_WAIT(2);
        } else if (kt + 1 < KT) {
            CPA_WAIT(1);
        } else {
            CPA_WAIT(0);
        }
        __syncthreads();

        const __half* Ah = (const __half*)(dsm + (kt&3)*GSTAGE);
        const __half* Bh = (const __half*)(dsm + (kt&3)*GSTAGE + GBOF);
        #pragma unroll
        for (int ks = 0; ks < 2; ks++) {
            unsigned a[4][4], b[8][2];
            #pragma unroll
            for (int mt = 0; mt < 4; mt++) {
                uint32_t ad = su32(Ah + (wm + (mt<<4) + l16)*40 + (ks<<4) + (l2<<3));
                LDSM4(a[mt][0], a[mt][1], a[mt][2], a[mt][3], ad);
            }
            #pragma unroll
            for (int np = 0; np < 4; np++) {
                uint32_t bd = su32(Bh + ((ks<<4) + l16)*264 + wn + (np<<4) + (l2<<3));
                uint32_t r0, r1, r2, r3;
                LDSM4T(r0, r1, r2, r3, bd);
                b[2*np][0] = r0; b[2*np][1] = r1;
                b[2*np+1][0] = r2; b[2*np+1][1] = r3;
            }
            #pragma unroll
            for (int mt = 0; mt < 4; mt++)
                #pragma unroll
                for (int nt = 0; nt < 8; nt++)
                    MMA_F16(acc[mt][nt], a[mt], b[nt]);
        }
    }

    #pragma unroll
    for (int mt = 0; mt < 4; mt++) {
        int mr = m0 + wm + (mt<<4) + gid;
        #pragma unroll
        for (int nt = 0; nt < 8; nt++) {
            int nc = n0 + wn + (nt<<3) + (tig<<1);
            float2 bb = make_float2(0.f, 0.f);
            if (HASBIAS) bb = *(const float2*)(bias + nc);
            float2 o0 = make_float2(acc[mt][nt][0] + bb.x, acc[mt][nt][1] + bb.y);
            float2 o1 = make_float2(acc[mt][nt][2] + bb.x, acc[mt][nt][3] + bb.y);
            if (RELU) {
                o0.x = fmaxf(o0.x, 0.f); o0.y = fmaxf(o0.y, 0.f);
                o1.x = fmaxf(o1.x, 0.f); o1.y = fmaxf(o1.y, 0.f);
            }
            if (HASRES) {
                float2 r0 = *(const float2*)(res + (size_t)mr * N + nc);
                float2 r1 = *(const float2*)(res + (size_t)(mr+8) * N + nc);
                o0.x += r0.x; o0.y += r0.y;
                o1.x += r1.x; o1.y += r1.y;
            }
            if (OUTHALF) {
                __half* Ch = (__half*)Cm;
                *(uint32_t*)(Ch + (size_t)mr     * N + nc) = f2h2(o0.x, o0.y);
                *(uint32_t*)(Ch + (size_t)(mr+8) * N + nc) = f2h2(o1.x, o1.y);
            } else {
                float* Cf = (float*)Cm;
                *(float2*)(Cf + (size_t)mr     * N + nc) = o0;
                *(float2*)(Cf + (size_t)(mr+8) * N + nc) = o1;
            }
        }
    }
}

// ---------------- fp16 flash attention, cp.async double-buffered K/V --------
// smem floats: Ss[128][68] | Ps 128x36w | K0 K1 V0 V1 64x36w | rows[384]
#define ATT_PS    (128*68)
#define ATT_K0    (ATT_PS + 128*36)
#define ATT_K1    (ATT_K0 + 64*36)
#define ATT_V0    (ATT_K1 + 64*36)
#define ATT_V1    (ATT_V0 + 64*36)
#define ATT_ROWS  (ATT_V1 + 64*36)
#define ATT_SMEM_FLOATS (ATT_ROWS + 3*128)
#define ATT_SMEM_BYTES  (ATT_SMEM_FLOATS*4)

__global__ __launch_bounds__(256, 2) void attn_kernel(
    const __half* __restrict__ qkv, __half* __restrict__ out)
{
    extern __shared__ float sm[];
    float*    Ss = sm;
    uint32_t* Pw = (uint32_t*)(sm + ATT_PS);       // row stride 36 words
    __half*   Ph = (__half*)Pw;
    uint32_t* Kbuf[2] = {(uint32_t*)(sm + ATT_K0), (uint32_t*)(sm + ATT_K1)};
    uint32_t* Vbuf[2] = {(uint32_t*)(sm + ATT_V0), (uint32_t*)(sm + ATT_V1)};
    float* mrow = sm + ATT_ROWS;
    float* lrow = mrow + 128;
    float* arow = lrow + 128;

    int qt = (int)gridDim.x - 1 - (int)blockIdx.x;   // heavy tiles first
    int bh = blockIdx.y;
    int q0 = qt << 7;
    int bb = bh >> 4, hh = bh & 15;
    const __half* Qg = qkv + (size_t)(bb * T_) * QKVN + hh * D_;
    const __half* Kg = Qg + C_;
    const __half* Vg = Qg + 2*C_;
    int tid = threadIdx.x;
    int warp = tid >> 5, lane = tid & 31;
    int l16 = lane & 15, l2 = lane >> 4;
    int gid = lane >> 2, tig = lane & 3;
    int i0 = warp << 4;
    const float scale = 0.03125f;    // C^-0.5, applied to fp32 S in softmax

    // K/V copy mapping (per thread): row r, 16 halves at c0
    int cr = tid >> 2, cc = (tid & 3) << 4;
    uint32_t kdst[2], vdst[2];
    #pragma unroll
    for (int b = 0; b < 2; b++) {
        kdst[b] = su32((__half*)Kbuf[b] + cr*72 + cc);
        vdst[b] = su32((__half*)Vbuf[b] + cr*72 + cc);
    }

    // Q fragments (packed half2 words straight from gmem)
    unsigned qa[4][4];
    {
        const __half* q0p = Qg + (size_t)(q0 + i0 + gid) * QKVN;
        const __half* q1p = q0p + 8 * QKVN;
        #pragma unroll
        for (int ks = 0; ks < 4; ks++) {
            int c = (ks<<4) + (tig<<1);
            qa[ks][0] = *(const uint32_t*)(q0p + c);
            qa[ks][1] = *(const uint32_t*)(q1p + c);
            qa[ks][2] = *(const uint32_t*)(q0p + c + 8);
            qa[ks][3] = *(const uint32_t*)(q1p + c + 8);
        }
    }
    if (tid < 128) { mrow[tid] = -1e30f; lrow[tid] = 0.f; }

    float oacc[8][4] = {};

    int ktmax = 2*qt + 1;
    // prefetch tile 0 -> buf 0
    {
        const __half* kp = Kg + (size_t)cr * QKVN + cc;
        const __half* vp = Vg + (size_t)cr * QKVN + cc;
        CPA16(kdst[0], kp); CPA16(kdst[0] + 16, kp + 8);
        CPA16(vdst[0], vp); CPA16(vdst[0] + 16, vp + 8);
        CPA_COMMIT();
    }

    for (int kt = 0; kt <= ktmax; kt++) {
        int buf = kt & 1;
        int k0 = kt << 6;
        __syncthreads();                 // prior compute done; safe to fill buf^1
        if (kt < ktmax) {
            int k1 = (kt + 1) << 6;
            const __half* kp = Kg + (size_t)(k1 + cr) * QKVN + cc;
            const __half* vp = Vg + (size_t)(k1 + cr) * QKVN + cc;
            CPA16(kdst[buf^1], kp); CPA16(kdst[buf^1] + 16, kp + 8);
            CPA16(vdst[buf^1], vp); CPA16(vdst[buf^1] + 16, vp + 8);
            CPA_COMMIT();
            CPA_WAIT(1);                 // tile kt ready (committed last iter)
        } else {
            CPA_WAIT(0);
        }
        __syncthreads();                 // tile kt visible to all warps

        const __half* Kh = (const __half*)Kbuf[buf];
        const __half* Vh = (const __half*)Vbuf[buf];

        // S = Q K^T
        {
            float sacc[8][4] = {};
            #pragma unroll
            for (int ks = 0; ks < 4; ks++) {
                #pragma unroll
                for (int np = 0; np < 4; np++) {
                    uint32_t kd = su32(Kh + ((np<<4) + l16)*72 + (ks<<4) + (l2<<3));
                    uint32_t r0, r1, r2, r3;
                    LDSM4(r0, r1, r2, r3, kd);
                    unsigned b0[2] = {r0, r2}, b1[2] = {r1, r3};
                    MMA_F16(sacc[2*np],   qa[ks], b0);
                    MMA_F16(sacc[2*np+1], qa[ks], b1);
                }
            }
            float* s0 = &Ss[(i0+gid)*68 + (tig<<1)];
            float* s1 = s0 + 8*68;
            #pragma unroll
            for (int nt = 0; nt < 8; nt++) {
                *(float2*)(s0 + (nt<<3)) = make_float2(sacc[nt][0], sacc[nt][1]);
                *(float2*)(s1 + (nt<<3)) = make_float2(sacc[nt][2], sacc[nt][3]);
            }
        }
        __syncwarp();

        // online softmax (fp32, scale applied here)
        {
            int r  = i0 + (lane >> 1);
            int co = (lane & 1) << 5;
            bool diag = (kt >= 2*qt);
            float sv[32];
            float mloc = -1e30f;
            #pragma unroll
            for (int u = 0; u < 8; u++) {
                float4 s4 = *(const float4*)&Ss[r*68 + co + (u<<2)];
                s4.x *= scale; s4.y *= scale; s4.z *= scale; s4.w *= scale;
                if (diag) {
                    int jb = k0 + co + (u<<2), ii = q0 + r;
                    if (jb+0 > ii) s4.x = -1e30f;
                    if (jb+1 > ii) s4.y = -1e30f;
                    if (jb+2 > ii) s4.z = -1e30f;
                    if (jb+3 > ii) s4.w = -1e30f;
                }
                sv[(u<<2)+0] = s4.x; sv[(u<<2)+1] = s4.y;
                sv[(u<<2)+2] = s4.z; sv[(u<<2)+3] = s4.w;
                mloc = fmaxf(mloc, fmaxf(fmaxf(s4.x, s4.y), fmaxf(s4.z, s4.w)));
            }
            mloc = fmaxf(mloc, __shfl_xor_sync(0xffffffffu, mloc, 1));
            float mold = mrow[r];
            float mnew = fmaxf(mold, mloc);
            float ls = 0.f;
            int wbase = r*36 + (co>>1);
            #pragma unroll
            for (int u = 0; u < 16; u++) {
                float e0 = __expf(sv[(u<<1)]   - mnew);
                float e1 = __expf(sv[(u<<1)+1] - mnew);
                ls += e0 + e1;
                Pw[wbase + u] = f2h2(e0, e1);
            }
            ls += __shfl_xor_sync(0xffffffffu, ls, 1);
            if ((lane & 1) == 0) {
                float al = __expf(mold - mnew);
                arow[r] = al;
                lrow[r] = lrow[r] * al + ls;
                mrow[r] = mnew;
            }
        }
        __syncwarp();

        // rescale O, accumulate P @ V
        {
            float al0 = arow[i0 + gid];
            float al1 = arow[i0 + gid + 8];
            #pragma unroll
            for (int nt = 0; nt < 8; nt++) {
                oacc[nt][0] *= al0; oacc[nt][1] *= al0;
                oacc[nt][2] *= al1; oacc[nt][3] *= al1;
            }
            #pragma unroll
            for (int ks = 0; ks < 4; ks++) {
                unsigned a[4];
                uint32_t pd = su32(Ph + (i0 + l16)*72 + (ks<<4) + (l2<<3));
                LDSM4(a[0], a[1], a[2], a[3], pd);
                #pragma unroll
                for (int np = 0; np < 4; np++) {
                    uint32_t vdx = su32(Vh + ((ks<<4) + l16)*72 + (np<<4) + (l2<<3));
                    uint32_t r0, r1, r2, r3;
                    LDSM4T(r0, r1, r2, r3, vdx);
                    unsigned b0[2] = {r0, r1}, b1[2] = {r2, r3};
                    MMA_F16(oacc[2*np],   a, b0);
                    MMA_F16(oacc[2*np+1], a, b1);
                }
            }
        }
    }
    __syncthreads();

    // normalize + write half out[b, t, hh*64 + d]
    {
        float inv0 = 1.0f / lrow[i0 + gid];
        float inv1 = 1.0f / lrow[i0 + gid + 8];
        __half* o0 = out + ((size_t)(bb * T_ + q0 + i0 + gid)) * C_ + hh * D_ + (tig<<1);
        __half* o1 = o0 + 8 * C_;
        #pragma unroll
        for (int nt = 0; nt < 8; nt++) {
            *(uint32_t*)(o0 + (nt<<3)) = f2h2(oacc[nt][0]*inv0, oacc[nt][1]*inv0);
            *(uint32_t*)(o1 + (nt<<3)) = f2h2(oacc[nt][2]*inv1, oacc[nt][3]*inv1);
        }
    }
}

// ---------------- launch ----------------------------------------------------
extern "C" void kernel_launch(void* const* d_in, const int* in_sizes, int n_in,
                              void* d_out, int out_size)
{
    const float* x   = (const float*)d_in[0];
    const float* Wq  = (const float*)d_in[1];
    const float* Wk  = (const float*)d_in[2];
    const float* Wv  = (const float*)d_in[3];
    const float* Wo  = (const float*)d_in[4];
    const float* bo  = (const float*)d_in[5];
    const float* W1  = (const float*)d_in[6];
    const float* b1  = (const float*)d_in[7];
    const float* W2  = (const float*)d_in[8];
    const float* b2  = (const float*)d_in[9];
    const float* g1  = (const float*)d_in[10];
    const float* be1 = (const float*)d_in[11];
    const float* g2  = (const float*)d_in[12];
    const float* be2 = (const float*)d_in[13];
    float* out = (float*)d_out;

    __half *h, *wp, *qkv, *att, *h2, *ff, *woh, *w1h, *w2h;
    float *x1;
    cudaGetSymbolAddress((void**)&h,   hb_h);
    cudaGetSymbolAddress((void**)&wp,  hb_wp);
    cudaGetSymbolAddress((void**)&qkv, hb_qkv);
    cudaGetSymbolAddress((void**)&att, hb_att);
    cudaGetSymbolAddress((void**)&h2,  hb_h2);
    cudaGetSymbolAddress((void**)&ff,  hb_ff);
    cudaGetSymbolAddress((void**)&woh, hb_wo);
    cudaGetSymbolAddress((void**)&w1h, hb_w1);
    cudaGetSymbolAddress((void**)&w2h, hb_w2);
    cudaGetSymbolAddress((void**)&x1,  g_x1);

    cudaFuncSetAttribute(attn_kernel,
        cudaFuncAttributeMaxDynamicSharedMemorySize, ATT_SMEM_BYTES);
    cudaFuncSetAttribute(tgemm<0,0,0,1>,
        cudaFuncAttributeMaxDynamicSharedMemorySize, GT_SMEM);
    cudaFuncSetAttribute(tgemm<0,1,1,0>,
        cudaFuncAttributeMaxDynamicSharedMemorySize, GT_SMEM);
    cudaFuncSetAttribute(tgemm<1,0,1,1>,
        cudaFuncAttributeMaxDynamicSharedMemorySize, GT_SMEM);

    // 1) LN1 (half out)
    ln_kernel<<<M_, 256>>>(x, g1, be1, h);
    // 2) weight conversions (merged) + qkv repack
    repack_kernel<<<dim3((C_*C_)/256, 3), 256>>>(Wq, Wk, Wv, wp);
    wprep_kernel<<<(C_*C_ + 2*C_*F_)/1024, 256>>>(Wo, W1, W2, woh, w1h, w2h);
    // 3) fused QKV projection (half in/out)
    tgemm<0,0,0,1><<<dim3(QKVN/256, M_/128), 256, GT_SMEM>>>(h, wp, qkv, M_, QKVN, C_, nullptr, nullptr);
    // 4) causal flash attention (half in/out, cp.async K/V pipeline)
    attn_kernel<<<dim3(T_/128, B_*H_), 256, ATT_SMEM_BYTES>>>(qkv, att);
    // 5) Wo projection + bias + residual (fp32 out)
    tgemm<0,1,1,0><<<dim3(C_/256, M_/128), 256, GT_SMEM>>>(att, woh, x1, M_, C_, C_, bo, x);
    // 6) LN2 (half out)
    ln_kernel<<<M_, 256>>>(x1, g2, be2, h2);
    // 7) FFN up + ReLU (half out)
    tgemm<1,0,1,1><<<dim3(F_/256, M_/128), 256, GT_SMEM>>>(h2, w1h, ff, M_, F_, C_, b1, nullptr);
    // 8) FFN down + bias + residual -> final fp32 output
    tgemm<0,1,1,0><<<dim3(C_/256, M_/128), 256, GT_SMEM>>>(ff, w2h, out, M_, C_, F_, b2, x1);
}

// round 10
// speedup vs baseline: 6.6502x; 1.0879x over previous
#include <cuda_runtime.h>
#include <cuda_fp16.h>
#include <cstdint>

#define B_ 2
#define T_ 2048
#define C_ 1024
#define H_ 16
#define D_ 64
#define F_ 4096
#define M_ (B_*T_)   // 4096 rows
#define QKVN 3072

// ---------------- scratch (device globals; no runtime allocation) ----------
__device__ __align__(16) __half hb_h  [M_*C_];    // ln1 out (half)
__device__ __align__(16) __half hb_wp [C_*QKVN];  // packed Wqkv (half)
__device__ __align__(16) __half hb_qkv[M_*QKVN];  // qkv activations (half)
__device__ __align__(16) __half hb_att[M_*C_];    // attn out (half)
__device__ __align__(16) __half hb_h2 [M_*C_];    // ln2 out (half)
__device__ __align__(16) __half hb_ff [M_*F_];    // ffn mid (half)
__device__ __align__(16) __half hb_wo [C_*C_];
__device__ __align__(16) __half hb_w1 [C_*F_];
__device__ __align__(16) __half hb_w2 [F_*C_];
__device__ __align__(16) float  g_x1  [M_*C_];    // attn residual out (fp32)

__device__ __forceinline__ uint32_t f2h2(float x, float y) {
    __half2 h = __floats2half2_rn(x, y);
    return *(uint32_t*)&h;
}
__device__ __forceinline__ uint32_t su32(const void* p) {
    return (uint32_t)__cvta_generic_to_shared(p);
}

#define MMA_F16(acc, a, b) \
    asm volatile( \
        "mma.sync.aligned.m16n8k16.row.col.f32.f16.f16.f32 " \
        "{%0,%1,%2,%3},{%4,%5,%6,%7},{%8,%9},{%0,%1,%2,%3};" \
        : "+f"((acc)[0]), "+f"((acc)[1]), "+f"((acc)[2]), "+f"((acc)[3]) \
        : "r"((a)[0]), "r"((a)[1]), "r"((a)[2]), "r"((a)[3]), \
          "r"((b)[0]), "r"((b)[1]))

#define LDSM4(r0, r1, r2, r3, addr) \
    asm volatile("ldmatrix.sync.aligned.m8n8.x4.shared.b16 {%0,%1,%2,%3}, [%4];" \
        : "=r"(r0), "=r"(r1), "=r"(r2), "=r"(r3) : "r"(addr))
#define LDSM4T(r0, r1, r2, r3, addr) \
    asm volatile("ldmatrix.sync.aligned.m8n8.x4.trans.shared.b16 {%0,%1,%2,%3}, [%4];" \
        : "=r"(r0), "=r"(r1), "=r"(r2), "=r"(r3) : "r"(addr))

#define CPA16(dst, src) \
    asm volatile("cp.async.cg.shared.global [%0], [%1], 16;" :: "r"(dst), "l"(src))
#define CPA_COMMIT() asm volatile("cp.async.commit_group;" ::: "memory")
#define CPA_WAIT(n)  asm volatile("cp.async.wait_group %0;" :: "n"(n) : "memory")

// ---------------- LayerNorm: fp32 in, half out ------------------------------
__global__ __launch_bounds__(256) void ln_kernel(
    const float* __restrict__ x, const float* __restrict__ g,
    const float* __restrict__ b, __half* __restrict__ out)
{
    int row = blockIdx.x;
    int tid = threadIdx.x;
    const float4 xv = ((const float4*)(x + (size_t)row*C_))[tid];
    float s  = xv.x + xv.y + xv.z + xv.w;
    float s2 = xv.x*xv.x + xv.y*xv.y + xv.z*xv.z + xv.w*xv.w;
    __shared__ float rs[8], rs2[8];
    #pragma unroll
    for (int o = 16; o; o >>= 1) {
        s  += __shfl_down_sync(0xffffffffu, s,  o);
        s2 += __shfl_down_sync(0xffffffffu, s2, o);
    }
    if ((tid & 31) == 0) { rs[tid>>5] = s; rs2[tid>>5] = s2; }
    __syncthreads();
    if (tid == 0) {
        float a = 0.f, c = 0.f;
        #pragma unroll
        for (int i = 0; i < 8; i++) { a += rs[i]; c += rs2[i]; }
        rs[0] = a; rs2[0] = c;
    }
    __syncthreads();
    float mean = rs[0] * (1.0f/C_);
    float var  = rs2[0] * (1.0f/C_) - mean*mean;
    float rstd = rsqrtf(var + 1e-5f);
    const float4 gv = ((const float4*)g)[tid];
    const float4 bv = ((const float4*)b)[tid];
    uint2 w;
    w.x = f2h2((xv.x-mean)*rstd*gv.x + bv.x, (xv.y-mean)*rstd*gv.y + bv.y);
    w.y = f2h2((xv.z-mean)*rstd*gv.z + bv.z, (xv.w-mean)*rstd*gv.w + bv.w);
    *(uint2*)(out + (size_t)row*C_ + (tid<<2)) = w;
}

// ---------------- merged weight prep: Wo/W1/W2 fp32 -> fp16 ------------------
__global__ __launch_bounds__(256) void wprep_kernel(
    const float* __restrict__ Wo, const float* __restrict__ W1,
    const float* __restrict__ W2, __half* __restrict__ woh,
    __half* __restrict__ w1h, __half* __restrict__ w2h)
{
    size_t i = ((size_t)blockIdx.x*256 + threadIdx.x) << 2;
    const float* src; __half* dst; size_t off;
    const size_t S0 = (size_t)C_*C_, S1 = S0 + (size_t)C_*F_;
    if (i < S0)      { src = Wo; dst = woh; off = i; }
    else if (i < S1) { src = W1; dst = w1h; off = i - S0; }
    else             { src = W2; dst = w2h; off = i - S1; }
    float4 v = *(const float4*)(src + off);
    uint2 w;
    w.x = f2h2(v.x, v.y); w.y = f2h2(v.z, v.w);
    *(uint2*)(dst + off) = w;
}

// ---------------- repack Wq/Wk/Wv [H][C][D] -> half [C][3*C] ----------------
__global__ __launch_bounds__(256) void repack_kernel(
    const float* __restrict__ Wq, const float* __restrict__ Wk,
    const float* __restrict__ Wv, __half* __restrict__ Wp)
{
    int idx = blockIdx.x*256 + threadIdx.x;        // over C*C
    int which = blockIdx.y;
    const float* W = (which==0) ? Wq : (which==1) ? Wk : Wv;
    int c = idx >> 10, n = idx & 1023;
    int h = n >> 6, d = n & 63;
    Wp[(size_t)c*QKVN + which*C_ + n] = __float2half_rn(W[((size_t)h*C_ + c)*D_ + d]);
}

// ---------------- fp16 GEMM: 128x256 tile, 64x64 warp tile, 4-stage async --
#define GSTAGE 27136
#define GBOF   10240
#define GT_SMEM (4*GSTAGE)

template<int RELU, int HASRES, int HASBIAS, int OUTHALF>
__global__ __launch_bounds__(256, 1) void tgemm(
    const __half* __restrict__ A, const __half* __restrict__ Bm,
    void* __restrict__ Cm, int M, int N, int K,
    const float* __restrict__ bias, const float* __restrict__ res)
{
    extern __shared__ char dsm[];
    int tid = threadIdx.x;
    int m0 = blockIdx.y << 7, n0 = blockIdx.x << 8;
    int warp = tid >> 5, lane = tid & 31;
    int l16 = lane & 15, l2 = lane >> 4;
    int gid = lane >> 2, tig = lane & 3;
    int wm = (warp & 1) << 6;
    int wn = (warp >> 1) << 6;

    float acc[4][8][4] = {};

    int ra = tid >> 1, ca = (tid & 1) << 4;
    int rb = tid >> 3, tb = (tid & 7) << 3;
    const __half* Ap = A  + (size_t)(m0 + ra) * K + ca;
    const __half* Bp = Bm + (size_t)rb * N + n0 + tb;
    uint32_t abase[4], bbase[4];
    #pragma unroll
    for (int s = 0; s < 4; s++) {
        abase[s] = su32(dsm + s*GSTAGE + (ra*40 + ca)*2);
        bbase[s] = su32(dsm + s*GSTAGE + GBOF + (rb*264 + tb)*2);
    }

    int KT = K >> 5;
    #pragma unroll
    for (int p = 0; p < 2; p++) {
        const __half* ap = Ap + (p<<5);
        const __half* bp = Bp + (size_t)(p<<5) * N;
        CPA16(abase[p],      ap);
        CPA16(abase[p] + 16, ap + 8);
        #pragma unroll
        for (int u = 0; u < 4; u++)
            CPA16(bbase[p] + (u<<7), bp + (u<<6));
        CPA_COMMIT();
    }

    for (int kt = 0; kt < KT; kt++) {
        if (kt + 2 < KT) {
            int s = (kt + 2) & 3;
            const __half* ap = Ap + ((kt+2)<<5);
            const __half* bp = Bp + (size_t)((kt+2)<<5) * N;
            CPA16(abase[s],      ap);
            CPA16(abase[s] + 16, ap + 8);
            #pragma unroll
            for (int u = 0; u < 4; u++)
                CPA16(bbase[s] + (u<<7), bp + (u<<6));
            CPA_COMMIT();
            CPA_WAIT(2);
        } else if (kt + 1 < KT) {
            CPA_WAIT(1);
        } else {
            CPA_WAIT(0);
        }
        __syncthreads();

        const __half* Ah = (const __half*)(dsm + (kt&3)*GSTAGE);
        const __half* Bh = (const __half*)(dsm + (kt&3)*GSTAGE + GBOF);
        #pragma unroll
        for (int ks = 0; ks < 2; ks++) {
            unsigned a[4][4], b[8][2];
            #pragma unroll
            for (int mt = 0; mt < 4; mt++) {
                uint32_t ad = su32(Ah + (wm + (mt<<4) + l16)*40 + (ks<<4) + (l2<<3));
                LDSM4(a[mt][0], a[mt][1], a[mt][2], a[mt][3], ad);
            }
            #pragma unroll
            for (int np = 0; np < 4; np++) {
                uint32_t bd = su32(Bh + ((ks<<4) + l16)*264 + wn + (np<<4) + (l2<<3));
                uint32_t r0, r1, r2, r3;
                LDSM4T(r0, r1, r2, r3, bd);
                b[2*np][0] = r0; b[2*np][1] = r1;
                b[2*np+1][0] = r2; b[2*np+1][1] = r3;
            }
            #pragma unroll
            for (int mt = 0; mt < 4; mt++)
                #pragma unroll
                for (int nt = 0; nt < 8; nt++)
                    MMA_F16(acc[mt][nt], a[mt], b[nt]);
        }
    }

    #pragma unroll
    for (int mt = 0; mt < 4; mt++) {
        int mr = m0 + wm + (mt<<4) + gid;
        #pragma unroll
        for (int nt = 0; nt < 8; nt++) {
            int nc = n0 + wn + (nt<<3) + (tig<<1);
            float2 bb = make_float2(0.f, 0.f);
            if (HASBIAS) bb = *(const float2*)(bias + nc);
            float2 o0 = make_float2(acc[mt][nt][0] + bb.x, acc[mt][nt][1] + bb.y);
            float2 o1 = make_float2(acc[mt][nt][2] + bb.x, acc[mt][nt][3] + bb.y);
            if (RELU) {
                o0.x = fmaxf(o0.x, 0.f); o0.y = fmaxf(o0.y, 0.f);
                o1.x = fmaxf(o1.x, 0.f); o1.y = fmaxf(o1.y, 0.f);
            }
            if (HASRES) {
                float2 r0 = *(const float2*)(res + (size_t)mr * N + nc);
                float2 r1 = *(const float2*)(res + (size_t)(mr+8) * N + nc);
                o0.x += r0.x; o0.y += r0.y;
                o1.x += r1.x; o1.y += r1.y;
            }
            if (OUTHALF) {
                __half* Ch = (__half*)Cm;
                *(uint32_t*)(Ch + (size_t)mr     * N + nc) = f2h2(o0.x, o0.y);
                *(uint32_t*)(Ch + (size_t)(mr+8) * N + nc) = f2h2(o1.x, o1.y);
            } else {
                float* Cf = (float*)Cm;
                *(float2*)(Cf + (size_t)mr     * N + nc) = o0;
                *(float2*)(Cf + (size_t)(mr+8) * N + nc) = o1;
            }
        }
    }
}

// ---------------- fp16 flash attention, register softmax, 4-stage K/V ring --
// stage: K 64x72h (9216B) + V 64x72h (9216B) = 18432B; 4 stages = 73728B
#define ASTG   18432
#define AVOF   9216
#define ATT_SMEM_BYTES (4*ASTG)

__global__ __launch_bounds__(256, 2) void attn_kernel(
    const __half* __restrict__ qkv, __half* __restrict__ out)
{
    extern __shared__ char asmem[];
    int qt = (int)gridDim.x - 1 - (int)blockIdx.x;   // heavy tiles first
    int bh = blockIdx.y;
    int q0 = qt << 7;
    int bb = bh >> 4, hh = bh & 15;
    const __half* Qg = qkv + (size_t)(bb * T_) * QKVN + hh * D_;
    const __half* Kg = Qg + C_;
    const __half* Vg = Qg + 2*C_;
    int tid = threadIdx.x;
    int warp = tid >> 5, lane = tid & 31;
    int l16 = lane & 15, l2 = lane >> 4;
    int gid = lane >> 2, tig = lane & 3;
    int i0 = warp << 4;

    // K/V cp.async mapping (per thread): row cr, 16 halves at cc
    int cr = tid >> 2, cc = (tid & 3) << 4;
    uint32_t kdst[4], vdst[4];
    #pragma unroll
    for (int s = 0; s < 4; s++) {
        kdst[s] = su32(asmem + s*ASTG        + (cr*72 + cc)*2);
        vdst[s] = su32(asmem + s*ASTG + AVOF + (cr*72 + cc)*2);
    }

    // Q fragments, pre-scaled by 1/32 (power of two -> exact in fp16)
    unsigned qa[4][4];
    {
        const __half* q0p = Qg + (size_t)(q0 + i0 + gid) * QKVN;
        const __half* q1p = q0p + 8 * QKVN;
        const __half2 sc = __half2half2(__float2half(0.03125f));
        #pragma unroll
        for (int ks = 0; ks < 4; ks++) {
            int c = (ks<<4) + (tig<<1);
            __half2 w0 = __hmul2(*(const __half2*)(q0p + c),     sc);
            __half2 w1 = __hmul2(*(const __half2*)(q1p + c),     sc);
            __half2 w2 = __hmul2(*(const __half2*)(q0p + c + 8), sc);
            __half2 w3 = __hmul2(*(const __half2*)(q1p + c + 8), sc);
            qa[ks][0] = *(uint32_t*)&w0; qa[ks][1] = *(uint32_t*)&w1;
            qa[ks][2] = *(uint32_t*)&w2; qa[ks][3] = *(uint32_t*)&w3;
        }
    }

    float oacc[8][4] = {};
    float m0 = -1e30f, m1 = -1e30f, l0 = 0.f, l1 = 0.f;
    int r0g = q0 + i0 + gid, r1g = r0g + 8;

    int ktmax = 2*qt + 1;
    // prologue: prefetch tiles 0,1 (ktmax >= 1 always)
    #pragma unroll
    for (int p = 0; p < 2; p++) {
        const __half* kp = Kg + (size_t)((p<<6) + cr) * QKVN + cc;
        const __half* vp = Vg + (size_t)((p<<6) + cr) * QKVN + cc;
        CPA16(kdst[p], kp); CPA16(kdst[p] + 16, kp + 8);
        CPA16(vdst[p], vp); CPA16(vdst[p] + 16, vp + 8);
        CPA_COMMIT();
    }

    for (int kt = 0; kt <= ktmax; kt++) {
        int st = kt & 3;
        int k0 = kt << 6;
        if (kt + 2 <= ktmax) {
            int s = (kt + 2) & 3;
            const __half* kp = Kg + (size_t)(((kt+2)<<6) + cr) * QKVN + cc;
            const __half* vp = Vg + (size_t)(((kt+2)<<6) + cr) * QKVN + cc;
            CPA16(kdst[s], kp); CPA16(kdst[s] + 16, kp + 8);
            CPA16(vdst[s], vp); CPA16(vdst[s] + 16, vp + 8);
            CPA_COMMIT();
            CPA_WAIT(2);
        } else if (kt + 1 <= ktmax) {
            CPA_WAIT(1);
        } else {
            CPA_WAIT(0);
        }
        __syncthreads();

        const __half* Kh = (const __half*)(asmem + st*ASTG);
        const __half* Vh = (const __half*)(asmem + st*ASTG + AVOF);

        // S = Q K^T  -> sacc[nt] = S[r0g / r1g][k0 + nt*8 + tig*2 (+1)]
        float sacc[8][4] = {};
        #pragma unroll
        for (int ks = 0; ks < 4; ks++) {
            #pragma unroll
            for (int np = 0; np < 4; np++) {
                uint32_t kd = su32(Kh + ((np<<4) + l16)*72 + (ks<<4) + (l2<<3));
                uint32_t t0, t1, t2, t3;
                LDSM4(t0, t1, t2, t3, kd);
                unsigned b0[2] = {t0, t2}, b1[2] = {t1, t3};
                MMA_F16(sacc[2*np],   qa[ks], b0);
                MMA_F16(sacc[2*np+1], qa[ks], b1);
            }
        }

        // causal mask (diag tiles only)
        if (kt >= 2*qt) {
            #pragma unroll
            for (int nt = 0; nt < 8; nt++) {
                int jb = k0 + (nt<<3) + (tig<<1);
                if (jb     > r0g) sacc[nt][0] = -1e30f;
                if (jb + 1 > r0g) sacc[nt][1] = -1e30f;
                if (jb     > r1g) sacc[nt][2] = -1e30f;
                if (jb + 1 > r1g) sacc[nt][3] = -1e30f;
            }
        }

        // register-resident online softmax (rows r0g, r1g per thread-quad)
        {
            float mx0 = -1e30f, mx1 = -1e30f;
            #pragma unroll
            for (int nt = 0; nt < 8; nt++) {
                mx0 = fmaxf(mx0, fmaxf(sacc[nt][0], sacc[nt][1]));
                mx1 = fmaxf(mx1, fmaxf(sacc[nt][2], sacc[nt][3]));
            }
            mx0 = fmaxf(mx0, __shfl_xor_sync(0xffffffffu, mx0, 1));
            mx0 = fmaxf(mx0, __shfl_xor_sync(0xffffffffu, mx0, 2));
            mx1 = fmaxf(mx1, __shfl_xor_sync(0xffffffffu, mx1, 1));
            mx1 = fmaxf(mx1, __shfl_xor_sync(0xffffffffu, mx1, 2));
            float m0n = fmaxf(m0, mx0), m1n = fmaxf(m1, mx1);
            float al0 = __expf(m0 - m0n), al1 = __expf(m1 - m1n);
            float s0 = 0.f, s1 = 0.f;
            #pragma unroll
            for (int nt = 0; nt < 8; nt++) {
                sacc[nt][0] = __expf(sacc[nt][0] - m0n);
                sacc[nt][1] = __expf(sacc[nt][1] - m0n);
                sacc[nt][2] = __expf(sacc[nt][2] - m1n);
                sacc[nt][3] = __expf(sacc[nt][3] - m1n);
                s0 += sacc[nt][0] + sacc[nt][1];
                s1 += sacc[nt][2] + sacc[nt][3];
            }
            s0 += __shfl_xor_sync(0xffffffffu, s0, 1);
            s0 += __shfl_xor_sync(0xffffffffu, s0, 2);
            s1 += __shfl_xor_sync(0xffffffffu, s1, 1);
            s1 += __shfl_xor_sync(0xffffffffu, s1, 2);
            l0 = l0 * al0 + s0;  m0 = m0n;
            l1 = l1 * al1 + s1;  m1 = m1n;
            #pragma unroll
            for (int nt = 0; nt < 8; nt++) {
                oacc[nt][0] *= al0; oacc[nt][1] *= al0;
                oacc[nt][2] *= al1; oacc[nt][3] *= al1;
            }
        }

        // P @ V: pack P fragments straight from sacc registers
        #pragma unroll
        for (int ks = 0; ks < 4; ks++) {
            unsigned a[4];
            a[0] = f2h2(sacc[2*ks  ][0], sacc[2*ks  ][1]);  // row gid,   k ks*16+2tig
            a[1] = f2h2(sacc[2*ks  ][2], sacc[2*ks  ][3]);  // row gid+8
            a[2] = f2h2(sacc[2*ks+1][0], sacc[2*ks+1][1]);  // row gid,   k ks*16+8+2tig
            a[3] = f2h2(sacc[2*ks+1][2], sacc[2*ks+1][3]);  // row gid+8
            #pragma unroll
            for (int np = 0; np < 4; np++) {
                uint32_t vdx = su32(Vh + ((ks<<4) + l16)*72 + (np<<4) + (l2<<3));
                uint32_t t0, t1, t2, t3;
                LDSM4T(t0, t1, t2, t3, vdx);
                unsigned b0[2] = {t0, t1}, b1[2] = {t2, t3};
                MMA_F16(oacc[2*np],   a, b0);
                MMA_F16(oacc[2*np+1], a, b1);
            }
        }
    }

    // normalize + write half out[b, t, hh*64 + d]
    {
        float inv0 = 1.0f / l0;
        float inv1 = 1.0f / l1;
        __half* o0 = out + ((size_t)(bb * T_ + r0g)) * C_ + hh * D_ + (tig<<1);
        __half* o1 = o0 + 8 * C_;
        #pragma unroll
        for (int nt = 0; nt < 8; nt++) {
            *(uint32_t*)(o0 + (nt<<3)) = f2h2(oacc[nt][0]*inv0, oacc[nt][1]*inv0);
            *(uint32_t*)(o1 + (nt<<3)) = f2h2(oacc[nt][2]*inv1, oacc[nt][3]*inv1);
        }
    }
}

// ---------------- launch ----------------------------------------------------
extern "C" void kernel_launch(void* const* d_in, const int* in_sizes, int n_in,
                              void* d_out, int out_size)
{
    const float* x   = (const float*)d_in[0];
    const float* Wq  = (const float*)d_in[1];
    const float* Wk  = (const float*)d_in[2];
    const float* Wv  = (const float*)d_in[3];
    const float* Wo  = (const float*)d_in[4];
    const float* bo  = (const float*)d_in[5];
    const float* W1  = (const float*)d_in[6];
    const float* b1  = (const float*)d_in[7];
    const float* W2  = (const float*)d_in[8];
    const float* b2  = (const float*)d_in[9];
    const float* g1  = (const float*)d_in[10];
    const float* be1 = (const float*)d_in[11];
    const float* g2  = (const float*)d_in[12];
    const float* be2 = (const float*)d_in[13];
    float* out = (float*)d_out;

    __half *h, *wp, *qkv, *att, *h2, *ff, *woh, *w1h, *w2h;
    float *x1;
    cudaGetSymbolAddress((void**)&h,   hb_h);
    cudaGetSymbolAddress((void**)&wp,  hb_wp);
    cudaGetSymbolAddress((void**)&qkv, hb_qkv);
    cudaGetSymbolAddress((void**)&att, hb_att);
    cudaGetSymbolAddress((void**)&h2,  hb_h2);
    cudaGetSymbolAddress((void**)&ff,  hb_ff);
    cudaGetSymbolAddress((void**)&woh, hb_wo);
    cudaGetSymbolAddress((void**)&w1h, hb_w1);
    cudaGetSymbolAddress((void**)&w2h, hb_w2);
    cudaGetSymbolAddress((void**)&x1,  g_x1);

    cudaFuncSetAttribute(attn_kernel,
        cudaFuncAttributeMaxDynamicSharedMemorySize, ATT_SMEM_BYTES);
    cudaFuncSetAttribute(tgemm<0,0,0,1>,
        cudaFuncAttributeMaxDynamicSharedMemorySize, GT_SMEM);
    cudaFuncSetAttribute(tgemm<0,1,1,0>,
        cudaFuncAttributeMaxDynamicSharedMemorySize, GT_SMEM);
    cudaFuncSetAttribute(tgemm<1,0,1,1>,
        cudaFuncAttributeMaxDynamicSharedMemorySize, GT_SMEM);

    // 1) LN1 (half out)
    ln_kernel<<<M_, 256>>>(x, g1, be1, h);
    // 2) weight conversions (merged) + qkv repack
    repack_kernel<<<dim3((C_*C_)/256, 3), 256>>>(Wq, Wk, Wv, wp);
    wprep_kernel<<<(C_*C_ + 2*C_*F_)/1024, 256>>>(Wo, W1, W2, woh, w1h, w2h);
    // 3) fused QKV projection (half in/out)
    tgemm<0,0,0,1><<<dim3(QKVN/256, M_/128), 256, GT_SMEM>>>(h, wp, qkv, M_, QKVN, C_, nullptr, nullptr);
    // 4) causal flash attention (register softmax, 4-stage K/V ring)
    attn_kernel<<<dim3(T_/128, B_*H_), 256, ATT_SMEM_BYTES>>>(qkv, att);
    // 5) Wo projection + bias + residual (fp32 out)
    tgemm<0,1,1,0><<<dim3(C_/256, M_/128), 256, GT_SMEM>>>(att, woh, x1, M_, C_, C_, bo, x);
    // 6) LN2 (half out)
    ln_kernel<<<M_, 256>>>(x1, g2, be2, h2);
    // 7) FFN up + ReLU (half out)
    tgemm<1,0,1,1><<<dim3(F_/256, M_/128), 256, GT_SMEM>>>(h2, w1h, ff, M_, F_, C_, b1, nullptr);
    // 8) FFN down + bias + residual -> final fp32 output
    tgemm<0,1,1,0><<<dim3(C_/256, M_/128), 256, GT_SMEM>>>(ff, w2h, out, M_, C_, F_, b2, x1);
}

// round 11
// speedup vs baseline: 6.6560x; 1.0009x over previous
#include <cuda_runtime.h>
#include <cuda_fp16.h>
#include <cstdint>

#define B_ 2
#define T_ 2048
#define C_ 1024
#define H_ 16
#define D_ 64
#define F_ 4096
#define M_ (B_*T_)   // 4096 rows
#define QKVN 3072

// ---------------- scratch (device globals; no runtime allocation) ----------
__device__ __align__(16) __half hb_h  [M_*C_];    // ln1 out (half)
__device__ __align__(16) __half hb_wp [C_*QKVN];  // packed Wqkv (half)
__device__ __align__(16) __half hb_qkv[M_*QKVN];  // qkv activations (half)
__device__ __align__(16) __half hb_att[M_*C_];    // attn out (half)
__device__ __align__(16) __half hb_h2 [M_*C_];    // ln2 out (half)
__device__ __align__(16) __half hb_ff [M_*F_];    // ffn mid (half)
__device__ __align__(16) __half hb_wo [C_*C_];
__device__ __align__(16) __half hb_w1 [C_*F_];
__device__ __align__(16) __half hb_w2 [F_*C_];
__device__ __align__(16) float  g_x1  [M_*C_];    // attn residual out (fp32)

__device__ __forceinline__ uint32_t f2h2(float x, float y) {
    __half2 h = __floats2half2_rn(x, y);
    return *(uint32_t*)&h;
}
__device__ __forceinline__ uint32_t su32(const void* p) {
    return (uint32_t)__cvta_generic_to_shared(p);
}

#define MMA_F16(acc, a, b) \
    asm volatile( \
        "mma.sync.aligned.m16n8k16.row.col.f32.f16.f16.f32 " \
        "{%0,%1,%2,%3},{%4,%5,%6,%7},{%8,%9},{%0,%1,%2,%3};" \
        : "+f"((acc)[0]), "+f"((acc)[1]), "+f"((acc)[2]), "+f"((acc)[3]) \
        : "r"((a)[0]), "r"((a)[1]), "r"((a)[2]), "r"((a)[3]), \
          "r"((b)[0]), "r"((b)[1]))

#define LDSM4(r0, r1, r2, r3, addr) \
    asm volatile("ldmatrix.sync.aligned.m8n8.x4.shared.b16 {%0,%1,%2,%3}, [%4];" \
        : "=r"(r0), "=r"(r1), "=r"(r2), "=r"(r3) : "r"(addr))
#define LDSM4T(r0, r1, r2, r3, addr) \
    asm volatile("ldmatrix.sync.aligned.m8n8.x4.trans.shared.b16 {%0,%1,%2,%3}, [%4];" \
        : "=r"(r0), "=r"(r1), "=r"(r2), "=r"(r3) : "r"(addr))

#define CPA16(dst, src) \
    asm volatile("cp.async.cg.shared.global [%0], [%1], 16;" :: "r"(dst), "l"(src))
#define CPA_COMMIT() asm volatile("cp.async.commit_group;" ::: "memory")
#define CPA_WAIT(n)  asm volatile("cp.async.wait_group %0;" :: "n"(n) : "memory")

// ---------------- LayerNorm: warp-per-row, fp32 in, half out ----------------
__global__ __launch_bounds__(256) void ln_kernel(
    const float* __restrict__ x, const float* __restrict__ g,
    const float* __restrict__ b, __half* __restrict__ out)
{
    int warp = threadIdx.x >> 5, lane = threadIdx.x & 31;
    int row = (blockIdx.x << 3) + warp;
    const float4* xp = (const float4*)(x + (size_t)row * C_);
    float4 v[8];
    float s = 0.f, s2 = 0.f;
    #pragma unroll
    for (int i = 0; i < 8; i++) {
        v[i] = xp[lane + (i << 5)];
        s  += v[i].x + v[i].y + v[i].z + v[i].w;
        s2 += v[i].x*v[i].x + v[i].y*v[i].y + v[i].z*v[i].z + v[i].w*v[i].w;
    }
    #pragma unroll
    for (int o = 16; o; o >>= 1) {
        s  += __shfl_xor_sync(0xffffffffu, s,  o);
        s2 += __shfl_xor_sync(0xffffffffu, s2, o);
    }
    float mean = s * (1.0f/C_);
    float var  = s2 * (1.0f/C_) - mean*mean;
    float rstd = rsqrtf(var + 1e-5f);
    const float4* gp = (const float4*)g;
    const float4* bp = (const float4*)b;
    uint2* op = (uint2*)(out + (size_t)row * C_);
    #pragma unroll
    for (int i = 0; i < 8; i++) {
        float4 gv = gp[lane + (i << 5)];
        float4 bv = bp[lane + (i << 5)];
        uint2 w;
        w.x = f2h2((v[i].x-mean)*rstd*gv.x + bv.x, (v[i].y-mean)*rstd*gv.y + bv.y);
        w.y = f2h2((v[i].z-mean)*rstd*gv.z + bv.z, (v[i].w-mean)*rstd*gv.w + bv.w);
        op[lane + (i << 5)] = w;
    }
}

// ---------------- merged weight prep: Wo/W1/W2 fp32 -> fp16 ------------------
__global__ __launch_bounds__(256) void wprep_kernel(
    const float* __restrict__ Wo, const float* __restrict__ W1,
    const float* __restrict__ W2, __half* __restrict__ woh,
    __half* __restrict__ w1h, __half* __restrict__ w2h)
{
    size_t i = ((size_t)blockIdx.x*256 + threadIdx.x) << 2;
    const float* src; __half* dst; size_t off;
    const size_t S0 = (size_t)C_*C_, S1 = S0 + (size_t)C_*F_;
    if (i < S0)      { src = Wo; dst = woh; off = i; }
    else if (i < S1) { src = W1; dst = w1h; off = i - S0; }
    else             { src = W2; dst = w2h; off = i - S1; }
    float4 v = *(const float4*)(src + off);
    uint2 w;
    w.x = f2h2(v.x, v.y); w.y = f2h2(v.z, v.w);
    *(uint2*)(dst + off) = w;
}

// ---------------- repack Wq/Wk/Wv [H][C][D] -> half [C][3*C] ----------------
__global__ __launch_bounds__(256) void repack_kernel(
    const float* __restrict__ Wq, const float* __restrict__ Wk,
    const float* __restrict__ Wv, __half* __restrict__ Wp)
{
    int idx = blockIdx.x*256 + threadIdx.x;        // over C*C
    int which = blockIdx.y;
    const float* W = (which==0) ? Wq : (which==1) ? Wk : Wv;
    int c = idx >> 10, n = idx & 1023;
    int h = n >> 6, d = n & 63;
    Wp[(size_t)c*QKVN + which*C_ + n] = __float2half_rn(W[((size_t)h*C_ + c)*D_ + d]);
}

// ---------------- fp16 GEMM: 128x256 tile, 8-stage ring, barrier / 2 tiles --
#define GSTAGE 27136
#define GBOF   10240
#define GT_SMEM (8*GSTAGE)    // 217088 B

template<int RELU, int HASRES, int HASBIAS, int OUTHALF>
__global__ __launch_bounds__(256, 1) void tgemm(
    const __half* __restrict__ A, const __half* __restrict__ Bm,
    void* __restrict__ Cm, int M, int N, int K,
    const float* __restrict__ bias, const float* __restrict__ res)
{
    extern __shared__ char dsm[];
    int tid = threadIdx.x;
    int m0 = blockIdx.y << 7, n0 = blockIdx.x << 8;
    int warp = tid >> 5, lane = tid & 31;
    int l16 = lane & 15, l2 = lane >> 4;
    int gid = lane >> 2, tig = lane & 3;
    int wm = (warp & 1) << 6;
    int wn = (warp >> 1) << 6;

    float acc[4][8][4] = {};

    int ra = tid >> 1, ca = (tid & 1) << 4;
    int rb = tid >> 3, tb = (tid & 7) << 3;
    const __half* Ap = A  + (size_t)(m0 + ra) * K + ca;
    const __half* Bp = Bm + (size_t)rb * N + n0 + tb;
    uint32_t aoff = (uint32_t)((ra*40 + ca)*2);
    uint32_t boff = (uint32_t)(GBOF + (rb*264 + tb)*2);
    uint32_t sbase = su32(dsm);

    int KT = K >> 5;
    int NB = KT >> 1;
    // prologue: tiles 0..3 (batches 0,1)
    #pragma unroll
    for (int p = 0; p < 4; p++) {
        const __half* ap = Ap + (p<<5);
        const __half* bp = Bp + (size_t)(p<<5) * N;
        uint32_t sb = sbase + p*GSTAGE;
        CPA16(sb + aoff,      ap);
        CPA16(sb + aoff + 16, ap + 8);
        #pragma unroll
        for (int u = 0; u < 4; u++)
            CPA16(sb + boff + (u<<7), bp + (u<<6));
        CPA_COMMIT();
    }

    for (int b = 0; b < NB; b++) {
        int t0 = b << 1;
        if (b + 2 < NB) {
            #pragma unroll
            for (int q = 0; q < 2; q++) {
                int t = t0 + 4 + q;
                const __half* ap = Ap + (t<<5);
                const __half* bp = Bp + (size_t)(t<<5) * N;
                uint32_t sb = sbase + (t & 7)*GSTAGE;
                CPA16(sb + aoff,      ap);
                CPA16(sb + aoff + 16, ap + 8);
                #pragma unroll
                for (int u = 0; u < 4; u++)
                    CPA16(sb + boff + (u<<7), bp + (u<<6));
                CPA_COMMIT();
            }
            CPA_WAIT(4);
        } else if (b + 1 < NB) {
            CPA_WAIT(2);
        } else {
            CPA_WAIT(0);
        }
        __syncthreads();

        // compute tiles t0, t0+1
        #pragma unroll
        for (int q = 0; q < 2; q++) {
            const __half* Ah = (const __half*)(dsm + ((t0 + q) & 7)*GSTAGE);
            const __half* Bh = (const __half*)(dsm + ((t0 + q) & 7)*GSTAGE + GBOF);
            #pragma unroll
            for (int ks = 0; ks < 2; ks++) {
                unsigned a[4][4], bfr[8][2];
                #pragma unroll
                for (int mt = 0; mt < 4; mt++) {
                    uint32_t ad = su32(Ah + (wm + (mt<<4) + l16)*40 + (ks<<4) + (l2<<3));
                    LDSM4(a[mt][0], a[mt][1], a[mt][2], a[mt][3], ad);
                }
                #pragma unroll
                for (int np = 0; np < 4; np++) {
                    uint32_t bd = su32(Bh + ((ks<<4) + l16)*264 + wn + (np<<4) + (l2<<3));
                    uint32_t r0, r1, r2, r3;
                    LDSM4T(r0, r1, r2, r3, bd);
                    bfr[2*np][0] = r0; bfr[2*np][1] = r1;
                    bfr[2*np+1][0] = r2; bfr[2*np+1][1] = r3;
                }
                #pragma unroll
                for (int mt = 0; mt < 4; mt++)
                    #pragma unroll
                    for (int nt = 0; nt < 8; nt++)
                        MMA_F16(acc[mt][nt], a[mt], bfr[nt]);
            }
        }
    }

    #pragma unroll
    for (int mt = 0; mt < 4; mt++) {
        int mr = m0 + wm + (mt<<4) + gid;
        #pragma unroll
        for (int nt = 0; nt < 8; nt++) {
            int nc = n0 + wn + (nt<<3) + (tig<<1);
            float2 bb = make_float2(0.f, 0.f);
            if (HASBIAS) bb = *(const float2*)(bias + nc);
            float2 o0 = make_float2(acc[mt][nt][0] + bb.x, acc[mt][nt][1] + bb.y);
            float2 o1 = make_float2(acc[mt][nt][2] + bb.x, acc[mt][nt][3] + bb.y);
            if (RELU) {
                o0.x = fmaxf(o0.x, 0.f); o0.y = fmaxf(o0.y, 0.f);
                o1.x = fmaxf(o1.x, 0.f); o1.y = fmaxf(o1.y, 0.f);
            }
            if (HASRES) {
                float2 r0 = *(const float2*)(res + (size_t)mr * N + nc);
                float2 r1 = *(const float2*)(res + (size_t)(mr+8) * N + nc);
                o0.x += r0.x; o0.y += r0.y;
                o1.x += r1.x; o1.y += r1.y;
            }
            if (OUTHALF) {
                __half* Ch = (__half*)Cm;
                *(uint32_t*)(Ch + (size_t)mr     * N + nc) = f2h2(o0.x, o0.y);
                *(uint32_t*)(Ch + (size_t)(mr+8) * N + nc) = f2h2(o1.x, o1.y);
            } else {
                float* Cf = (float*)Cm;
                *(float2*)(Cf + (size_t)mr     * N + nc) = o0;
                *(float2*)(Cf + (size_t)(mr+8) * N + nc) = o1;
            }
        }
    }
}

// ---------------- fp16 flash attention, register softmax, 4-stage K/V ring --
#define ASTG   18432
#define AVOF   9216
#define ATT_SMEM_BYTES (4*ASTG)

__global__ __launch_bounds__(256, 2) void attn_kernel(
    const __half* __restrict__ qkv, __half* __restrict__ out)
{
    extern __shared__ char asmem[];
    int qt = (int)gridDim.x - 1 - (int)blockIdx.x;   // heavy tiles first
    int bh = blockIdx.y;
    int q0 = qt << 7;
    int bb = bh >> 4, hh = bh & 15;
    const __half* Qg = qkv + (size_t)(bb * T_) * QKVN + hh * D_;
    const __half* Kg = Qg + C_;
    const __half* Vg = Qg + 2*C_;
    int tid = threadIdx.x;
    int warp = tid >> 5, lane = tid & 31;
    int l16 = lane & 15, l2 = lane >> 4;
    int gid = lane >> 2, tig = lane & 3;
    int i0 = warp << 4;

    int cr = tid >> 2, cc = (tid & 3) << 4;
    uint32_t kdst[4], vdst[4];
    #pragma unroll
    for (int s = 0; s < 4; s++) {
        kdst[s] = su32(asmem + s*ASTG        + (cr*72 + cc)*2);
        vdst[s] = su32(asmem + s*ASTG + AVOF + (cr*72 + cc)*2);
    }

    unsigned qa[4][4];
    {
        const __half* q0p = Qg + (size_t)(q0 + i0 + gid) * QKVN;
        const __half* q1p = q0p + 8 * QKVN;
        const __half2 sc = __half2half2(__float2half(0.03125f));
        #pragma unroll
        for (int ks = 0; ks < 4; ks++) {
            int c = (ks<<4) + (tig<<1);
            __half2 w0 = __hmul2(*(const __half2*)(q0p + c),     sc);
            __half2 w1 = __hmul2(*(const __half2*)(q1p + c),     sc);
            __half2 w2 = __hmul2(*(const __half2*)(q0p + c + 8), sc);
            __half2 w3 = __hmul2(*(const __half2*)(q1p + c + 8), sc);
            qa[ks][0] = *(uint32_t*)&w0; qa[ks][1] = *(uint32_t*)&w1;
            qa[ks][2] = *(uint32_t*)&w2; qa[ks][3] = *(uint32_t*)&w3;
        }
    }

    float oacc[8][4] = {};
    float m0 = -1e30f, m1 = -1e30f, l0 = 0.f, l1 = 0.f;
    int r0g = q0 + i0 + gid, r1g = r0g + 8;

    int ktmax = 2*qt + 1;
    #pragma unroll
    for (int p = 0; p < 2; p++) {
        const __half* kp = Kg + (size_t)((p<<6) + cr) * QKVN + cc;
        const __half* vp = Vg + (size_t)((p<<6) + cr) * QKVN + cc;
        CPA16(kdst[p], kp); CPA16(kdst[p] + 16, kp + 8);
        CPA16(vdst[p], vp); CPA16(vdst[p] + 16, vp + 8);
        CPA_COMMIT();
    }

    for (int kt = 0; kt <= ktmax; kt++) {
        int st = kt & 3;
        int k0 = kt << 6;
        if (kt + 2 <= ktmax) {
            int s = (kt + 2) & 3;
            const __half* kp = Kg + (size_t)(((kt+2)<<6) + cr) * QKVN + cc;
            const __half* vp = Vg + (size_t)(((kt+2)<<6) + cr) * QKVN + cc;
            CPA16(kdst[s], kp); CPA16(kdst[s] + 16, kp + 8);
            CPA16(vdst[s], vp); CPA16(vdst[s] + 16, vp + 8);
            CPA_COMMIT();
            CPA_WAIT(2);
        } else if (kt + 1 <= ktmax) {
            CPA_WAIT(1);
        } else {
            CPA_WAIT(0);
        }
        __syncthreads();

        const __half* Kh = (const __half*)(asmem + st*ASTG);
        const __half* Vh = (const __half*)(asmem + st*ASTG + AVOF);

        float sacc[8][4] = {};
        #pragma unroll
        for (int ks = 0; ks < 4; ks++) {
            #pragma unroll
            for (int np = 0; np < 4; np++) {
                uint32_t kd = su32(Kh + ((np<<4) + l16)*72 + (ks<<4) + (l2<<3));
                uint32_t t0, t1, t2, t3;
                LDSM4(t0, t1, t2, t3, kd);
                unsigned b0[2] = {t0, t2}, b1[2] = {t1, t3};
                MMA_F16(sacc[2*np],   qa[ks], b0);
                MMA_F16(sacc[2*np+1], qa[ks], b1);
            }
        }

        if (kt >= 2*qt) {
            #pragma unroll
            for (int nt = 0; nt < 8; nt++) {
                int jb = k0 + (nt<<3) + (tig<<1);
                if (jb     > r0g) sacc[nt][0] = -1e30f;
                if (jb + 1 > r0g) sacc[nt][1] = -1e30f;
                if (jb     > r1g) sacc[nt][2] = -1e30f;
                if (jb + 1 > r1g) sacc[nt][3] = -1e30f;
            }
        }

        {
            float mx0 = -1e30f, mx1 = -1e30f;
            #pragma unroll
            for (int nt = 0; nt < 8; nt++) {
                mx0 = fmaxf(mx0, fmaxf(sacc[nt][0], sacc[nt][1]));
                mx1 = fmaxf(mx1, fmaxf(sacc[nt][2], sacc[nt][3]));
            }
            mx0 = fmaxf(mx0, __shfl_xor_sync(0xffffffffu, mx0, 1));
            mx0 = fmaxf(mx0, __shfl_xor_sync(0xffffffffu, mx0, 2));
            mx1 = fmaxf(mx1, __shfl_xor_sync(0xffffffffu, mx1, 1));
            mx1 = fmaxf(mx1, __shfl_xor_sync(0xffffffffu, mx1, 2));
            float m0n = fmaxf(m0, mx0), m1n = fmaxf(m1, mx1);
            float al0 = __expf(m0 - m0n), al1 = __expf(m1 - m1n);
            float s0 = 0.f, s1 = 0.f;
            #pragma unroll
            for (int nt = 0; nt < 8; nt++) {
                sacc[nt][0] = __expf(sacc[nt][0] - m0n);
                sacc[nt][1] = __expf(sacc[nt][1] - m0n);
                sacc[nt][2] = __expf(sacc[nt][2] - m1n);
                sacc[nt][3] = __expf(sacc[nt][3] - m1n);
                s0 += sacc[nt][0] + sacc[nt][1];
                s1 += sacc[nt][2] + sacc[nt][3];
            }
            s0 += __shfl_xor_sync(0xffffffffu, s0, 1);
            s0 += __shfl_xor_sync(0xffffffffu, s0, 2);
            s1 += __shfl_xor_sync(0xffffffffu, s1, 1);
            s1 += __shfl_xor_sync(0xffffffffu, s1, 2);
            l0 = l0 * al0 + s0;  m0 = m0n;
            l1 = l1 * al1 + s1;  m1 = m1n;
            #pragma unroll
            for (int nt = 0; nt < 8; nt++) {
                oacc[nt][0] *= al0; oacc[nt][1] *= al0;
                oacc[nt][2] *= al1; oacc[nt][3] *= al1;
            }
        }

        #pragma unroll
        for (int ks = 0; ks < 4; ks++) {
            unsigned a[4];
            a[0] = f2h2(sacc[2*ks  ][0], sacc[2*ks  ][1]);
            a[1] = f2h2(sacc[2*ks  ][2], sacc[2*ks  ][3]);
            a[2] = f2h2(sacc[2*ks+1][0], sacc[2*ks+1][1]);
            a[3] = f2h2(sacc[2*ks+1][2], sacc[2*ks+1][3]);
            #pragma unroll
            for (int np = 0; np < 4; np++) {
                uint32_t vdx = su32(Vh + ((ks<<4) + l16)*72 + (np<<4) + (l2<<3));
                uint32_t t0, t1, t2, t3;
                LDSM4T(t0, t1, t2, t3, vdx);
                unsigned b0[2] = {t0, t1}, b1[2] = {t2, t3};
                MMA_F16(oacc[2*np],   a, b0);
                MMA_F16(oacc[2*np+1], a, b1);
            }
        }
    }

    {
        float inv0 = 1.0f / l0;
        float inv1 = 1.0f / l1;
        __half* o0 = out + ((size_t)(bb * T_ + r0g)) * C_ + hh * D_ + (tig<<1);
        __half* o1 = o0 + 8 * C_;
        #pragma unroll
        for (int nt = 0; nt < 8; nt++) {
            *(uint32_t*)(o0 + (nt<<3)) = f2h2(oacc[nt][0]*inv0, oacc[nt][1]*inv0);
            *(uint32_t*)(o1 + (nt<<3)) = f2h2(oacc[nt][2]*inv1, oacc[nt][3]*inv1);
        }
    }
}

// ---------------- launch ----------------------------------------------------
extern "C" void kernel_launch(void* const* d_in, const int* in_sizes, int n_in,
                              void* d_out, int out_size)
{
    const float* x   = (const float*)d_in[0];
    const float* Wq  = (const float*)d_in[1];
    const float* Wk  = (const float*)d_in[2];
    const float* Wv  = (const float*)d_in[3];
    const float* Wo  = (const float*)d_in[4];
    const float* bo  = (const float*)d_in[5];
    const float* W1  = (const float*)d_in[6];
    const float* b1  = (const float*)d_in[7];
    const float* W2  = (const float*)d_in[8];
    const float* b2  = (const float*)d_in[9];
    const float* g1  = (const float*)d_in[10];
    const float* be1 = (const float*)d_in[11];
    const float* g2  = (const float*)d_in[12];
    const float* be2 = (const float*)d_in[13];
    float* out = (float*)d_out;

    __half *h, *wp, *qkv, *att, *h2, *ff, *woh, *w1h, *w2h;
    float *x1;
    cudaGetSymbolAddress((void**)&h,   hb_h);
    cudaGetSymbolAddress((void**)&wp,  hb_wp);
    cudaGetSymbolAddress((void**)&qkv, hb_qkv);
    cudaGetSymbolAddress((void**)&att, hb_att);
    cudaGetSymbolAddress((void**)&h2,  hb_h2);
    cudaGetSymbolAddress((void**)&ff,  hb_ff);
    cudaGetSymbolAddress((void**)&woh, hb_wo);
    cudaGetSymbolAddress((void**)&w1h, hb_w1);
    cudaGetSymbolAddress((void**)&w2h, hb_w2);
    cudaGetSymbolAddress((void**)&x1,  g_x1);

    cudaFuncSetAttribute(attn_kernel,
        cudaFuncAttributeMaxDynamicSharedMemorySize, ATT_SMEM_BYTES);
    cudaFuncSetAttribute(tgemm<0,0,0,1>,
        cudaFuncAttributeMaxDynamicSharedMemorySize, GT_SMEM);
    cudaFuncSetAttribute(tgemm<0,1,1,0>,
        cudaFuncAttributeMaxDynamicSharedMemorySize, GT_SMEM);
    cudaFuncSetAttribute(tgemm<1,0,1,1>,
        cudaFuncAttributeMaxDynamicSharedMemorySize, GT_SMEM);

    // 1) LN1 (half out)
    ln_kernel<<<M_/8, 256>>>(x, g1, be1, h);
    // 2) weight conversions (merged) + qkv repack
    repack_kernel<<<dim3((C_*C_)/256, 3), 256>>>(Wq, Wk, Wv, wp);
    wprep_kernel<<<(C_*C_ + 2*C_*F_)/1024, 256>>>(Wo, W1, W2, woh, w1h, w2h);
    // 3) fused QKV projection (half in/out)
    tgemm<0,0,0,1><<<dim3(QKVN/256, M_/128), 256, GT_SMEM>>>(h, wp, qkv, M_, QKVN, C_, nullptr, nullptr);
    // 4) causal flash attention (register softmax, 4-stage K/V ring)
    attn_kernel<<<dim3(T_/128, B_*H_), 256, ATT_SMEM_BYTES>>>(qkv, att);
    // 5) Wo projection + bias + residual (fp32 out)
    tgemm<0,1,1,0><<<dim3(C_/256, M_/128), 256, GT_SMEM>>>(att, woh, x1, M_, C_, C_, bo, x);
    // 6) LN2 (half out)
    ln_kernel<<<M_/8, 256>>>(x1, g2, be2, h2);
    // 7) FFN up + ReLU (half out)
    tgemm<1,0,1,1><<<dim3(F_/256, M_/128), 256, GT_SMEM>>>(h2, w1h, ff, M_, F_, C_, b1, nullptr);
    // 8) FFN down + bias + residual -> final fp32 output
    tgemm<0,1,1,0><<<dim3(C_/256, M_/128), 256, GT_SMEM>>>(ff, w2h, out, M_, C_, F_, b2, x1);
}

// round 12
// speedup vs baseline: 7.0907x; 1.0653x over previous
#include <cuda_runtime.h>
#include <cuda_fp16.h>
#include <cstdint>

#define B_ 2
#define T_ 2048
#define C_ 1024
#define H_ 16
#define D_ 64
#define F_ 4096
#define M_ (B_*T_)   // 4096 rows
#define QKVN 3072

// ---------------- scratch (device globals; no runtime allocation) ----------
__device__ __align__(16) __half hb_h  [M_*C_];    // ln1 out (half)
__device__ __align__(16) __half hb_wp [C_*QKVN];  // packed Wqkv (half)
__device__ __align__(16) __half hb_qkv[M_*QKVN];  // qkv activations (half)
__device__ __align__(16) __half hb_att[M_*C_];    // attn out (half)
__device__ __align__(16) __half hb_h2 [M_*C_];    // ln2 out (half)
__device__ __align__(16) __half hb_ff [M_*F_];    // ffn mid (half)
__device__ __align__(16) __half hb_wo [C_*C_];
__device__ __align__(16) __half hb_w1 [C_*F_];
__device__ __align__(16) __half hb_w2 [F_*C_];
__device__ __align__(16) float  g_x1  [M_*C_];    // attn residual out (fp32)

__device__ __forceinline__ uint32_t f2h2(float x, float y) {
    __half2 h = __floats2half2_rn(x, y);
    return *(uint32_t*)&h;
}
__device__ __forceinline__ uint32_t su32(const void* p) {
    return (uint32_t)__cvta_generic_to_shared(p);
}

#define MMA_F16(acc, a, b) \
    asm volatile( \
        "mma.sync.aligned.m16n8k16.row.col.f32.f16.f16.f32 " \
        "{%0,%1,%2,%3},{%4,%5,%6,%7},{%8,%9},{%0,%1,%2,%3};" \
        : "+f"((acc)[0]), "+f"((acc)[1]), "+f"((acc)[2]), "+f"((acc)[3]) \
        : "r"((a)[0]), "r"((a)[1]), "r"((a)[2]), "r"((a)[3]), \
          "r"((b)[0]), "r"((b)[1]))

#define LDSM4(r0, r1, r2, r3, addr) \
    asm volatile("ldmatrix.sync.aligned.m8n8.x4.shared.b16 {%0,%1,%2,%3}, [%4];" \
        : "=r"(r0), "=r"(r1), "=r"(r2), "=r"(r3) : "r"(addr))
#define LDSM4T(r0, r1, r2, r3, addr) \
    asm volatile("ldmatrix.sync.aligned.m8n8.x4.trans.shared.b16 {%0,%1,%2,%3}, [%4];" \
        : "=r"(r0), "=r"(r1), "=r"(r2), "=r"(r3) : "r"(addr))

#define CPA16(dst, src) \
    asm volatile("cp.async.cg.shared.global [%0], [%1], 16;" :: "r"(dst), "l"(src))
#define CPA_COMMIT() asm volatile("cp.async.commit_group;" ::: "memory")
#define CPA_WAIT(n)  asm volatile("cp.async.wait_group %0;" :: "n"(n) : "memory")

// ---------------- LayerNorm: warp-per-row, fp32 in, half out ----------------
__global__ __launch_bounds__(256) void ln_kernel(
    const float* __restrict__ x, const float* __restrict__ g,
    const float* __restrict__ b, __half* __restrict__ out)
{
    int warp = threadIdx.x >> 5, lane = threadIdx.x & 31;
    int row = (blockIdx.x << 3) + warp;
    const float4* xp = (const float4*)(x + (size_t)row * C_);
    float4 v[8];
    float s = 0.f, s2 = 0.f;
    #pragma unroll
    for (int i = 0; i < 8; i++) {
        v[i] = xp[lane + (i << 5)];
        s  += v[i].x + v[i].y + v[i].z + v[i].w;
        s2 += v[i].x*v[i].x + v[i].y*v[i].y + v[i].z*v[i].z + v[i].w*v[i].w;
    }
    #pragma unroll
    for (int o = 16; o; o >>= 1) {
        s  += __shfl_xor_sync(0xffffffffu, s,  o);
        s2 += __shfl_xor_sync(0xffffffffu, s2, o);
    }
    float mean = s * (1.0f/C_);
    float var  = s2 * (1.0f/C_) - mean*mean;
    float rstd = rsqrtf(var + 1e-5f);
    const float4* gp = (const float4*)g;
    const float4* bp = (const float4*)b;
    uint2* op = (uint2*)(out + (size_t)row * C_);
    #pragma unroll
    for (int i = 0; i < 8; i++) {
        float4 gv = gp[lane + (i << 5)];
        float4 bv = bp[lane + (i << 5)];
        uint2 w;
        w.x = f2h2((v[i].x-mean)*rstd*gv.x + bv.x, (v[i].y-mean)*rstd*gv.y + bv.y);
        w.y = f2h2((v[i].z-mean)*rstd*gv.z + bv.z, (v[i].w-mean)*rstd*gv.w + bv.w);
        op[lane + (i << 5)] = w;
    }
}

// ---------------- merged weight prep: Wo/W1/W2 fp32 -> fp16 ------------------
__global__ __launch_bounds__(256) void wprep_kernel(
    const float* __restrict__ Wo, const float* __restrict__ W1,
    const float* __restrict__ W2, __half* __restrict__ woh,
    __half* __restrict__ w1h, __half* __restrict__ w2h)
{
    size_t i = ((size_t)blockIdx.x*256 + threadIdx.x) << 2;
    const float* src; __half* dst; size_t off;
    const size_t S0 = (size_t)C_*C_, S1 = S0 + (size_t)C_*F_;
    if (i < S0)      { src = Wo; dst = woh; off = i; }
    else if (i < S1) { src = W1; dst = w1h; off = i - S0; }
    else             { src = W2; dst = w2h; off = i - S1; }
    float4 v = *(const float4*)(src + off);
    uint2 w;
    w.x = f2h2(v.x, v.y); w.y = f2h2(v.z, v.w);
    *(uint2*)(dst + off) = w;
}

// ---------------- repack Wq/Wk/Wv [H][C][D] -> half [C][3*C] ----------------
__global__ __launch_bounds__(256) void repack_kernel(
    const float* __restrict__ Wq, const float* __restrict__ Wk,
    const float* __restrict__ Wv, __half* __restrict__ Wp)
{
    int idx = blockIdx.x*256 + threadIdx.x;        // over C*C
    int which = blockIdx.y;
    const float* W = (which==0) ? Wq : (which==1) ? Wk : Wv;
    int c = idx >> 10, n = idx & 1023;
    int h = n >> 6, d = n & 63;
    Wp[(size_t)c*QKVN + which*C_ + n] = __float2half_rn(W[((size_t)h*C_ + c)*D_ + d]);
}

// ---------------- fp16 GEMM: 128x256 tile, 512 thr (16 warps), 8-stage ring -
#define GSTAGE 27136
#define GBOF   10240
#define GT_SMEM (8*GSTAGE)    // 217088 B

template<int RELU, int HASRES, int HASBIAS, int OUTHALF>
__global__ __launch_bounds__(512, 1) void tgemm(
    const __half* __restrict__ A, const __half* __restrict__ Bm,
    void* __restrict__ Cm, int M, int N, int K,
    const float* __restrict__ bias, const float* __restrict__ res)
{
    extern __shared__ char dsm[];
    int tid = threadIdx.x;
    int m0 = blockIdx.y << 7, n0 = blockIdx.x << 8;
    int warp = tid >> 5, lane = tid & 31;
    int l16 = lane & 15, l2 = lane >> 4;
    int gid = lane >> 2, tig = lane & 3;
    int wm = (warp & 3) << 5;        // 4 m-strips of 32 rows
    int wn = (warp >> 2) << 6;       // 4 n-strips of 64 cols

    float acc[2][8][4] = {};

    // cp.async maps (512 threads)
    int ra = tid >> 2, ca = (tid & 3) << 3;    // A: row 0..127, 8-half col base
    int rb = tid >> 4, nb = (tid & 15) << 4;   // B: k-row 0..31, 16-half col base
    const __half* Ap = A  + (size_t)(m0 + ra) * K + ca;
    const __half* Bp = Bm + (size_t)rb * N + n0 + nb;
    uint32_t aoff = (uint32_t)((ra*40 + ca)*2);
    uint32_t boff = (uint32_t)(GBOF + (rb*264 + nb)*2);
    uint32_t sbase = su32(dsm);

    int KT = K >> 5;
    int NB = KT >> 1;
    // prologue: tiles 0..3
    #pragma unroll
    for (int p = 0; p < 4; p++) {
        const __half* ap = Ap + (p<<5);
        const __half* bp = Bp + (size_t)(p<<5) * N;
        uint32_t sb = sbase + p*GSTAGE;
        CPA16(sb + aoff, ap);
        CPA16(sb + boff,      bp);
        CPA16(sb + boff + 16, bp + 8);
        CPA_COMMIT();
    }

    for (int b = 0; b < NB; b++) {
        int t0 = b << 1;
        if (b + 2 < NB) {
            #pragma unroll
            for (int q = 0; q < 2; q++) {
                int t = t0 + 4 + q;
                const __half* ap = Ap + (t<<5);
                const __half* bp = Bp + (size_t)(t<<5) * N;
                uint32_t sb = sbase + (t & 7)*GSTAGE;
                CPA16(sb + aoff, ap);
                CPA16(sb + boff,      bp);
                CPA16(sb + boff + 16, bp + 8);
                CPA_COMMIT();
            }
            CPA_WAIT(4);
        } else if (b + 1 < NB) {
            CPA_WAIT(2);
        } else {
            CPA_WAIT(0);
        }
        __syncthreads();

        // compute tiles t0, t0+1
        #pragma unroll
        for (int q = 0; q < 2; q++) {
            const __half* Ah = (const __half*)(dsm + ((t0 + q) & 7)*GSTAGE);
            const __half* Bh = (const __half*)(dsm + ((t0 + q) & 7)*GSTAGE + GBOF);
            #pragma unroll
            for (int ks = 0; ks < 2; ks++) {
                unsigned a[2][4], bfr[8][2];
                #pragma unroll
                for (int mt = 0; mt < 2; mt++) {
                    uint32_t ad = su32(Ah + (wm + (mt<<4) + l16)*40 + (ks<<4) + (l2<<3));
                    LDSM4(a[mt][0], a[mt][1], a[mt][2], a[mt][3], ad);
                }
                #pragma unroll
                for (int np = 0; np < 4; np++) {
                    uint32_t bd = su32(Bh + ((ks<<4) + l16)*264 + wn + (np<<4) + (l2<<3));
                    uint32_t r0, r1, r2, r3;
                    LDSM4T(r0, r1, r2, r3, bd);
                    bfr[2*np][0] = r0; bfr[2*np][1] = r1;
                    bfr[2*np+1][0] = r2; bfr[2*np+1][1] = r3;
                }
                #pragma unroll
                for (int mt = 0; mt < 2; mt++)
                    #pragma unroll
                    for (int nt = 0; nt < 8; nt++)
                        MMA_F16(acc[mt][nt], a[mt], bfr[nt]);
            }
        }
    }

    #pragma unroll
    for (int mt = 0; mt < 2; mt++) {
        int mr = m0 + wm + (mt<<4) + gid;
        #pragma unroll
        for (int nt = 0; nt < 8; nt++) {
            int nc = n0 + wn + (nt<<3) + (tig<<1);
            float2 bb = make_float2(0.f, 0.f);
            if (HASBIAS) bb = *(const float2*)(bias + nc);
            float2 o0 = make_float2(acc[mt][nt][0] + bb.x, acc[mt][nt][1] + bb.y);
            float2 o1 = make_float2(acc[mt][nt][2] + bb.x, acc[mt][nt][3] + bb.y);
            if (RELU) {
                o0.x = fmaxf(o0.x, 0.f); o0.y = fmaxf(o0.y, 0.f);
                o1.x = fmaxf(o1.x, 0.f); o1.y = fmaxf(o1.y, 0.f);
            }
            if (HASRES) {
                float2 r0 = *(const float2*)(res + (size_t)mr * N + nc);
                float2 r1 = *(const float2*)(res + (size_t)(mr+8) * N + nc);
                o0.x += r0.x; o0.y += r0.y;
                o1.x += r1.x; o1.y += r1.y;
            }
            if (OUTHALF) {
                __half* Ch = (__half*)Cm;
                *(uint32_t*)(Ch + (size_t)mr     * N + nc) = f2h2(o0.x, o0.y);
                *(uint32_t*)(Ch + (size_t)(mr+8) * N + nc) = f2h2(o1.x, o1.y);
            } else {
                float* Cf = (float*)Cm;
                *(float2*)(Cf + (size_t)mr     * N + nc) = o0;
                *(float2*)(Cf + (size_t)(mr+8) * N + nc) = o1;
            }
        }
    }
}

// ---------------- fp16 flash attention, register softmax, 4-stage K/V ring --
#define ASTG   18432
#define AVOF   9216
#define ATT_SMEM_BYTES (4*ASTG)

__global__ __launch_bounds__(256, 2) void attn_kernel(
    const __half* __restrict__ qkv, __half* __restrict__ out)
{
    extern __shared__ char asmem[];
    int qt = (int)gridDim.x - 1 - (int)blockIdx.x;   // heavy tiles first
    int bh = blockIdx.y;
    int q0 = qt << 7;
    int bb = bh >> 4, hh = bh & 15;
    const __half* Qg = qkv + (size_t)(bb * T_) * QKVN + hh * D_;
    const __half* Kg = Qg + C_;
    const __half* Vg = Qg + 2*C_;
    int tid = threadIdx.x;
    int warp = tid >> 5, lane = tid & 31;
    int l16 = lane & 15, l2 = lane >> 4;
    int gid = lane >> 2, tig = lane & 3;
    int i0 = warp << 4;

    int cr = tid >> 2, cc = (tid & 3) << 4;
    uint32_t kdst[4], vdst[4];
    #pragma unroll
    for (int s = 0; s < 4; s++) {
        kdst[s] = su32(asmem + s*ASTG        + (cr*72 + cc)*2);
        vdst[s] = su32(asmem + s*ASTG + AVOF + (cr*72 + cc)*2);
    }

    unsigned qa[4][4];
    {
        const __half* q0p = Qg + (size_t)(q0 + i0 + gid) * QKVN;
        const __half* q1p = q0p + 8 * QKVN;
        const __half2 sc = __half2half2(__float2half(0.03125f));
        #pragma unroll
        for (int ks = 0; ks < 4; ks++) {
            int c = (ks<<4) + (tig<<1);
            __half2 w0 = __hmul2(*(const __half2*)(q0p + c),     sc);
            __half2 w1 = __hmul2(*(const __half2*)(q1p + c),     sc);
            __half2 w2 = __hmul2(*(const __half2*)(q0p + c + 8), sc);
            __half2 w3 = __hmul2(*(const __half2*)(q1p + c + 8), sc);
            qa[ks][0] = *(uint32_t*)&w0; qa[ks][1] = *(uint32_t*)&w1;
            qa[ks][2] = *(uint32_t*)&w2; qa[ks][3] = *(uint32_t*)&w3;
        }
    }

    float oacc[8][4] = {};
    float m0 = -1e30f, m1 = -1e30f, l0 = 0.f, l1 = 0.f;
    int r0g = q0 + i0 + gid, r1g = r0g + 8;

    int ktmax = 2*qt + 1;
    #pragma unroll
    for (int p = 0; p < 2; p++) {
        const __half* kp = Kg + (size_t)((p<<6) + cr) * QKVN + cc;
        const __half* vp = Vg + (size_t)((p<<6) + cr) * QKVN + cc;
        CPA16(kdst[p], kp); CPA16(kdst[p] + 16, kp + 8);
        CPA16(vdst[p], vp); CPA16(vdst[p] + 16, vp + 8);
        CPA_COMMIT();
    }

    for (int kt = 0; kt <= ktmax; kt++) {
        int st = kt & 3;
        int k0 = kt << 6;
        if (kt + 2 <= ktmax) {
            int s = (kt + 2) & 3;
            const __half* kp = Kg + (size_t)(((kt+2)<<6) + cr) * QKVN + cc;
            const __half* vp = Vg + (size_t)(((kt+2)<<6) + cr) * QKVN + cc;
            CPA16(kdst[s], kp); CPA16(kdst[s] + 16, kp + 8);
            CPA16(vdst[s], vp); CPA16(vdst[s] + 16, vp + 8);
            CPA_COMMIT();
            CPA_WAIT(2);
        } else if (kt + 1 <= ktmax) {
            CPA_WAIT(1);
        } else {
            CPA_WAIT(0);
        }
        __syncthreads();

        const __half* Kh = (const __half*)(asmem + st*ASTG);
        const __half* Vh = (const __half*)(asmem + st*ASTG + AVOF);

        float sacc[8][4] = {};
        #pragma unroll
        for (int ks = 0; ks < 4; ks++) {
            #pragma unroll
            for (int np = 0; np < 4; np++) {
                uint32_t kd = su32(Kh + ((np<<4) + l16)*72 + (ks<<4) + (l2<<3));
                uint32_t t0, t1, t2, t3;
                LDSM4(t0, t1, t2, t3, kd);
                unsigned b0[2] = {t0, t2}, b1[2] = {t1, t3};
                MMA_F16(sacc[2*np],   qa[ks], b0);
                MMA_F16(sacc[2*np+1], qa[ks], b1);
            }
        }

        if (kt >= 2*qt) {
            #pragma unroll
            for (int nt = 0; nt < 8; nt++) {
                int jb = k0 + (nt<<3) + (tig<<1);
                if (jb     > r0g) sacc[nt][0] = -1e30f;
                if (jb + 1 > r0g) sacc[nt][1] = -1e30f;
                if (jb     > r1g) sacc[nt][2] = -1e30f;
                if (jb + 1 > r1g) sacc[nt][3] = -1e30f;
            }
        }

        {
            float mx0 = -1e30f, mx1 = -1e30f;
            #pragma unroll
            for (int nt = 0; nt < 8; nt++) {
                mx0 = fmaxf(mx0, fmaxf(sacc[nt][0], sacc[nt][1]));
                mx1 = fmaxf(mx1, fmaxf(sacc[nt][2], sacc[nt][3]));
            }
            mx0 = fmaxf(mx0, __shfl_xor_sync(0xffffffffu, mx0, 1));
            mx0 = fmaxf(mx0, __shfl_xor_sync(0xffffffffu, mx0, 2));
            mx1 = fmaxf(mx1, __shfl_xor_sync(0xffffffffu, mx1, 1));
            mx1 = fmaxf(mx1, __shfl_xor_sync(0xffffffffu, mx1, 2));
            float m0n = fmaxf(m0, mx0), m1n = fmaxf(m1, mx1);
            float al0 = __expf(m0 - m0n), al1 = __expf(m1 - m1n);
            float s0 = 0.f, s1 = 0.f;
            #pragma unroll
            for (int nt = 0; nt < 8; nt++) {
                sacc[nt][0] = __expf(sacc[nt][0] - m0n);
                sacc[nt][1] = __expf(sacc[nt][1] - m0n);
                sacc[nt][2] = __expf(sacc[nt][2] - m1n);
                sacc[nt][3] = __expf(sacc[nt][3] - m1n);
                s0 += sacc[nt][0] + sacc[nt][1];
                s1 += sacc[nt][2] + sacc[nt][3];
            }
            s0 += __shfl_xor_sync(0xffffffffu, s0, 1);
            s0 += __shfl_xor_sync(0xffffffffu, s0, 2);
            s1 += __shfl_xor_sync(0xffffffffu, s1, 1);
            s1 += __shfl_xor_sync(0xffffffffu, s1, 2);
            l0 = l0 * al0 + s0;  m0 = m0n;
            l1 = l1 * al1 + s1;  m1 = m1n;
            #pragma unroll
            for (int nt = 0; nt < 8; nt++) {
                oacc[nt][0] *= al0; oacc[nt][1] *= al0;
                oacc[nt][2] *= al1; oacc[nt][3] *= al1;
            }
        }

        #pragma unroll
        for (int ks = 0; ks < 4; ks++) {
            unsigned a[4];
            a[0] = f2h2(sacc[2*ks  ][0], sacc[2*ks  ][1]);
            a[1] = f2h2(sacc[2*ks  ][2], sacc[2*ks  ][3]);
            a[2] = f2h2(sacc[2*ks+1][0], sacc[2*ks+1][1]);
            a[3] = f2h2(sacc[2*ks+1][2], sacc[2*ks+1][3]);
            #pragma unroll
            for (int np = 0; np < 4; np++) {
                uint32_t vdx = su32(Vh + ((ks<<4) + l16)*72 + (np<<4) + (l2<<3));
                uint32_t t0, t1, t2, t3;
                LDSM4T(t0, t1, t2, t3, vdx);
                unsigned b0[2] = {t0, t1}, b1[2] = {t2, t3};
                MMA_F16(oacc[2*np],   a, b0);
                MMA_F16(oacc[2*np+1], a, b1);
            }
        }
    }

    {
        float inv0 = 1.0f / l0;
        float inv1 = 1.0f / l1;
        __half* o0 = out + ((size_t)(bb * T_ + r0g)) * C_ + hh * D_ + (tig<<1);
        __half* o1 = o0 + 8 * C_;
        #pragma unroll
        for (int nt = 0; nt < 8; nt++) {
            *(uint32_t*)(o0 + (nt<<3)) = f2h2(oacc[nt][0]*inv0, oacc[nt][1]*inv0);
            *(uint32_t*)(o1 + (nt<<3)) = f2h2(oacc[nt][2]*inv1, oacc[nt][3]*inv1);
        }
    }
}

// ---------------- launch ----------------------------------------------------
extern "C" void kernel_launch(void* const* d_in, const int* in_sizes, int n_in,
                              void* d_out, int out_size)
{
    const float* x   = (const float*)d_in[0];
    const float* Wq  = (const float*)d_in[1];
    const float* Wk  = (const float*)d_in[2];
    const float* Wv  = (const float*)d_in[3];
    const float* Wo  = (const float*)d_in[4];
    const float* bo  = (const float*)d_in[5];
    const float* W1  = (const float*)d_in[6];
    const float* b1  = (const float*)d_in[7];
    const float* W2  = (const float*)d_in[8];
    const float* b2  = (const float*)d_in[9];
    const float* g1  = (const float*)d_in[10];
    const float* be1 = (const float*)d_in[11];
    const float* g2  = (const float*)d_in[12];
    const float* be2 = (const float*)d_in[13];
    float* out = (float*)d_out;

    __half *h, *wp, *qkv, *att, *h2, *ff, *woh, *w1h, *w2h;
    float *x1;
    cudaGetSymbolAddress((void**)&h,   hb_h);
    cudaGetSymbolAddress((void**)&wp,  hb_wp);
    cudaGetSymbolAddress((void**)&qkv, hb_qkv);
    cudaGetSymbolAddress((void**)&att, hb_att);
    cudaGetSymbolAddress((void**)&h2,  hb_h2);
    cudaGetSymbolAddress((void**)&ff,  hb_ff);
    cudaGetSymbolAddress((void**)&woh, hb_wo);
    cudaGetSymbolAddress((void**)&w1h, hb_w1);
    cudaGetSymbolAddress((void**)&w2h, hb_w2);
    cudaGetSymbolAddress((void**)&x1,  g_x1);

    cudaFuncSetAttribute(attn_kernel,
        cudaFuncAttributeMaxDynamicSharedMemorySize, ATT_SMEM_BYTES);
    cudaFuncSetAttribute(tgemm<0,0,0,1>,
        cudaFuncAttributeMaxDynamicSharedMemorySize, GT_SMEM);
    cudaFuncSetAttribute(tgemm<0,1,1,0>,
        cudaFuncAttributeMaxDynamicSharedMemorySize, GT_SMEM);
    cudaFuncSetAttribute(tgemm<1,0,1,1>,
        cudaFuncAttributeMaxDynamicSharedMemorySize, GT_SMEM);

    // 1) LN1 (half out)
    ln_kernel<<<M_/8, 256>>>(x, g1, be1, h);
    // 2) weight conversions (merged) + qkv repack
    repack_kernel<<<dim3((C_*C_)/256, 3), 256>>>(Wq, Wk, Wv, wp);
    wprep_kernel<<<(C_*C_ + 2*C_*F_)/1024, 256>>>(Wo, W1, W2, woh, w1h, w2h);
    // 3) fused QKV projection (half in/out)
    tgemm<0,0,0,1><<<dim3(QKVN/256, M_/128), 512, GT_SMEM>>>(h, wp, qkv, M_, QKVN, C_, nullptr, nullptr);
    // 4) causal flash attention (register softmax, 4-stage K/V ring)
    attn_kernel<<<dim3(T_/128, B_*H_), 256, ATT_SMEM_BYTES>>>(qkv, att);
    // 5) Wo projection + bias + residual (fp32 out)
    tgemm<0,1,1,0><<<dim3(C_/256, M_/128), 512, GT_SMEM>>>(att, woh, x1, M_, C_, C_, bo, x);
    // 6) LN2 (half out)
    ln_kernel<<<M_/8, 256>>>(x1, g2, be2, h2);
    // 7) FFN up + ReLU (half out)
    tgemm<1,0,1,1><<<dim3(F_/256, M_/128), 512, GT_SMEM>>>(h2, w1h, ff, M_, F_, C_, b1, nullptr);
    // 8) FFN down + bias + residual -> final fp32 output
    tgemm<0,1,1,0><<<dim3(C_/256, M_/128), 512, GT_SMEM>>>(ff, w2h, out, M_, C_, F_, b2, x1);
}

// round 13
// speedup vs baseline: 7.1189x; 1.0040x over previous
#include <cuda_runtime.h>
#include <cuda_fp16.h>
#include <cstdint>

#define B_ 2
#define T_ 2048
#define C_ 1024
#define H_ 16
#define D_ 64
#define F_ 4096
#define M_ (B_*T_)   // 4096 rows
#define QKVN 3072

// ---------------- scratch (device globals; no runtime allocation) ----------
__device__ __align__(16) __half hb_h  [M_*C_];    // ln1 out (half)
__device__ __align__(16) __half hb_wp [C_*QKVN];  // packed Wqkv (half)
__device__ __align__(16) __half hb_qkv[M_*QKVN];  // qkv activations (half)
__device__ __align__(16) __half hb_att[M_*C_];    // attn out (half)
__device__ __align__(16) __half hb_h2 [M_*C_];    // ln2 out (half)
__device__ __align__(16) __half hb_ff [M_*F_];    // ffn mid (half)
__device__ __align__(16) __half hb_wo [C_*C_];
__device__ __align__(16) __half hb_w1 [C_*F_];
__device__ __align__(16) __half hb_w2 [F_*C_];
__device__ __align__(16) float  g_x1  [M_*C_];    // attn residual out (fp32)

__device__ __forceinline__ uint32_t f2h2(float x, float y) {
    __half2 h = __floats2half2_rn(x, y);
    return *(uint32_t*)&h;
}
__device__ __forceinline__ uint32_t su32(const void* p) {
    return (uint32_t)__cvta_generic_to_shared(p);
}

#define MMA_F16(acc, a, b) \
    asm volatile( \
        "mma.sync.aligned.m16n8k16.row.col.f32.f16.f16.f32 " \
        "{%0,%1,%2,%3},{%4,%5,%6,%7},{%8,%9},{%0,%1,%2,%3};" \
        : "+f"((acc)[0]), "+f"((acc)[1]), "+f"((acc)[2]), "+f"((acc)[3]) \
        : "r"((a)[0]), "r"((a)[1]), "r"((a)[2]), "r"((a)[3]), \
          "r"((b)[0]), "r"((b)[1]))

#define LDSM4(r0, r1, r2, r3, addr) \
    asm volatile("ldmatrix.sync.aligned.m8n8.x4.shared.b16 {%0,%1,%2,%3}, [%4];" \
        : "=r"(r0), "=r"(r1), "=r"(r2), "=r"(r3) : "r"(addr))
#define LDSM4T(r0, r1, r2, r3, addr) \
    asm volatile("ldmatrix.sync.aligned.m8n8.x4.trans.shared.b16 {%0,%1,%2,%3}, [%4];" \
        : "=r"(r0), "=r"(r1), "=r"(r2), "=r"(r3) : "r"(addr))

#define CPA16(dst, src) \
    asm volatile("cp.async.cg.shared.global [%0], [%1], 16;" :: "r"(dst), "l"(src))
#define CPA_COMMIT() asm volatile("cp.async.commit_group;" ::: "memory")
#define CPA_WAIT(n)  asm volatile("cp.async.wait_group %0;" :: "n"(n) : "memory")

// ---------------- LayerNorm: warp-per-row, fp32 in, half out ----------------
__global__ __launch_bounds__(256) void ln_kernel(
    const float* __restrict__ x, const float* __restrict__ g,
    const float* __restrict__ b, __half* __restrict__ out)
{
    int warp = threadIdx.x >> 5, lane = threadIdx.x & 31;
    int row = (blockIdx.x << 3) + warp;
    const float4* xp = (const float4*)(x + (size_t)row * C_);
    float4 v[8];
    float s = 0.f, s2 = 0.f;
    #pragma unroll
    for (int i = 0; i < 8; i++) {
        v[i] = xp[lane + (i << 5)];
        s  += v[i].x + v[i].y + v[i].z + v[i].w;
        s2 += v[i].x*v[i].x + v[i].y*v[i].y + v[i].z*v[i].z + v[i].w*v[i].w;
    }
    #pragma unroll
    for (int o = 16; o; o >>= 1) {
        s  += __shfl_xor_sync(0xffffffffu, s,  o);
        s2 += __shfl_xor_sync(0xffffffffu, s2, o);
    }
    float mean = s * (1.0f/C_);
    float var  = s2 * (1.0f/C_) - mean*mean;
    float rstd = rsqrtf(var + 1e-5f);
    const float4* gp = (const float4*)g;
    const float4* bp = (const float4*)b;
    uint2* op = (uint2*)(out + (size_t)row * C_);
    #pragma unroll
    for (int i = 0; i < 8; i++) {
        float4 gv = gp[lane + (i << 5)];
        float4 bv = bp[lane + (i << 5)];
        uint2 w;
        w.x = f2h2((v[i].x-mean)*rstd*gv.x + bv.x, (v[i].y-mean)*rstd*gv.y + bv.y);
        w.y = f2h2((v[i].z-mean)*rstd*gv.z + bv.z, (v[i].w-mean)*rstd*gv.w + bv.w);
        op[lane + (i << 5)] = w;
    }
}

// ---------------- merged weight prep: Wo/W1/W2 fp32 -> fp16 ------------------
__global__ __launch_bounds__(256) void wprep_kernel(
    const float* __restrict__ Wo, const float* __restrict__ W1,
    const float* __restrict__ W2, __half* __restrict__ woh,
    __half* __restrict__ w1h, __half* __restrict__ w2h)
{
    size_t i = ((size_t)blockIdx.x*256 + threadIdx.x) << 2;
    const float* src; __half* dst; size_t off;
    const size_t S0 = (size_t)C_*C_, S1 = S0 + (size_t)C_*F_;
    if (i < S0)      { src = Wo; dst = woh; off = i; }
    else if (i < S1) { src = W1; dst = w1h; off = i - S0; }
    else             { src = W2; dst = w2h; off = i - S1; }
    float4 v = *(const float4*)(src + off);
    uint2 w;
    w.x = f2h2(v.x, v.y); w.y = f2h2(v.z, v.w);
    *(uint2*)(dst + off) = w;
}

// ---------------- repack Wq/Wk/Wv [H][C][D] -> half [C][3*C] ----------------
__global__ __launch_bounds__(256) void repack_kernel(
    const float* __restrict__ Wq, const float* __restrict__ Wk,
    const float* __restrict__ Wv, __half* __restrict__ Wp)
{
    int idx = blockIdx.x*256 + threadIdx.x;        // over C*C
    int which = blockIdx.y;
    const float* W = (which==0) ? Wq : (which==1) ? Wk : Wv;
    int c = idx >> 10, n = idx & 1023;
    int h = n >> 6, d = n & 63;
    Wp[(size_t)c*QKVN + which*C_ + n] = __float2half_rn(W[((size_t)h*C_ + c)*D_ + d]);
}

// ---------------- fp16 GEMM: 128x256 tile, 512 thr (16 warps), 8-stage ring -
#define GSTAGE 27136
#define GBOF   10240
#define GT_SMEM (8*GSTAGE)    // 217088 B

template<int RELU, int HASRES, int HASBIAS, int OUTHALF>
__global__ __launch_bounds__(512, 1) void tgemm(
    const __half* __restrict__ A, const __half* __restrict__ Bm,
    void* __restrict__ Cm, int M, int N, int K,
    const float* __restrict__ bias, const float* __restrict__ res)
{
    extern __shared__ char dsm[];
    int tid = threadIdx.x;
    int m0 = blockIdx.y << 7, n0 = blockIdx.x << 8;
    int warp = tid >> 5, lane = tid & 31;
    int l16 = lane & 15, l2 = lane >> 4;
    int gid = lane >> 2, tig = lane & 3;
    int wm = (warp & 3) << 5;        // 4 m-strips of 32 rows
    int wn = (warp >> 2) << 6;       // 4 n-strips of 64 cols

    float acc[2][8][4] = {};

    // cp.async maps (512 threads)
    int ra = tid >> 2, ca = (tid & 3) << 3;    // A: row 0..127, 8-half col base
    int rb = tid >> 4, nb = (tid & 15) << 4;   // B: k-row 0..31, 16-half col base
    const __half* Ap = A  + (size_t)(m0 + ra) * K + ca;
    const __half* Bp = Bm + (size_t)rb * N + n0 + nb;
    uint32_t aoff = (uint32_t)((ra*40 + ca)*2);
    uint32_t boff = (uint32_t)(GBOF + (rb*264 + nb)*2);
    uint32_t sbase = su32(dsm);

    int KT = K >> 5;
    int NB = KT >> 1;
    // prologue: tiles 0..3
    #pragma unroll
    for (int p = 0; p < 4; p++) {
        const __half* ap = Ap + (p<<5);
        const __half* bp = Bp + (size_t)(p<<5) * N;
        uint32_t sb = sbase + p*GSTAGE;
        CPA16(sb + aoff, ap);
        CPA16(sb + boff,      bp);
        CPA16(sb + boff + 16, bp + 8);
        CPA_COMMIT();
    }

    for (int b = 0; b < NB; b++) {
        int t0 = b << 1;
        if (b + 2 < NB) {
            #pragma unroll
            for (int q = 0; q < 2; q++) {
                int t = t0 + 4 + q;
                const __half* ap = Ap + (t<<5);
                const __half* bp = Bp + (size_t)(t<<5) * N;
                uint32_t sb = sbase + (t & 7)*GSTAGE;
                CPA16(sb + aoff, ap);
                CPA16(sb + boff,      bp);
                CPA16(sb + boff + 16, bp + 8);
                CPA_COMMIT();
            }
            CPA_WAIT(4);
        } else if (b + 1 < NB) {
            CPA_WAIT(2);
        } else {
            CPA_WAIT(0);
        }
        __syncthreads();

        // compute tiles t0, t0+1
        #pragma unroll
        for (int q = 0; q < 2; q++) {
            const __half* Ah = (const __half*)(dsm + ((t0 + q) & 7)*GSTAGE);
            const __half* Bh = (const __half*)(dsm + ((t0 + q) & 7)*GSTAGE + GBOF);
            #pragma unroll
            for (int ks = 0; ks < 2; ks++) {
                unsigned a[2][4], bfr[8][2];
                #pragma unroll
                for (int mt = 0; mt < 2; mt++) {
                    uint32_t ad = su32(Ah + (wm + (mt<<4) + l16)*40 + (ks<<4) + (l2<<3));
                    LDSM4(a[mt][0], a[mt][1], a[mt][2], a[mt][3], ad);
                }
                #pragma unroll
                for (int np = 0; np < 4; np++) {
                    uint32_t bd = su32(Bh + ((ks<<4) + l16)*264 + wn + (np<<4) + (l2<<3));
                    uint32_t r0, r1, r2, r3;
                    LDSM4T(r0, r1, r2, r3, bd);
                    bfr[2*np][0] = r0; bfr[2*np][1] = r1;
                    bfr[2*np+1][0] = r2; bfr[2*np+1][1] = r3;
                }
                #pragma unroll
                for (int mt = 0; mt < 2; mt++)
                    #pragma unroll
                    for (int nt = 0; nt < 8; nt++)
                        MMA_F16(acc[mt][nt], a[mt], bfr[nt]);
            }
        }
    }

    #pragma unroll
    for (int mt = 0; mt < 2; mt++) {
        int mr = m0 + wm + (mt<<4) + gid;
        #pragma unroll
        for (int nt = 0; nt < 8; nt++) {
            int nc = n0 + wn + (nt<<3) + (tig<<1);
            float2 bb = make_float2(0.f, 0.f);
            if (HASBIAS) bb = *(const float2*)(bias + nc);
            float2 o0 = make_float2(acc[mt][nt][0] + bb.x, acc[mt][nt][1] + bb.y);
            float2 o1 = make_float2(acc[mt][nt][2] + bb.x, acc[mt][nt][3] + bb.y);
            if (RELU) {
                o0.x = fmaxf(o0.x, 0.f); o0.y = fmaxf(o0.y, 0.f);
                o1.x = fmaxf(o1.x, 0.f); o1.y = fmaxf(o1.y, 0.f);
            }
            if (HASRES) {
                float2 r0 = *(const float2*)(res + (size_t)mr * N + nc);
                float2 r1 = *(const float2*)(res + (size_t)(mr+8) * N + nc);
                o0.x += r0.x; o0.y += r0.y;
                o1.x += r1.x; o1.y += r1.y;
            }
            if (OUTHALF) {
                __half* Ch = (__half*)Cm;
                *(uint32_t*)(Ch + (size_t)mr     * N + nc) = f2h2(o0.x, o0.y);
                *(uint32_t*)(Ch + (size_t)(mr+8) * N + nc) = f2h2(o1.x, o1.y);
            } else {
                float* Cf = (float*)Cm;
                *(float2*)(Cf + (size_t)mr     * N + nc) = o0;
                *(float2*)(Cf + (size_t)(mr+8) * N + nc) = o1;
            }
        }
    }
}

// ---------------- fp16 flash attention, register softmax, 4-stage K/V ring --
#define ASTG   18432
#define AVOF   9216
#define ATT_SMEM_BYTES (4*ASTG)

__global__ __launch_bounds__(256, 2) void attn_kernel(
    const __half* __restrict__ qkv, __half* __restrict__ out)
{
    extern __shared__ char asmem[];
    int qt = (int)gridDim.x - 1 - (int)blockIdx.x;   // heavy tiles first
    int bh = blockIdx.y;
    int q0 = qt << 7;
    int bb = bh >> 4, hh = bh & 15;
    const __half* Qg = qkv + (size_t)(bb * T_) * QKVN + hh * D_;
    const __half* Kg = Qg + C_;
    const __half* Vg = Qg + 2*C_;
    int tid = threadIdx.x;
    int warp = tid >> 5, lane = tid & 31;
    int l16 = lane & 15, l2 = lane >> 4;
    int gid = lane >> 2, tig = lane & 3;
    int i0 = warp << 4;

    int cr = tid >> 2, cc = (tid & 3) << 4;
    uint32_t kdst[4], vdst[4];
    #pragma unroll
    for (int s = 0; s < 4; s++) {
        kdst[s] = su32(asmem + s*ASTG        + (cr*72 + cc)*2);
        vdst[s] = su32(asmem + s*ASTG + AVOF + (cr*72 + cc)*2);
    }

    unsigned qa[4][4];
    {
        const __half* q0p = Qg + (size_t)(q0 + i0 + gid) * QKVN;
        const __half* q1p = q0p + 8 * QKVN;
        const __half2 sc = __half2half2(__float2half(0.03125f));
        #pragma unroll
        for (int ks = 0; ks < 4; ks++) {
            int c = (ks<<4) + (tig<<1);
            __half2 w0 = __hmul2(*(const __half2*)(q0p + c),     sc);
            __half2 w1 = __hmul2(*(const __half2*)(q1p + c),     sc);
            __half2 w2 = __hmul2(*(const __half2*)(q0p + c + 8), sc);
            __half2 w3 = __hmul2(*(const __half2*)(q1p + c + 8), sc);
            qa[ks][0] = *(uint32_t*)&w0; qa[ks][1] = *(uint32_t*)&w1;
            qa[ks][2] = *(uint32_t*)&w2; qa[ks][3] = *(uint32_t*)&w3;
        }
    }

    float oacc[8][4] = {};
    float m0 = -1e30f, m1 = -1e30f, l0 = 0.f, l1 = 0.f;
    int r0g = q0 + i0 + gid, r1g = r0g + 8;

    int ktmax = 2*qt + 1;
    #pragma unroll
    for (int p = 0; p < 2; p++) {
        const __half* kp = Kg + (size_t)((p<<6) + cr) * QKVN + cc;
        const __half* vp = Vg + (size_t)((p<<6) + cr) * QKVN + cc;
        CPA16(kdst[p], kp); CPA16(kdst[p] + 16, kp + 8);
        CPA16(vdst[p], vp); CPA16(vdst[p] + 16, vp + 8);
        CPA_COMMIT();
    }

    for (int kt = 0; kt <= ktmax; kt++) {
        int st = kt & 3;
        int k0 = kt << 6;
        if (kt + 2 <= ktmax) {
            int s = (kt + 2) & 3;
            const __half* kp = Kg + (size_t)(((kt+2)<<6) + cr) * QKVN + cc;
            const __half* vp = Vg + (size_t)(((kt+2)<<6) + cr) * QKVN + cc;
            CPA16(kdst[s], kp); CPA16(kdst[s] + 16, kp + 8);
            CPA16(vdst[s], vp); CPA16(vdst[s] + 16, vp + 8);
            CPA_COMMIT();
            CPA_WAIT(2);
        } else if (kt + 1 <= ktmax) {
            CPA_WAIT(1);
        } else {
            CPA_WAIT(0);
        }
        __syncthreads();

        const __half* Kh = (const __half*)(asmem + st*ASTG);
        const __half* Vh = (const __half*)(asmem + st*ASTG + AVOF);

        float sacc[8][4] = {};
        #pragma unroll
        for (int ks = 0; ks < 4; ks++) {
            #pragma unroll
            for (int np = 0; np < 4; np++) {
                uint32_t kd = su32(Kh + ((np<<4) + l16)*72 + (ks<<4) + (l2<<3));
                uint32_t t0, t1, t2, t3;
                LDSM4(t0, t1, t2, t3, kd);
                unsigned b0[2] = {t0, t2}, b1[2] = {t1, t3};
                MMA_F16(sacc[2*np],   qa[ks], b0);
                MMA_F16(sacc[2*np+1], qa[ks], b1);
            }
        }

        if (kt >= 2*qt) {
            #pragma unroll
            for (int nt = 0; nt < 8; nt++) {
                int jb = k0 + (nt<<3) + (tig<<1);
                if (jb     > r0g) sacc[nt][0] = -1e30f;
                if (jb + 1 > r0g) sacc[nt][1] = -1e30f;
                if (jb     > r1g) sacc[nt][2] = -1e30f;
                if (jb + 1 > r1g) sacc[nt][3] = -1e30f;
            }
        }

        {
            float mx0 = -1e30f, mx1 = -1e30f;
            #pragma unroll
            for (int nt = 0; nt < 8; nt++) {
                mx0 = fmaxf(mx0, fmaxf(sacc[nt][0], sacc[nt][1]));
                mx1 = fmaxf(mx1, fmaxf(sacc[nt][2], sacc[nt][3]));
            }
            mx0 = fmaxf(mx0, __shfl_xor_sync(0xffffffffu, mx0, 1));
            mx0 = fmaxf(mx0, __shfl_xor_sync(0xffffffffu, mx0, 2));
            mx1 = fmaxf(mx1, __shfl_xor_sync(0xffffffffu, mx1, 1));
            mx1 = fmaxf(mx1, __shfl_xor_sync(0xffffffffu, mx1, 2));
            float m0n = fmaxf(m0, mx0), m1n = fmaxf(m1, mx1);
            float al0 = __expf(m0 - m0n), al1 = __expf(m1 - m1n);
            float s0 = 0.f, s1 = 0.f;
            #pragma unroll
            for (int nt = 0; nt < 8; nt++) {
                sacc[nt][0] = __expf(sacc[nt][0] - m0n);
                sacc[nt][1] = __expf(sacc[nt][1] - m0n);
                sacc[nt][2] = __expf(sacc[nt][2] - m1n);
                sacc[nt][3] = __expf(sacc[nt][3] - m1n);
                s0 += sacc[nt][0] + sacc[nt][1];
                s1 += sacc[nt][2] + sacc[nt][3];
            }
            s0 += __shfl_xor_sync(0xffffffffu, s0, 1);
            s0 += __shfl_xor_sync(0xffffffffu, s0, 2);
            s1 += __shfl_xor_sync(0xffffffffu, s1, 1);
            s1 += __shfl_xor_sync(0xffffffffu, s1, 2);
            l0 = l0 * al0 + s0;  m0 = m0n;
            l1 = l1 * al1 + s1;  m1 = m1n;
            #pragma unroll
            for (int nt = 0; nt < 8; nt++) {
                oacc[nt][0] *= al0; oacc[nt][1] *= al0;
                oacc[nt][2] *= al1; oacc[nt][3] *= al1;
            }
        }

        #pragma unroll
        for (int ks = 0; ks < 4; ks++) {
            unsigned a[4];
            a[0] = f2h2(sacc[2*ks  ][0], sacc[2*ks  ][1]);
            a[1] = f2h2(sacc[2*ks  ][2], sacc[2*ks  ][3]);
            a[2] = f2h2(sacc[2*ks+1][0], sacc[2*ks+1][1]);
            a[3] = f2h2(sacc[2*ks+1][2], sacc[2*ks+1][3]);
            #pragma unroll
            for (int np = 0; np < 4; np++) {
                uint32_t vdx = su32(Vh + ((ks<<4) + l16)*72 + (np<<4) + (l2<<3));
                uint32_t t0, t1, t2, t3;
                LDSM4T(t0, t1, t2, t3, vdx);
                unsigned b0[2] = {t0, t1}, b1[2] = {t2, t3};
                MMA_F16(oacc[2*np],   a, b0);
                MMA_F16(oacc[2*np+1], a, b1);
            }
        }
    }

    {
        float inv0 = 1.0f / l0;
        float inv1 = 1.0f / l1;
        __half* o0 = out + ((size_t)(bb * T_ + r0g)) * C_ + hh * D_ + (tig<<1);
        __half* o1 = o0 + 8 * C_;
        #pragma unroll
        for (int nt = 0; nt < 8; nt++) {
            *(uint32_t*)(o0 + (nt<<3)) = f2h2(oacc[nt][0]*inv0, oacc[nt][1]*inv0);
            *(uint32_t*)(o1 + (nt<<3)) = f2h2(oacc[nt][2]*inv1, oacc[nt][3]*inv1);
        }
    }
}

// ---------------- launch ----------------------------------------------------
extern "C" void kernel_launch(void* const* d_in, const int* in_sizes, int n_in,
                              void* d_out, int out_size)
{
    const float* x   = (const float*)d_in[0];
    const float* Wq  = (const float*)d_in[1];
    const float* Wk  = (const float*)d_in[2];
    const float* Wv  = (const float*)d_in[3];
    const float* Wo  = (const float*)d_in[4];
    const float* bo  = (const float*)d_in[5];
    const float* W1  = (const float*)d_in[6];
    const float* b1  = (const float*)d_in[7];
    const float* W2  = (const float*)d_in[8];
    const float* b2  = (const float*)d_in[9];
    const float* g1  = (const float*)d_in[10];
    const float* be1 = (const float*)d_in[11];
    const float* g2  = (const float*)d_in[12];
    const float* be2 = (const float*)d_in[13];
    float* out = (float*)d_out;

    __half *h, *wp, *qkv, *att, *h2, *ff, *woh, *w1h, *w2h;
    float *x1;
    cudaGetSymbolAddress((void**)&h,   hb_h);
    cudaGetSymbolAddress((void**)&wp,  hb_wp);
    cudaGetSymbolAddress((void**)&qkv, hb_qkv);
    cudaGetSymbolAddress((void**)&att, hb_att);
    cudaGetSymbolAddress((void**)&h2,  hb_h2);
    cudaGetSymbolAddress((void**)&ff,  hb_ff);
    cudaGetSymbolAddress((void**)&woh, hb_wo);
    cudaGetSymbolAddress((void**)&w1h, hb_w1);
    cudaGetSymbolAddress((void**)&w2h, hb_w2);
    cudaGetSymbolAddress((void**)&x1,  g_x1);

    cudaFuncSetAttribute(attn_kernel,
        cudaFuncAttributeMaxDynamicSharedMemorySize, ATT_SMEM_BYTES);
    cudaFuncSetAttribute(tgemm<0,0,0,1>,
        cudaFuncAttributeMaxDynamicSharedMemorySize, GT_SMEM);
    cudaFuncSetAttribute(tgemm<0,1,1,0>,
        cudaFuncAttributeMaxDynamicSharedMemorySize, GT_SMEM);
    cudaFuncSetAttribute(tgemm<1,0,1,1>,
        cudaFuncAttributeMaxDynamicSharedMemorySize, GT_SMEM);

    // ---- fork weight-prep onto a side stream (captured via event fork) ----
    cudaStream_t s2;
    cudaStreamCreateWithFlags(&s2, cudaStreamNonBlocking);
    cudaEvent_t e0, eR, eW;
    cudaEventCreateWithFlags(&e0, cudaEventDisableTiming);
    cudaEventCreateWithFlags(&eR, cudaEventDisableTiming);
    cudaEventCreateWithFlags(&eW, cudaEventDisableTiming);

    cudaEventRecord(e0, 0);               // fork point on capture stream
    cudaStreamWaitEvent(s2, e0, 0);
    repack_kernel<<<dim3((C_*C_)/256, 3), 256, 0, s2>>>(Wq, Wk, Wv, wp);
    cudaEventRecord(eR, s2);              // repack done (needed by QKV)
    wprep_kernel<<<(C_*C_ + 2*C_*F_)/1024, 256, 0, s2>>>(Wo, W1, W2, woh, w1h, w2h);
    cudaEventRecord(eW, s2);              // wprep done (needed by Wo GEMM)

    // 1) LN1 (half out) — overlaps repack
    ln_kernel<<<M_/8, 256>>>(x, g1, be1, h);
    // 2) join repack, then QKV projection (wprep continues in background)
    cudaStreamWaitEvent(0, eR, 0);
    tgemm<0,0,0,1><<<dim3(QKVN/256, M_/128), 512, GT_SMEM>>>(h, wp, qkv, M_, QKVN, C_, nullptr, nullptr);
    // 3) causal flash attention (register softmax, 4-stage K/V ring)
    attn_kernel<<<dim3(T_/128, B_*H_), 256, ATT_SMEM_BYTES>>>(qkv, att);
    // 4) join wprep, then Wo projection + bias + residual (fp32 out)
    cudaStreamWaitEvent(0, eW, 0);
    tgemm<0,1,1,0><<<dim3(C_/256, M_/128), 512, GT_SMEM>>>(att, woh, x1, M_, C_, C_, bo, x);
    // 5) LN2 (half out)
    ln_kernel<<<M_/8, 256>>>(x1, g2, be2, h2);
    // 6) FFN up + ReLU (half out)
    tgemm<1,0,1,1><<<dim3(F_/256, M_/128), 512, GT_SMEM>>>(h2, w1h, ff, M_, F_, C_, b1, nullptr);
    // 7) FFN down + bias + residual -> final fp32 output
    tgemm<0,1,1,0><<<dim3(C_/256, M_/128), 512, GT_SMEM>>>(ff, w2h, out, M_, C_, F_, b2, x1);
}